// round 5
// baseline (speedup 1.0000x reference)
#include <cuda_runtime.h>
#include <cuda_bf16.h>
#include <math.h>
#include <stdint.h>

// B=8, H=W=128, C=128, HEADS=4, d=32, WS=8, SHIFT=4, HIDDEN=512
#define MTOK 131072

// ---------------- scratch (device globals; no allocs allowed) ----------------
static __device__ unsigned short g_ln1[(size_t)MTOK * 128];  // bf16
static __device__ unsigned short g_qkv[(size_t)MTOK * 384];  // bf16
static __device__ unsigned short g_ao [(size_t)MTOK * 128];  // bf16
static __device__ float          g_x1 [(size_t)MTOK * 128];  // fp32 residual 1
static __device__ unsigned short g_ln2[(size_t)MTOK * 128];  // bf16
static __device__ unsigned short g_hid[(size_t)MTOK * 512];  // bf16
static __device__ unsigned short g_wq[384 * 128];
static __device__ unsigned short g_wp[128 * 128];
static __device__ unsigned short g_w1[512 * 128];
static __device__ unsigned short g_w2[128 * 512];
static __device__ float          g_abias[4 * 4 * 4 * 32 * 32]; // [type][h][wm][lane][32]

// ---------------- PTX helpers (sm_80+ features only) ----------------
static __device__ __forceinline__ uint32_t smem_u32(const void* p) {
    uint32_t a;
    asm("{ .reg .u64 t; cvta.to.shared.u64 t, %1; cvt.u32.u64 %0, t; }" : "=r"(a) : "l"(p));
    return a;
}
static __device__ __forceinline__ void cpa16(uint32_t s, const void* g) {
    asm volatile("cp.async.cg.shared.global [%0], [%1], 16;" :: "r"(s), "l"(g) : "memory");
}
static __device__ __forceinline__ void ldsm4(uint32_t* r, uint32_t addr) {
    asm volatile("ldmatrix.sync.aligned.m8n8.x4.shared.b16 {%0,%1,%2,%3}, [%4];"
                 : "=r"(r[0]), "=r"(r[1]), "=r"(r[2]), "=r"(r[3]) : "r"(addr));
}
static __device__ __forceinline__ void ldsm4t(uint32_t* r, uint32_t addr) {
    asm volatile("ldmatrix.sync.aligned.m8n8.x4.trans.shared.b16 {%0,%1,%2,%3}, [%4];"
                 : "=r"(r[0]), "=r"(r[1]), "=r"(r[2]), "=r"(r[3]) : "r"(addr));
}
static __device__ __forceinline__ void mma_bf16(float* c,
    uint32_t a0, uint32_t a1, uint32_t a2, uint32_t a3, uint32_t b0, uint32_t b1) {
    asm volatile(
        "mma.sync.aligned.m16n8k16.row.col.f32.bf16.bf16.f32 "
        "{%0,%1,%2,%3}, {%4,%5,%6,%7}, {%8,%9}, {%0,%1,%2,%3};"
        : "+f"(c[0]), "+f"(c[1]), "+f"(c[2]), "+f"(c[3])
        : "r"(a0), "r"(a1), "r"(a2), "r"(a3), "r"(b0), "r"(b1));
}
static __device__ __forceinline__ uint32_t packbf(float a, float b) {
    __nv_bfloat162 p = __floats2bfloat162_rn(a, b);
    return *reinterpret_cast<uint32_t*>(&p);
}

// ---------------- prep: weight f2bf + fragment-ordered bias/mask table --------
__global__ __launch_bounds__(256) void prep_kernel(
    const float* __restrict__ s0, unsigned short* __restrict__ d0,
    const float* __restrict__ s1, unsigned short* __restrict__ d1,
    const float* __restrict__ s2, unsigned short* __restrict__ d2,
    const float* __restrict__ s3, unsigned short* __restrict__ d3,
    const float* __restrict__ rpb, float* __restrict__ abias)
{
    int blk = blockIdx.x;
    if (blk < 192) {
        int i = blk * 256 + threadIdx.x;   // 0..49151 float4 groups
        const float* s; unsigned short* d; int o;
        if (i < 12288)      { s = s0; d = d0; o = i; }
        else if (i < 16384) { s = s1; d = d1; o = i - 12288; }
        else if (i < 32768) { s = s2; d = d2; o = i - 16384; }
        else                { s = s3; d = d3; o = i - 32768; }
        float4 v = ((const float4*)s)[o];
        uint2 u;
        u.x = packbf(v.x, v.y);
        u.y = packbf(v.z, v.w);
        ((uint2*)d)[o] = u;
    } else {
        int i = (blk - 192) * 256 + threadIdx.x;  // 0..65535
        int c    = i & 3;
        int nt8  = (i >> 2) & 7;
        int lane = (i >> 5) & 31;
        int wm   = (i >> 10) & 3;
        int h    = (i >> 12) & 3;
        int type = (i >> 14) & 3;
        int row = wm * 16 + (lane >> 2) + ((c >> 1) ? 8 : 0);
        int col = nt8 * 8 + (lane & 3) * 2 + (c & 1);
        int i1 = row >> 3, j1 = row & 7, i2 = col >> 3, j2 = col & 7;
        float v = rpb[((i1 - i2 + 7) * 15 + (j1 - j2 + 7)) * 4 + h];
        int ra = (type & 2) ? (i1 < 4 ? 1 : 2) : 0;
        int rb = (type & 1) ? (j1 < 4 ? 1 : 2) : 0;
        int ca = (type & 2) ? (i2 < 4 ? 1 : 2) : 0;
        int cb = (type & 1) ? (j2 < 4 ? 1 : 2) : 0;
        if (3 * ra + rb != 3 * ca + cb) v -= 100.f;
        abias[i] = v;
    }
}

// ---------------- LayerNorm (warp/token) + shift-gather, bf16 out -------------
__global__ __launch_bounds__(256) void ln_kernel(
    const float* __restrict__ xin, const float* __restrict__ gam,
    const float* __restrict__ bet, unsigned short* __restrict__ out)
{
    int t = (blockIdx.x * blockDim.x + threadIdx.x) >> 5;
    int lane = threadIdx.x & 31;
    int w = t >> 6, n = t & 63;
    int b = w >> 8, wrem = w & 255;
    int wi = wrem >> 4, wj = wrem & 15;
    int i = n >> 3, j = n & 7;
    int y  = (wi * 8 + i + 4) & 127;
    int xc = (wj * 8 + j + 4) & 127;
    size_t src = ((size_t)b << 14) + (size_t)y * 128 + xc;
    float4 v = *(const float4*)(xin + src * 128 + lane * 4);
    float s  = v.x + v.y + v.z + v.w;
    float sq = v.x * v.x + v.y * v.y + v.z * v.z + v.w * v.w;
    #pragma unroll
    for (int o = 16; o; o >>= 1) {
        s  += __shfl_xor_sync(0xffffffffu, s,  o);
        sq += __shfl_xor_sync(0xffffffffu, sq, o);
    }
    float mean = s * (1.f / 128.f);
    float rstd = rsqrtf(sq * (1.f / 128.f) - mean * mean + 1e-5f);
    float4 g4 = *(const float4*)(gam + lane * 4);
    float4 b4 = *(const float4*)(bet + lane * 4);
    uint2 u;
    u.x = packbf((v.x - mean) * rstd * g4.x + b4.x, (v.y - mean) * rstd * g4.y + b4.y);
    u.y = packbf((v.z - mean) * rstd * g4.z + b4.z, (v.w - mean) * rstd * g4.w + b4.w);
    *(uint2*)(out + (size_t)t * 128 + lane * 4) = u;
}

// ---------------- bf16 HMMA GEMM: D[M,N] = A[M,K] @ B[N,K]^T + bias ----------
// mode 0: bf16 out; 1: GELU bf16 out; 2: +res fp32 out;
// mode 4: scatter +res fp32 out AND fused LayerNorm -> bf16 ln2 out (N must be 128)
#define GSMEM 65536
static __device__ __forceinline__ void stage_load(
    uint32_t sbase, const __nv_bfloat16* A, const __nv_bfloat16* B,
    int m0, int n0, int K, int kb, int tid)
{
    #pragma unroll
    for (int it = 0; it < 4; it++) {
        int idx = tid + (it << 8);
        int r = idx >> 3, q = idx & 7;
        uint32_t off = (uint32_t)((r << 7) | (q << 4));
        off ^= (off >> 3) & 0x70;   // SW128
        cpa16(sbase + off,           A + (size_t)(m0 + r) * K + kb * 64 + q * 8);
        cpa16(sbase + 16384u + off,  B + (size_t)(n0 + r) * K + kb * 64 + q * 8);
    }
    asm volatile("cp.async.commit_group;" ::: "memory");
}

__global__ __launch_bounds__(256) void gemm_mma(
    const unsigned short* __restrict__ Au, const unsigned short* __restrict__ Bu,
    const float* __restrict__ bias, const float* __restrict__ res,
    void* __restrict__ Dv, int M, int N, int K, int mode,
    const float* __restrict__ g2, const float* __restrict__ b2,
    unsigned short* __restrict__ ln2o)
{
    extern __shared__ char dsm[];
    const __nv_bfloat16* A = (const __nv_bfloat16*)Au;
    const __nv_bfloat16* B = (const __nv_bfloat16*)Bu;
    uint32_t s0 = smem_u32(dsm);
    const int tid = threadIdx.x, lane = tid & 31, wid = tid >> 5;
    const int wm = wid >> 2, wn = wid & 3;
    const int m0 = blockIdx.y * 128, n0 = blockIdx.x * 128;

    float acc[4][4][4];
    #pragma unroll
    for (int a = 0; a < 4; a++)
        #pragma unroll
        for (int b = 0; b < 4; b++)
            #pragma unroll
            for (int c = 0; c < 4; c++) acc[a][b][c] = 0.f;

    const int lrow = (lane & 7) + ((lane >> 3) & 1) * 8;
    const int lhi  = lane >> 4;

    const int KB = K >> 6;
    stage_load(s0, A, B, m0, n0, K, 0, tid);

    for (int kb = 0; kb < KB; kb++) {
        const uint32_t ab = s0 + (uint32_t)(kb & 1) * 32768u;
        const uint32_t bb = ab + 16384u;
        if (kb + 1 < KB) {
            stage_load(s0 + (uint32_t)((kb + 1) & 1) * 32768u, A, B, m0, n0, K, kb + 1, tid);
            asm volatile("cp.async.wait_group 1;" ::: "memory");
        } else {
            asm volatile("cp.async.wait_group 0;" ::: "memory");
        }
        __syncthreads();
        #pragma unroll
        for (int ks = 0; ks < 4; ks++) {
            uint32_t af[4][4], bf[2][4];
            const int chunk = ks * 2 + lhi;
            #pragma unroll
            for (int tm = 0; tm < 4; tm++) {
                int row = wm * 64 + tm * 16 + lrow;
                ldsm4(af[tm], ab + (uint32_t)(row * 128 + ((chunk ^ (row & 7)) << 4)));
            }
            #pragma unroll
            for (int t2 = 0; t2 < 2; t2++) {
                int row = wn * 32 + t2 * 16 + lrow;
                ldsm4(bf[t2], bb + (uint32_t)(row * 128 + ((chunk ^ (row & 7)) << 4)));
            }
            #pragma unroll
            for (int tm = 0; tm < 4; tm++)
                #pragma unroll
                for (int tn = 0; tn < 4; tn++)
                    mma_bf16(acc[tm][tn],
                             af[tm][0], af[tm][1], af[tm][2], af[tm][3],
                             bf[tn >> 1][tn & 1], bf[tn >> 1][2 + (tn & 1)]);
        }
        __syncthreads();
    }

    float2 bs[4];
    #pragma unroll
    for (int tn = 0; tn < 4; tn++)
        bs[tn] = *(const float2*)(bias + n0 + wn * 32 + tn * 8 + (lane & 3) * 2);

    if (mode != 4) {
        #pragma unroll
        for (int tm = 0; tm < 4; tm++) {
            #pragma unroll
            for (int h = 0; h < 2; h++) {
                const int m = m0 + wm * 64 + tm * 16 + (lane >> 2) + h * 8;
                #pragma unroll
                for (int tn = 0; tn < 4; tn++) {
                    const int nn = n0 + wn * 32 + tn * 8 + (lane & 3) * 2;
                    float v0 = acc[tm][tn][h * 2 + 0] + bs[tn].x;
                    float v1 = acc[tm][tn][h * 2 + 1] + bs[tn].y;
                    if (mode == 1) {
                        v0 = 0.5f * v0 * (1.f + erff(v0 * 0.70710678118654752f));
                        v1 = 0.5f * v1 * (1.f + erff(v1 * 0.70710678118654752f));
                    } else if (mode == 2) {
                        float2 r2 = *(const float2*)(res + (size_t)m * N + nn);
                        v0 += r2.x; v1 += r2.y;
                    }
                    if (mode <= 1) {
                        *(uint32_t*)((__nv_bfloat16*)Dv + (size_t)m * N + nn) = packbf(v0, v1);
                    } else {
                        *(float2*)((float*)Dv + (size_t)m * N + nn) = make_float2(v0, v1);
                    }
                }
            }
        }
        return;
    }

    // ---- mode 4: proj scatter + residual (fp32) + fused LayerNorm (bf16) ----
    float* red = (float*)dsm;   // [128][8]: per-row {s,sq} x 4 warp-columns
    #pragma unroll
    for (int tm = 0; tm < 4; tm++) {
        #pragma unroll
        for (int h = 0; h < 2; h++) {
            const int m = m0 + wm * 64 + tm * 16 + (lane >> 2) + h * 8;
            int w = m >> 6, nt = m & 63;
            int b = w >> 8, wrem = w & 255;
            int wwi = wrem >> 4, wwj = wrem & 15;
            int yf = (wwi * 8 + (nt >> 3) + 4) & 127;
            int xf = (wwj * 8 + (nt & 7) + 4) & 127;
            size_t mo = ((size_t)b << 14) + (size_t)yf * 128 + xf;
            float s = 0.f, sq = 0.f;
            #pragma unroll
            for (int tn = 0; tn < 4; tn++) {
                const int nn = wn * 32 + tn * 8 + (lane & 3) * 2;
                float v0 = acc[tm][tn][h * 2 + 0] + bs[tn].x;
                float v1 = acc[tm][tn][h * 2 + 1] + bs[tn].y;
                float2 r2 = *(const float2*)(res + mo * 128 + nn);
                v0 += r2.x; v1 += r2.y;
                acc[tm][tn][h * 2 + 0] = v0;
                acc[tm][tn][h * 2 + 1] = v1;
                *(float2*)((float*)Dv + mo * 128 + nn) = make_float2(v0, v1);
                s += v0 + v1;
                sq += v0 * v0 + v1 * v1;
            }
            #pragma unroll
            for (int o = 1; o <= 2; o <<= 1) {
                s  += __shfl_xor_sync(0xffffffffu, s,  o);
                sq += __shfl_xor_sync(0xffffffffu, sq, o);
            }
            if ((lane & 3) == 0) {
                const int rloc = wm * 64 + tm * 16 + (lane >> 2) + h * 8;
                red[rloc * 8 + wn * 2 + 0] = s;
                red[rloc * 8 + wn * 2 + 1] = sq;
            }
        }
    }
    __syncthreads();
    #pragma unroll
    for (int tm = 0; tm < 4; tm++) {
        #pragma unroll
        for (int h = 0; h < 2; h++) {
            const int rloc = wm * 64 + tm * 16 + (lane >> 2) + h * 8;
            const int m = m0 + rloc;
            int w = m >> 6, nt = m & 63;
            int b = w >> 8, wrem = w & 255;
            int wwi = wrem >> 4, wwj = wrem & 15;
            int yf = (wwi * 8 + (nt >> 3) + 4) & 127;
            int xf = (wwj * 8 + (nt & 7) + 4) & 127;
            size_t mo = ((size_t)b << 14) + (size_t)yf * 128 + xf;
            float4 p0 = *(const float4*)(red + rloc * 8);
            float4 p1 = *(const float4*)(red + rloc * 8 + 4);
            float s  = p0.x + p0.z + p1.x + p1.z;
            float sq = p0.y + p0.w + p1.y + p1.w;
            float mean = s * (1.f / 128.f);
            float rstd = rsqrtf(sq * (1.f / 128.f) - mean * mean + 1e-5f);
            #pragma unroll
            for (int tn = 0; tn < 4; tn++) {
                const int nn = wn * 32 + tn * 8 + (lane & 3) * 2;
                float2 gg = *(const float2*)(g2 + nn);
                float2 bb2 = *(const float2*)(b2 + nn);
                float v0 = (acc[tm][tn][h * 2 + 0] - mean) * rstd * gg.x + bb2.x;
                float v1 = (acc[tm][tn][h * 2 + 1] - mean) * rstd * gg.y + bb2.y;
                *(uint32_t*)(ln2o + mo * 128 + nn) = packbf(v0, v1);
            }
        }
    }
}

// ---------------- HMMA windowed attention: block = (window, head), 4 warps ----
__global__ __launch_bounds__(128) void attn_mma(
    const unsigned short* __restrict__ qkvu, const float* __restrict__ abias,
    unsigned short* __restrict__ aou)
{
    __shared__ __align__(16) unsigned short qs[64 * 40];
    __shared__ __align__(16) unsigned short ks[64 * 40];
    __shared__ __align__(16) unsigned short vs[64 * 40];
    const __nv_bfloat16* qkv = (const __nv_bfloat16*)qkvu;
    const int tid = threadIdx.x, lane = tid & 31, wm = tid >> 5;
    const int w = blockIdx.x >> 2, h = blockIdx.x & 3;

    // fragment-ordered bias+mask: 8 coalesced float4 per thread (L2-resident)
    const int wrem = w & 255, wi = wrem >> 4, wj = wrem & 15;
    const int type = ((wi == 15) ? 2 : 0) | ((wj == 15) ? 1 : 0);
    float bias[32];
    {
        const float4* tb = (const float4*)(abias + ((((type * 4 + h) * 4 + wm) * 32 + lane) << 5));
        #pragma unroll
        for (int q = 0; q < 8; q++) *(float4*)(bias + q * 4) = tb[q];
    }

    // stage q/k/v head-slice
    {
        const size_t tokbase = (size_t)w * 64;
        #pragma unroll
        for (int it = 0; it < 6; it++) {
            int c = tid + it * 128;
            int mat = c >> 8, rem = c & 255;
            int row = rem >> 2, ch = rem & 3;
            const uint4 v = *(const uint4*)(qkv + (tokbase + row) * 384 + mat * 128 + h * 32 + ch * 8);
            unsigned short* dst = (mat == 0 ? qs : (mat == 1 ? ks : vs));
            *(uint4*)(dst + row * 40 + ch * 8) = v;
        }
    }
    __syncthreads();

    const uint32_t qb = smem_u32(qs), kb_ = smem_u32(ks), vb_ = smem_u32(vs);
    const int lr8 = (lane & 7) + ((lane >> 3) & 1) * 8;
    const uint32_t lh16 = ((lane >> 4) & 1) * 16;

    uint32_t qa[2][4];
    {
        uint32_t addr = qb + (uint32_t)((wm * 16 + lr8) * 80) + lh16;
        ldsm4(qa[0], addr);
        ldsm4(qa[1], addr + 32);
    }
    uint32_t kf[4][2][4];
    #pragma unroll
    for (int nt = 0; nt < 4; nt++) {
        uint32_t addr = kb_ + (uint32_t)((nt * 16 + lr8) * 80) + lh16;
        ldsm4(kf[nt][0], addr);
        ldsm4(kf[nt][1], addr + 32);
    }

    float sc[8][4];
    #pragma unroll
    for (int i = 0; i < 8; i++)
        #pragma unroll
        for (int c = 0; c < 4; c++) sc[i][c] = 0.f;
    #pragma unroll
    for (int nt8 = 0; nt8 < 8; nt8++) {
        const int nt = nt8 >> 1, ii = nt8 & 1;
        mma_bf16(sc[nt8], qa[0][0], qa[0][1], qa[0][2], qa[0][3], kf[nt][0][ii], kf[nt][0][2 + ii]);
        mma_bf16(sc[nt8], qa[1][0], qa[1][1], qa[1][2], qa[1][3], kf[nt][1][ii], kf[nt][1][2 + ii]);
    }

    const float scale = 0.17677669529663689f;
    #pragma unroll
    for (int nt8 = 0; nt8 < 8; nt8++)
        #pragma unroll
        for (int c = 0; c < 4; c++)
            sc[nt8][c] = fmaf(sc[nt8][c], scale, bias[nt8 * 4 + c]);

    float mx0 = -1e30f, mx1 = -1e30f;
    #pragma unroll
    for (int nt8 = 0; nt8 < 8; nt8++) {
        mx0 = fmaxf(mx0, fmaxf(sc[nt8][0], sc[nt8][1]));
        mx1 = fmaxf(mx1, fmaxf(sc[nt8][2], sc[nt8][3]));
    }
    #pragma unroll
    for (int o = 1; o <= 2; o <<= 1) {
        mx0 = fmaxf(mx0, __shfl_xor_sync(0xffffffffu, mx0, o));
        mx1 = fmaxf(mx1, __shfl_xor_sync(0xffffffffu, mx1, o));
    }
    float sm0 = 0.f, sm1 = 0.f;
    #pragma unroll
    for (int nt8 = 0; nt8 < 8; nt8++) {
        sc[nt8][0] = __expf(sc[nt8][0] - mx0);
        sc[nt8][1] = __expf(sc[nt8][1] - mx0);
        sc[nt8][2] = __expf(sc[nt8][2] - mx1);
        sc[nt8][3] = __expf(sc[nt8][3] - mx1);
        sm0 += sc[nt8][0] + sc[nt8][1];
        sm1 += sc[nt8][2] + sc[nt8][3];
    }
    #pragma unroll
    for (int o = 1; o <= 2; o <<= 1) {
        sm0 += __shfl_xor_sync(0xffffffffu, sm0, o);
        sm1 += __shfl_xor_sync(0xffffffffu, sm1, o);
    }
    const float inv0 = 1.f / sm0, inv1 = 1.f / sm1;

    float oc[4][4];
    #pragma unroll
    for (int nt = 0; nt < 4; nt++)
        #pragma unroll
        for (int c = 0; c < 4; c++) oc[nt][c] = 0.f;
    #pragma unroll
    for (int kc = 0; kc < 4; kc++) {
        const uint32_t a0 = packbf(sc[2 * kc][0],     sc[2 * kc][1]);
        const uint32_t a1 = packbf(sc[2 * kc][2],     sc[2 * kc][3]);
        const uint32_t a2 = packbf(sc[2 * kc + 1][0], sc[2 * kc + 1][1]);
        const uint32_t a3 = packbf(sc[2 * kc + 1][2], sc[2 * kc + 1][3]);
        uint32_t vf0[4], vf1[4];
        const uint32_t vaddr = vb_ + (uint32_t)((kc * 16 + lr8) * 80) + lh16;
        ldsm4t(vf0, vaddr);
        ldsm4t(vf1, vaddr + 32);
        mma_bf16(oc[0], a0, a1, a2, a3, vf0[0], vf0[1]);
        mma_bf16(oc[1], a0, a1, a2, a3, vf0[2], vf0[3]);
        mma_bf16(oc[2], a0, a1, a2, a3, vf1[0], vf1[1]);
        mma_bf16(oc[3], a0, a1, a2, a3, vf1[2], vf1[3]);
    }

    __nv_bfloat16* ao = (__nv_bfloat16*)aou;
    const size_t t0 = (size_t)w * 64;
    const int r0 = wm * 16 + (lane >> 2), r1 = r0 + 8;
    #pragma unroll
    for (int nt = 0; nt < 4; nt++) {
        const int ch = h * 32 + nt * 8 + (lane & 3) * 2;
        *(uint32_t*)(ao + (t0 + r0) * 128 + ch) = packbf(oc[nt][0] * inv0, oc[nt][1] * inv0);
        *(uint32_t*)(ao + (t0 + r1) * 128 + ch) = packbf(oc[nt][2] * inv1, oc[nt][3] * inv1);
    }
}

// ---------------- launch ----------------
extern "C" void kernel_launch(void* const* d_in, const int* in_sizes, int n_in,
                              void* d_out, int out_size)
{
    const float* x      = (const float*)d_in[0];
    const float* rpb    = (const float*)d_in[1];
    const float* n1g    = (const float*)d_in[2];
    const float* n1b    = (const float*)d_in[3];
    const float* qkv_w  = (const float*)d_in[4];
    const float* qkv_b  = (const float*)d_in[5];
    const float* proj_w = (const float*)d_in[6];
    const float* proj_b = (const float*)d_in[7];
    const float* n2g    = (const float*)d_in[8];
    const float* n2b    = (const float*)d_in[9];
    const float* fc1_w  = (const float*)d_in[10];
    const float* fc1_b  = (const float*)d_in[11];
    const float* fc2_w  = (const float*)d_in[12];
    const float* fc2_b  = (const float*)d_in[13];
    float* out = (float*)d_out;

    unsigned short *ln1, *qkv, *ao, *ln2, *hid, *wq, *wp, *w1, *w2;
    float *x1, *abias;
    cudaGetSymbolAddress((void**)&ln1, g_ln1);
    cudaGetSymbolAddress((void**)&qkv, g_qkv);
    cudaGetSymbolAddress((void**)&ao,  g_ao);
    cudaGetSymbolAddress((void**)&x1,  g_x1);
    cudaGetSymbolAddress((void**)&ln2, g_ln2);
    cudaGetSymbolAddress((void**)&hid, g_hid);
    cudaGetSymbolAddress((void**)&wq,  g_wq);
    cudaGetSymbolAddress((void**)&wp,  g_wp);
    cudaGetSymbolAddress((void**)&w1,  g_w1);
    cudaGetSymbolAddress((void**)&w2,  g_w2);
    cudaGetSymbolAddress((void**)&abias, g_abias);

    cudaFuncSetAttribute(gemm_mma, cudaFuncAttributeMaxDynamicSharedMemorySize, GSMEM);

    const int M = MTOK;

    // prep: weights -> bf16, bias+mask fragment table
    prep_kernel<<<448, 256>>>(qkv_w, wq, proj_w, wp, fc1_w, w1, fc2_w, w2, rpb, abias);

    // 1) LN1 + cyclic shift + window partition (bf16)
    ln_kernel<<<M / 8, 256>>>(x, n1g, n1b, ln1);
    // 2) QKV GEMM: [M,384] bf16
    gemm_mma<<<dim3(3, M / 128), 256, GSMEM>>>(ln1, wq, qkv_b, nullptr, qkv, M, 384, 128, 0,
                                               nullptr, nullptr, nullptr);
    // 3) HMMA windowed attention
    attn_mma<<<8192, 128>>>(qkv, abias, ao);
    // 4) proj GEMM + scatter + residual + fused LN2 (x1 fp32, ln2 bf16)
    gemm_mma<<<dim3(1, M / 128), 256, GSMEM>>>(ao, wp, proj_b, x, x1, M, 128, 128, 4,
                                               n2g, n2b, ln2);
    // 5) fc1 + GELU (bf16 out)
    gemm_mma<<<dim3(4, M / 128), 256, GSMEM>>>(ln2, w1, fc1_b, nullptr, hid, M, 512, 128, 1,
                                               nullptr, nullptr, nullptr);
    // 6) fc2 + residual -> final fp32 output
    gemm_mma<<<dim3(1, M / 128), 256, GSMEM>>>(hid, w2, fc2_b, x1, out, M, 128, 512, 2,
                                               nullptr, nullptr, nullptr);
}

// round 6
// speedup vs baseline: 1.9134x; 1.9134x over previous
#include <cuda_runtime.h>
#include <cuda_bf16.h>
#include <math.h>
#include <stdint.h>

// B=8, H=W=128, C=128, HEADS=4, d=32, WS=8, SHIFT=4, HIDDEN=512
#define MTOK 131072

// ---------------- scratch (device globals; no allocs allowed) ----------------
static __device__ unsigned short g_ln1[(size_t)MTOK * 128];  // bf16
static __device__ unsigned short g_qkv[(size_t)MTOK * 384];  // bf16
static __device__ unsigned short g_ao [(size_t)MTOK * 128];  // bf16
static __device__ float          g_x1 [(size_t)MTOK * 128];  // fp32 residual 1
static __device__ unsigned short g_ln2[(size_t)MTOK * 128];  // bf16
static __device__ unsigned short g_wq[384 * 128];
static __device__ unsigned short g_wp[128 * 128];
static __device__ unsigned short g_w1[512 * 128];
static __device__ unsigned short g_w2[128 * 512];

// ---------------- PTX helpers (sm_80+ features only) ----------------
static __device__ __forceinline__ uint32_t smem_u32(const void* p) {
    uint32_t a;
    asm("{ .reg .u64 t; cvta.to.shared.u64 t, %1; cvt.u32.u64 %0, t; }" : "=r"(a) : "l"(p));
    return a;
}
static __device__ __forceinline__ void cpa16(uint32_t s, const void* g) {
    asm volatile("cp.async.cg.shared.global [%0], [%1], 16;" :: "r"(s), "l"(g) : "memory");
}
static __device__ __forceinline__ void ldsm4(uint32_t* r, uint32_t addr) {
    asm volatile("ldmatrix.sync.aligned.m8n8.x4.shared.b16 {%0,%1,%2,%3}, [%4];"
                 : "=r"(r[0]), "=r"(r[1]), "=r"(r[2]), "=r"(r[3]) : "r"(addr));
}
static __device__ __forceinline__ void ldsm4t(uint32_t* r, uint32_t addr) {
    asm volatile("ldmatrix.sync.aligned.m8n8.x4.trans.shared.b16 {%0,%1,%2,%3}, [%4];"
                 : "=r"(r[0]), "=r"(r[1]), "=r"(r[2]), "=r"(r[3]) : "r"(addr));
}
static __device__ __forceinline__ void mma_bf16(float* c,
    uint32_t a0, uint32_t a1, uint32_t a2, uint32_t a3, uint32_t b0, uint32_t b1) {
    asm volatile(
        "mma.sync.aligned.m16n8k16.row.col.f32.bf16.bf16.f32 "
        "{%0,%1,%2,%3}, {%4,%5,%6,%7}, {%8,%9}, {%0,%1,%2,%3};"
        : "+f"(c[0]), "+f"(c[1]), "+f"(c[2]), "+f"(c[3])
        : "r"(a0), "r"(a1), "r"(a2), "r"(a3), "r"(b0), "r"(b1));
}
static __device__ __forceinline__ uint32_t packbf(float a, float b) {
    __nv_bfloat162 p = __floats2bfloat162_rn(a, b);
    return *reinterpret_cast<uint32_t*>(&p);
}

// ---------------- merged fp32 -> bf16 weight conversion ----------------
__global__ __launch_bounds__(256) void f2bf_all(
    const float* __restrict__ s0, unsigned short* __restrict__ d0,
    const float* __restrict__ s1, unsigned short* __restrict__ d1,
    const float* __restrict__ s2, unsigned short* __restrict__ d2,
    const float* __restrict__ s3, unsigned short* __restrict__ d3)
{
    int i = blockIdx.x * 256 + threadIdx.x;   // 0..49151 float4 groups
    const float* s; unsigned short* d; int o;
    if (i < 12288)      { s = s0; d = d0; o = i; }
    else if (i < 16384) { s = s1; d = d1; o = i - 12288; }
    else if (i < 32768) { s = s2; d = d2; o = i - 16384; }
    else                { s = s3; d = d3; o = i - 32768; }
    float4 v = ((const float4*)s)[o];
    uint2 u;
    u.x = packbf(v.x, v.y);
    u.y = packbf(v.z, v.w);
    ((uint2*)d)[o] = u;
}

// ---------------- LayerNorm (warp/token), optional shift-gather, bf16 out ------
__global__ __launch_bounds__(256) void ln_kernel(
    const float* __restrict__ xin, const float* __restrict__ gam,
    const float* __restrict__ bet, unsigned short* __restrict__ out, int gather)
{
    int t = (blockIdx.x * blockDim.x + threadIdx.x) >> 5;
    int lane = threadIdx.x & 31;
    size_t src;
    if (gather) {
        int w = t >> 6, n = t & 63;
        int b = w >> 8, wrem = w & 255;
        int wi = wrem >> 4, wj = wrem & 15;
        int i = n >> 3, j = n & 7;
        int y  = (wi * 8 + i + 4) & 127;
        int xc = (wj * 8 + j + 4) & 127;
        src = ((size_t)b << 14) + (size_t)y * 128 + xc;
    } else {
        src = (size_t)t;
    }
    float4 v = *(const float4*)(xin + src * 128 + lane * 4);
    float s  = v.x + v.y + v.z + v.w;
    float sq = v.x * v.x + v.y * v.y + v.z * v.z + v.w * v.w;
    #pragma unroll
    for (int o = 16; o; o >>= 1) {
        s  += __shfl_xor_sync(0xffffffffu, s,  o);
        sq += __shfl_xor_sync(0xffffffffu, sq, o);
    }
    float mean = s * (1.f / 128.f);
    float rstd = rsqrtf(sq * (1.f / 128.f) - mean * mean + 1e-5f);
    float4 g4 = *(const float4*)(gam + lane * 4);
    float4 b4 = *(const float4*)(bet + lane * 4);
    uint2 u;
    u.x = packbf((v.x - mean) * rstd * g4.x + b4.x, (v.y - mean) * rstd * g4.y + b4.y);
    u.y = packbf((v.z - mean) * rstd * g4.z + b4.z, (v.w - mean) * rstd * g4.w + b4.w);
    *(uint2*)(out + (size_t)t * 128 + lane * 4) = u;
}

// ---------------- bf16 HMMA GEMM: D[M,N] = A[M,K] @ B[N,K]^T + bias ----------
// mode 0: bf16 out; 1: GELU bf16 out; 2: +res fp32 out; 3: scatter +res fp32 out
#define GSMEM 65536
static __device__ __forceinline__ void stage_load(
    uint32_t sbase, const __nv_bfloat16* A, const __nv_bfloat16* B,
    int m0, int n0, int K, int kb, int tid)
{
    #pragma unroll
    for (int it = 0; it < 4; it++) {
        int idx = tid + (it << 8);
        int r = idx >> 3, q = idx & 7;
        uint32_t off = (uint32_t)((r << 7) | (q << 4));
        off ^= (off >> 3) & 0x70;   // SW128
        cpa16(sbase + off,           A + (size_t)(m0 + r) * K + kb * 64 + q * 8);
        cpa16(sbase + 16384u + off,  B + (size_t)(n0 + r) * K + kb * 64 + q * 8);
    }
    asm volatile("cp.async.commit_group;" ::: "memory");
}

__global__ __launch_bounds__(256) void gemm_mma(
    const unsigned short* __restrict__ Au, const unsigned short* __restrict__ Bu,
    const float* __restrict__ bias, const float* __restrict__ res,
    void* __restrict__ Dv, int M, int N, int K, int mode)
{
    extern __shared__ char dsm[];
    const __nv_bfloat16* A = (const __nv_bfloat16*)Au;
    const __nv_bfloat16* B = (const __nv_bfloat16*)Bu;
    uint32_t s0 = smem_u32(dsm);
    const int tid = threadIdx.x, lane = tid & 31, wid = tid >> 5;
    const int wm = wid >> 2, wn = wid & 3;
    const int m0 = blockIdx.y * 128, n0 = blockIdx.x * 128;

    float acc[4][4][4];
    #pragma unroll
    for (int a = 0; a < 4; a++)
        #pragma unroll
        for (int b = 0; b < 4; b++)
            #pragma unroll
            for (int c = 0; c < 4; c++) acc[a][b][c] = 0.f;

    const int lrow = (lane & 7) + ((lane >> 3) & 1) * 8;
    const int lhi  = lane >> 4;

    const int KB = K >> 6;
    stage_load(s0, A, B, m0, n0, K, 0, tid);

    for (int kb = 0; kb < KB; kb++) {
        const uint32_t ab = s0 + (uint32_t)(kb & 1) * 32768u;
        const uint32_t bb = ab + 16384u;
        if (kb + 1 < KB) {
            stage_load(s0 + (uint32_t)((kb + 1) & 1) * 32768u, A, B, m0, n0, K, kb + 1, tid);
            asm volatile("cp.async.wait_group 1;" ::: "memory");
        } else {
            asm volatile("cp.async.wait_group 0;" ::: "memory");
        }
        __syncthreads();
        #pragma unroll
        for (int ks = 0; ks < 4; ks++) {
            uint32_t af[4][4], bf[2][4];
            const int chunk = ks * 2 + lhi;
            #pragma unroll
            for (int tm = 0; tm < 4; tm++) {
                int row = wm * 64 + tm * 16 + lrow;
                ldsm4(af[tm], ab + (uint32_t)(row * 128 + ((chunk ^ (row & 7)) << 4)));
            }
            #pragma unroll
            for (int t2 = 0; t2 < 2; t2++) {
                int row = wn * 32 + t2 * 16 + lrow;
                ldsm4(bf[t2], bb + (uint32_t)(row * 128 + ((chunk ^ (row & 7)) << 4)));
            }
            #pragma unroll
            for (int tm = 0; tm < 4; tm++)
                #pragma unroll
                for (int tn = 0; tn < 4; tn++)
                    mma_bf16(acc[tm][tn],
                             af[tm][0], af[tm][1], af[tm][2], af[tm][3],
                             bf[tn >> 1][tn & 1], bf[tn >> 1][2 + (tn & 1)]);
        }
        __syncthreads();
    }

    float2 bs[4];
    #pragma unroll
    for (int tn = 0; tn < 4; tn++)
        bs[tn] = *(const float2*)(bias + n0 + wn * 32 + tn * 8 + (lane & 3) * 2);

    #pragma unroll
    for (int tm = 0; tm < 4; tm++) {
        #pragma unroll
        for (int h = 0; h < 2; h++) {
            const int m = m0 + wm * 64 + tm * 16 + (lane >> 2) + h * 8;
            size_t mo = (size_t)m;
            if (mode == 3) {
                int w = m >> 6, nt = m & 63;
                int b = w >> 8, wrem = w & 255;
                int wwi = wrem >> 4, wwj = wrem & 15;
                int yf = (wwi * 8 + (nt >> 3) + 4) & 127;
                int xf = (wwj * 8 + (nt & 7) + 4) & 127;
                mo = ((size_t)b << 14) + (size_t)yf * 128 + xf;
            }
            #pragma unroll
            for (int tn = 0; tn < 4; tn++) {
                const int nn = n0 + wn * 32 + tn * 8 + (lane & 3) * 2;
                float v0 = acc[tm][tn][h * 2 + 0] + bs[tn].x;
                float v1 = acc[tm][tn][h * 2 + 1] + bs[tn].y;
                if (mode == 1) {
                    v0 = 0.5f * v0 * (1.f + erff(v0 * 0.70710678118654752f));
                    v1 = 0.5f * v1 * (1.f + erff(v1 * 0.70710678118654752f));
                } else if (mode == 2) {
                    float2 r2 = *(const float2*)(res + (size_t)m * N + nn);
                    v0 += r2.x; v1 += r2.y;
                } else if (mode == 3) {
                    float2 r2 = *(const float2*)(res + mo * (size_t)N + nn);
                    v0 += r2.x; v1 += r2.y;
                }
                if (mode <= 1) {
                    *(uint32_t*)((__nv_bfloat16*)Dv + (size_t)m * N + nn) = packbf(v0, v1);
                } else {
                    *(float2*)((float*)Dv + mo * (size_t)N + nn) = make_float2(v0, v1);
                }
            }
        }
    }
}

// ---------------- fused MLP: out = x1 + fc2(GELU(fc1(ln2))) ------------------
// CTA: 128 rows. Loop 4 hidden chunks of 128; fc1 -> GELU -> smem(bf16) -> fc2 acc.
// smem: A 32K | hid 32K | 2 x (W1c 32K + W2c 32K) = 192KB
#define MSMEM 196608
static __device__ __forceinline__ void mlp_stage_w(
    uint32_t wbuf, const __nv_bfloat16* W1, const __nv_bfloat16* W2, int c, int tid)
{
    const int nc0 = c * 128;
    #pragma unroll
    for (int it = 0; it < 8; it++) {
        int idx = tid + (it << 8);          // 0..2047
        int r = idx >> 4, q = idx & 15;     // r: row, q: 16B chunk (16/row)
        int kblk = q >> 3, qi = q & 7;
        uint32_t off = (uint32_t)((r << 7) | (qi << 4));
        off ^= (off >> 3) & 0x70;
        cpa16(wbuf + (uint32_t)kblk * 16384u + off,            W1 + (size_t)(nc0 + r) * 128 + q * 8);
        cpa16(wbuf + 32768u + (uint32_t)kblk * 16384u + off,   W2 + (size_t)r * 512 + nc0 + q * 8);
    }
    asm volatile("cp.async.commit_group;" ::: "memory");
}

__global__ __launch_bounds__(256) void mlp_fused(
    const unsigned short* __restrict__ ln2u, const unsigned short* __restrict__ w1u,
    const float* __restrict__ b1, const unsigned short* __restrict__ w2u,
    const float* __restrict__ b2, const float* __restrict__ res,
    float* __restrict__ out)
{
    extern __shared__ char dsm[];
    const __nv_bfloat16* A  = (const __nv_bfloat16*)ln2u;
    const __nv_bfloat16* W1 = (const __nv_bfloat16*)w1u;
    const __nv_bfloat16* W2 = (const __nv_bfloat16*)w2u;
    const uint32_t s0 = smem_u32(dsm);
    const uint32_t A_B = s0;
    const uint32_t H_B = s0 + 32768u;
    const uint32_t W_B = s0 + 65536u;   // + buf*65536
    const int tid = threadIdx.x, lane = tid & 31, wid = tid >> 5;
    const int wm = wid >> 2, wn = wid & 3;
    const int m0 = blockIdx.x * 128;
    const int lrow = (lane & 7) + ((lane >> 3) & 1) * 8;
    const int lhi  = lane >> 4;

    // stage A (128x128 bf16, 2 k-blocks) — rides in group 0 with chunk-0 weights
    #pragma unroll
    for (int it = 0; it < 8; it++) {
        int idx = tid + (it << 8);
        int r = idx >> 4, q = idx & 15;
        int kblk = q >> 3, qi = q & 7;
        uint32_t off = (uint32_t)((r << 7) | (qi << 4));
        off ^= (off >> 3) & 0x70;
        cpa16(A_B + (uint32_t)kblk * 16384u + off, A + (size_t)(m0 + r) * 128 + q * 8);
    }
    mlp_stage_w(W_B, W1, W2, 0, tid);   // group 0 (A + chunk0)

    float acc2[4][4][4];
    #pragma unroll
    for (int a = 0; a < 4; a++)
        #pragma unroll
        for (int b = 0; b < 4; b++)
            #pragma unroll
            for (int c = 0; c < 4; c++) acc2[a][b][c] = 0.f;

    for (int c = 0; c < 4; c++) {
        if (c + 1 < 4) mlp_stage_w(W_B + (uint32_t)((c + 1) & 1) * 65536u, W1, W2, c + 1, tid);
        if (c + 1 < 4) { asm volatile("cp.async.wait_group 1;" ::: "memory"); }
        else           { asm volatile("cp.async.wait_group 0;" ::: "memory"); }
        __syncthreads();

        const uint32_t wb = W_B + (uint32_t)(c & 1) * 65536u;

        // ---- fc1: acc1 = A @ W1c^T ----
        float acc1[4][4][4];
        #pragma unroll
        for (int a = 0; a < 4; a++)
            #pragma unroll
            for (int b = 0; b < 4; b++)
                #pragma unroll
                for (int q = 0; q < 4; q++) acc1[a][b][q] = 0.f;
        #pragma unroll
        for (int kb = 0; kb < 2; kb++) {
            const uint32_t ab = A_B + (uint32_t)kb * 16384u;
            const uint32_t bb = wb + (uint32_t)kb * 16384u;
            #pragma unroll
            for (int ks = 0; ks < 4; ks++) {
                uint32_t af[4][4], bf[2][4];
                const int chunk = ks * 2 + lhi;
                #pragma unroll
                for (int tm = 0; tm < 4; tm++) {
                    int row = wm * 64 + tm * 16 + lrow;
                    ldsm4(af[tm], ab + (uint32_t)(row * 128 + ((chunk ^ (row & 7)) << 4)));
                }
                #pragma unroll
                for (int t2 = 0; t2 < 2; t2++) {
                    int row = wn * 32 + t2 * 16 + lrow;
                    ldsm4(bf[t2], bb + (uint32_t)(row * 128 + ((chunk ^ (row & 7)) << 4)));
                }
                #pragma unroll
                for (int tm = 0; tm < 4; tm++)
                    #pragma unroll
                    for (int tn = 0; tn < 4; tn++)
                        mma_bf16(acc1[tm][tn],
                                 af[tm][0], af[tm][1], af[tm][2], af[tm][3],
                                 bf[tn >> 1][tn & 1], bf[tn >> 1][2 + (tn & 1)]);
            }
        }

        // ---- bias + GELU -> hid smem (bf16, swizzled) ----
        {
            float2 bs1[4];
            #pragma unroll
            for (int tn = 0; tn < 4; tn++)
                bs1[tn] = *(const float2*)(b1 + c * 128 + wn * 32 + tn * 8 + (lane & 3) * 2);
            #pragma unroll
            for (int tm = 0; tm < 4; tm++) {
                #pragma unroll
                for (int h = 0; h < 2; h++) {
                    const int row = wm * 64 + tm * 16 + (lane >> 2) + h * 8;
                    #pragma unroll
                    for (int tn = 0; tn < 4; tn++) {
                        const int nn = wn * 32 + tn * 8 + (lane & 3) * 2;
                        float v0 = acc1[tm][tn][h * 2 + 0] + bs1[tn].x;
                        float v1 = acc1[tm][tn][h * 2 + 1] + bs1[tn].y;
                        v0 = 0.5f * v0 * (1.f + erff(v0 * 0.70710678118654752f));
                        v1 = 0.5f * v1 * (1.f + erff(v1 * 0.70710678118654752f));
                        uint32_t boff = (uint32_t)((row << 7) + (nn & 63) * 2);
                        boff ^= (boff >> 3) & 0x70;
                        uint32_t dst = H_B + ((nn >= 64) ? 16384u : 0u) + boff;
                        asm volatile("st.shared.b32 [%0], %1;" :: "r"(dst), "r"(packbf(v0, v1)) : "memory");
                    }
                }
            }
        }
        __syncthreads();

        // ---- fc2 partial: acc2 += hid @ W2c^T ----
        #pragma unroll
        for (int kb = 0; kb < 2; kb++) {
            const uint32_t ab = H_B + (uint32_t)kb * 16384u;
            const uint32_t bb = wb + 32768u + (uint32_t)kb * 16384u;
            #pragma unroll
            for (int ks = 0; ks < 4; ks++) {
                uint32_t af[4][4], bf[2][4];
                const int chunk = ks * 2 + lhi;
                #pragma unroll
                for (int tm = 0; tm < 4; tm++) {
                    int row = wm * 64 + tm * 16 + lrow;
                    ldsm4(af[tm], ab + (uint32_t)(row * 128 + ((chunk ^ (row & 7)) << 4)));
                }
                #pragma unroll
                for (int t2 = 0; t2 < 2; t2++) {
                    int row = wn * 32 + t2 * 16 + lrow;
                    ldsm4(bf[t2], bb + (uint32_t)(row * 128 + ((chunk ^ (row & 7)) << 4)));
                }
                #pragma unroll
                for (int tm = 0; tm < 4; tm++)
                    #pragma unroll
                    for (int tn = 0; tn < 4; tn++)
                        mma_bf16(acc2[tm][tn],
                                 af[tm][0], af[tm][1], af[tm][2], af[tm][3],
                                 bf[tn >> 1][tn & 1], bf[tn >> 1][2 + (tn & 1)]);
            }
        }
        __syncthreads();   // hid reads done before next chunk overwrites
    }

    // ---- epilogue: + b2 + residual(x1) -> fp32 out ----
    float2 bs[4];
    #pragma unroll
    for (int tn = 0; tn < 4; tn++)
        bs[tn] = *(const float2*)(b2 + wn * 32 + tn * 8 + (lane & 3) * 2);
    #pragma unroll
    for (int tm = 0; tm < 4; tm++) {
        #pragma unroll
        for (int h = 0; h < 2; h++) {
            const int m = m0 + wm * 64 + tm * 16 + (lane >> 2) + h * 8;
            #pragma unroll
            for (int tn = 0; tn < 4; tn++) {
                const int nn = wn * 32 + tn * 8 + (lane & 3) * 2;
                float2 r2 = *(const float2*)(res + (size_t)m * 128 + nn);
                float v0 = acc2[tm][tn][h * 2 + 0] + bs[tn].x + r2.x;
                float v1 = acc2[tm][tn][h * 2 + 1] + bs[tn].y + r2.y;
                *(float2*)(out + (size_t)m * 128 + nn) = make_float2(v0, v1);
            }
        }
    }
}

// ---------------- HMMA windowed attention: block = (window, head), 4 warps ----
__device__ __forceinline__ int reg3(int y) { return y < 120 ? 0 : (y < 124 ? 1 : 2); }

__global__ __launch_bounds__(128) void attn_mma(
    const unsigned short* __restrict__ qkvu, const float* __restrict__ rpb,
    unsigned short* __restrict__ aou)
{
    __shared__ __align__(16) unsigned short qs[64 * 40];
    __shared__ __align__(16) unsigned short ks[64 * 40];
    __shared__ __align__(16) unsigned short vs[64 * 40];
    __shared__ float rpbs[900];
    __shared__ int  regtok[64];
    const __nv_bfloat16* qkv = (const __nv_bfloat16*)qkvu;
    const int tid = threadIdx.x, lane = tid & 31, wm = tid >> 5;
    const int w = blockIdx.x >> 2, h = blockIdx.x & 3;

    {
        const size_t tokbase = (size_t)w * 64;
        #pragma unroll
        for (int it = 0; it < 6; it++) {
            int c = tid + it * 128;
            int mat = c >> 8, rem = c & 255;
            int row = rem >> 2, ch = rem & 3;
            const uint4 v = *(const uint4*)(qkv + (tokbase + row) * 384 + mat * 128 + h * 32 + ch * 8);
            unsigned short* dst = (mat == 0 ? qs : (mat == 1 ? ks : vs));
            *(uint4*)(dst + row * 40 + ch * 8) = v;
        }
        #pragma unroll
        for (int it = 0; it < 8; it++) {
            int idx = tid + it * 128;
            if (idx < 900) rpbs[idx] = rpb[idx];
        }
        if (tid < 64) {
            int wrem = w & 255, wi = wrem >> 4, wj = wrem & 15;
            regtok[tid] = 3 * reg3(wi * 8 + (tid >> 3)) + reg3(wj * 8 + (tid & 7));
        }
    }
    __syncthreads();

    const uint32_t qb = smem_u32(qs), kb_ = smem_u32(ks), vb_ = smem_u32(vs);
    const int lr8 = (lane & 7) + ((lane >> 3) & 1) * 8;
    const uint32_t lh16 = ((lane >> 4) & 1) * 16;

    uint32_t qa[2][4];
    {
        uint32_t addr = qb + (uint32_t)((wm * 16 + lr8) * 80) + lh16;
        ldsm4(qa[0], addr);
        ldsm4(qa[1], addr + 32);
    }
    uint32_t kf[4][2][4];
    #pragma unroll
    for (int nt = 0; nt < 4; nt++) {
        uint32_t addr = kb_ + (uint32_t)((nt * 16 + lr8) * 80) + lh16;
        ldsm4(kf[nt][0], addr);
        ldsm4(kf[nt][1], addr + 32);
    }

    float sc[8][4];
    #pragma unroll
    for (int i = 0; i < 8; i++)
        #pragma unroll
        for (int c = 0; c < 4; c++) sc[i][c] = 0.f;
    #pragma unroll
    for (int nt8 = 0; nt8 < 8; nt8++) {
        const int nt = nt8 >> 1, ii = nt8 & 1;
        mma_bf16(sc[nt8], qa[0][0], qa[0][1], qa[0][2], qa[0][3], kf[nt][0][ii], kf[nt][0][2 + ii]);
        mma_bf16(sc[nt8], qa[1][0], qa[1][1], qa[1][2], qa[1][3], kf[nt][1][ii], kf[nt][1][2 + ii]);
    }

    const float scale = 0.17677669529663689f;
    const int r0 = wm * 16 + (lane >> 2), r1 = r0 + 8;
    const int rg0 = regtok[r0], rg1 = regtok[r1];
    const int i1a = r0 >> 3, j1a = r0 & 7, i1b = r1 >> 3, j1b = r1 & 7;
    #pragma unroll
    for (int nt8 = 0; nt8 < 8; nt8++) {
        #pragma unroll
        for (int c = 0; c < 4; c++) {
            const int col = nt8 * 8 + (lane & 3) * 2 + (c & 1);
            const int i2 = col >> 3, j2 = col & 7;
            const int rgc = regtok[col];
            float v = sc[nt8][c] * scale;
            if (c < 2) {
                v += rpbs[((i1a - i2 + 7) * 15 + (j1a - j2 + 7)) * 4 + h];
                if (rgc != rg0) v -= 100.f;
            } else {
                v += rpbs[((i1b - i2 + 7) * 15 + (j1b - j2 + 7)) * 4 + h];
                if (rgc != rg1) v -= 100.f;
            }
            sc[nt8][c] = v;
        }
    }

    float mx0 = -1e30f, mx1 = -1e30f;
    #pragma unroll
    for (int nt8 = 0; nt8 < 8; nt8++) {
        mx0 = fmaxf(mx0, fmaxf(sc[nt8][0], sc[nt8][1]));
        mx1 = fmaxf(mx1, fmaxf(sc[nt8][2], sc[nt8][3]));
    }
    #pragma unroll
    for (int o = 1; o <= 2; o <<= 1) {
        mx0 = fmaxf(mx0, __shfl_xor_sync(0xffffffffu, mx0, o));
        mx1 = fmaxf(mx1, __shfl_xor_sync(0xffffffffu, mx1, o));
    }
    float sm0 = 0.f, sm1 = 0.f;
    #pragma unroll
    for (int nt8 = 0; nt8 < 8; nt8++) {
        sc[nt8][0] = __expf(sc[nt8][0] - mx0);
        sc[nt8][1] = __expf(sc[nt8][1] - mx0);
        sc[nt8][2] = __expf(sc[nt8][2] - mx1);
        sc[nt8][3] = __expf(sc[nt8][3] - mx1);
        sm0 += sc[nt8][0] + sc[nt8][1];
        sm1 += sc[nt8][2] + sc[nt8][3];
    }
    #pragma unroll
    for (int o = 1; o <= 2; o <<= 1) {
        sm0 += __shfl_xor_sync(0xffffffffu, sm0, o);
        sm1 += __shfl_xor_sync(0xffffffffu, sm1, o);
    }
    const float inv0 = 1.f / sm0, inv1 = 1.f / sm1;

    float oc[4][4];
    #pragma unroll
    for (int nt = 0; nt < 4; nt++)
        #pragma unroll
        for (int c = 0; c < 4; c++) oc[nt][c] = 0.f;
    #pragma unroll
    for (int kc = 0; kc < 4; kc++) {
        const uint32_t a0 = packbf(sc[2 * kc][0],     sc[2 * kc][1]);
        const uint32_t a1 = packbf(sc[2 * kc][2],     sc[2 * kc][3]);
        const uint32_t a2 = packbf(sc[2 * kc + 1][0], sc[2 * kc + 1][1]);
        const uint32_t a3 = packbf(sc[2 * kc + 1][2], sc[2 * kc + 1][3]);
        uint32_t vf0[4], vf1[4];
        const uint32_t vaddr = vb_ + (uint32_t)((kc * 16 + lr8) * 80) + lh16;
        ldsm4t(vf0, vaddr);
        ldsm4t(vf1, vaddr + 32);
        mma_bf16(oc[0], a0, a1, a2, a3, vf0[0], vf0[1]);
        mma_bf16(oc[1], a0, a1, a2, a3, vf0[2], vf0[3]);
        mma_bf16(oc[2], a0, a1, a2, a3, vf1[0], vf1[1]);
        mma_bf16(oc[3], a0, a1, a2, a3, vf1[2], vf1[3]);
    }

    __nv_bfloat16* ao = (__nv_bfloat16*)aou;
    const size_t t0 = (size_t)w * 64;
    #pragma unroll
    for (int nt = 0; nt < 4; nt++) {
        const int ch = h * 32 + nt * 8 + (lane & 3) * 2;
        *(uint32_t*)(ao + (t0 + r0) * 128 + ch) = packbf(oc[nt][0] * inv0, oc[nt][1] * inv0);
        *(uint32_t*)(ao + (t0 + r1) * 128 + ch) = packbf(oc[nt][2] * inv1, oc[nt][3] * inv1);
    }
}

// ---------------- launch ----------------
extern "C" void kernel_launch(void* const* d_in, const int* in_sizes, int n_in,
                              void* d_out, int out_size)
{
    const float* x      = (const float*)d_in[0];
    const float* rpb    = (const float*)d_in[1];
    const float* n1g    = (const float*)d_in[2];
    const float* n1b    = (const float*)d_in[3];
    const float* qkv_w  = (const float*)d_in[4];
    const float* qkv_b  = (const float*)d_in[5];
    const float* proj_w = (const float*)d_in[6];
    const float* proj_b = (const float*)d_in[7];
    const float* n2g    = (const float*)d_in[8];
    const float* n2b    = (const float*)d_in[9];
    const float* fc1_w  = (const float*)d_in[10];
    const float* fc1_b  = (const float*)d_in[11];
    const float* fc2_w  = (const float*)d_in[12];
    const float* fc2_b  = (const float*)d_in[13];
    float* out = (float*)d_out;

    unsigned short *ln1, *qkv, *ao, *ln2, *wq, *wp, *w1, *w2;
    float *x1;
    cudaGetSymbolAddress((void**)&ln1, g_ln1);
    cudaGetSymbolAddress((void**)&qkv, g_qkv);
    cudaGetSymbolAddress((void**)&ao,  g_ao);
    cudaGetSymbolAddress((void**)&x1,  g_x1);
    cudaGetSymbolAddress((void**)&ln2, g_ln2);
    cudaGetSymbolAddress((void**)&wq,  g_wq);
    cudaGetSymbolAddress((void**)&wp,  g_wp);
    cudaGetSymbolAddress((void**)&w1,  g_w1);
    cudaGetSymbolAddress((void**)&w2,  g_w2);

    cudaFuncSetAttribute(gemm_mma, cudaFuncAttributeMaxDynamicSharedMemorySize, GSMEM);
    cudaFuncSetAttribute(mlp_fused, cudaFuncAttributeMaxDynamicSharedMemorySize, MSMEM);

    const int M = MTOK;

    // weight conversions (one launch)
    f2bf_all<<<192, 256>>>(qkv_w, wq, proj_w, wp, fc1_w, w1, fc2_w, w2);

    // 1) LN1 + cyclic shift + window partition (bf16)
    ln_kernel<<<M / 8, 256>>>(x, n1g, n1b, ln1, 1);
    // 2) QKV GEMM: [M,384] bf16
    gemm_mma<<<dim3(3, M / 128), 256, GSMEM>>>(ln1, wq, qkv_b, nullptr, qkv, M, 384, 128, 0);
    // 3) HMMA windowed attention
    attn_mma<<<8192, 128>>>(qkv, rpb, ao);
    // 4) proj GEMM + window-reverse + unshift + residual (fp32 out)
    gemm_mma<<<dim3(1, M / 128), 256, GSMEM>>>(ao, wp, proj_b, x, x1, M, 128, 128, 3);
    // 5) LN2 (bf16)
    ln_kernel<<<M / 8, 256>>>(x1, n2g, n2b, ln2, 0);
    // 6+7) fused MLP: out = x1 + fc2(GELU(fc1(ln2)))
    mlp_fused<<<M / 128, 256, MSMEM>>>(ln2, w1, fc1_b, w2, fc2_b, x1, out);
}

// round 7
// speedup vs baseline: 2.0017x; 1.0461x over previous
#include <cuda_runtime.h>
#include <cuda_bf16.h>
#include <math.h>
#include <stdint.h>

// B=8, H=W=128, C=128, HEADS=4, d=32, WS=8, SHIFT=4, HIDDEN=512
#define MTOK 131072

// ---------------- scratch (device globals; no allocs allowed) ----------------
static __device__ unsigned short g_ln1[(size_t)MTOK * 128];  // bf16
static __device__ unsigned short g_qkv[(size_t)MTOK * 384];  // bf16, [mat][h][tok][32]
static __device__ unsigned short g_ao [(size_t)MTOK * 128];  // bf16, [h][tok][32]
static __device__ float          g_x1 [(size_t)MTOK * 128];  // fp32 residual 1
static __device__ unsigned short g_ln2[(size_t)MTOK * 128];  // bf16
static __device__ unsigned short g_wq[384 * 128];
static __device__ unsigned short g_wp[128 * 128];
static __device__ unsigned short g_w1[512 * 128];
static __device__ unsigned short g_w2[128 * 512];

// ---------------- PTX helpers (sm_80+ features only) ----------------
static __device__ __forceinline__ uint32_t smem_u32(const void* p) {
    uint32_t a;
    asm("{ .reg .u64 t; cvta.to.shared.u64 t, %1; cvt.u32.u64 %0, t; }" : "=r"(a) : "l"(p));
    return a;
}
static __device__ __forceinline__ void cpa16(uint32_t s, const void* g) {
    asm volatile("cp.async.cg.shared.global [%0], [%1], 16;" :: "r"(s), "l"(g) : "memory");
}
static __device__ __forceinline__ void ldsm4(uint32_t* r, uint32_t addr) {
    asm volatile("ldmatrix.sync.aligned.m8n8.x4.shared.b16 {%0,%1,%2,%3}, [%4];"
                 : "=r"(r[0]), "=r"(r[1]), "=r"(r[2]), "=r"(r[3]) : "r"(addr));
}
static __device__ __forceinline__ void ldsm4t(uint32_t* r, uint32_t addr) {
    asm volatile("ldmatrix.sync.aligned.m8n8.x4.trans.shared.b16 {%0,%1,%2,%3}, [%4];"
                 : "=r"(r[0]), "=r"(r[1]), "=r"(r[2]), "=r"(r[3]) : "r"(addr));
}
static __device__ __forceinline__ void mma_bf16(float* c,
    uint32_t a0, uint32_t a1, uint32_t a2, uint32_t a3, uint32_t b0, uint32_t b1) {
    asm volatile(
        "mma.sync.aligned.m16n8k16.row.col.f32.bf16.bf16.f32 "
        "{%0,%1,%2,%3}, {%4,%5,%6,%7}, {%8,%9}, {%0,%1,%2,%3};"
        : "+f"(c[0]), "+f"(c[1]), "+f"(c[2]), "+f"(c[3])
        : "r"(a0), "r"(a1), "r"(a2), "r"(a3), "r"(b0), "r"(b1));
}
static __device__ __forceinline__ uint32_t packbf(float a, float b) {
    __nv_bfloat162 p = __floats2bfloat162_rn(a, b);
    return *reinterpret_cast<uint32_t*>(&p);
}

// ---------------- merged fp32 -> bf16 weight conversion ----------------
__global__ __launch_bounds__(256) void f2bf_all(
    const float* __restrict__ s0, unsigned short* __restrict__ d0,
    const float* __restrict__ s1, unsigned short* __restrict__ d1,
    const float* __restrict__ s2, unsigned short* __restrict__ d2,
    const float* __restrict__ s3, unsigned short* __restrict__ d3)
{
    int i = blockIdx.x * 256 + threadIdx.x;
    const float* s; unsigned short* d; int o;
    if (i < 12288)      { s = s0; d = d0; o = i; }
    else if (i < 16384) { s = s1; d = d1; o = i - 12288; }
    else if (i < 32768) { s = s2; d = d2; o = i - 16384; }
    else                { s = s3; d = d3; o = i - 32768; }
    float4 v = ((const float4*)s)[o];
    uint2 u;
    u.x = packbf(v.x, v.y);
    u.y = packbf(v.z, v.w);
    ((uint2*)d)[o] = u;
}

// ---------------- LayerNorm (warp/token), optional shift-gather, bf16 out ------
__global__ __launch_bounds__(256) void ln_kernel(
    const float* __restrict__ xin, const float* __restrict__ gam,
    const float* __restrict__ bet, unsigned short* __restrict__ out, int gather)
{
    int t = (blockIdx.x * blockDim.x + threadIdx.x) >> 5;
    int lane = threadIdx.x & 31;
    size_t src;
    if (gather) {
        int w = t >> 6, n = t & 63;
        int b = w >> 8, wrem = w & 255;
        int wi = wrem >> 4, wj = wrem & 15;
        int i = n >> 3, j = n & 7;
        int y  = (wi * 8 + i + 4) & 127;
        int xc = (wj * 8 + j + 4) & 127;
        src = ((size_t)b << 14) + (size_t)y * 128 + xc;
    } else {
        src = (size_t)t;
    }
    float4 v = *(const float4*)(xin + src * 128 + lane * 4);
    float s  = v.x + v.y + v.z + v.w;
    float sq = v.x * v.x + v.y * v.y + v.z * v.z + v.w * v.w;
    #pragma unroll
    for (int o = 16; o; o >>= 1) {
        s  += __shfl_xor_sync(0xffffffffu, s,  o);
        sq += __shfl_xor_sync(0xffffffffu, sq, o);
    }
    float mean = s * (1.f / 128.f);
    float rstd = rsqrtf(sq * (1.f / 128.f) - mean * mean + 1e-5f);
    float4 g4 = *(const float4*)(gam + lane * 4);
    float4 b4 = *(const float4*)(bet + lane * 4);
    uint2 u;
    u.x = packbf((v.x - mean) * rstd * g4.x + b4.x, (v.y - mean) * rstd * g4.y + b4.y);
    u.y = packbf((v.z - mean) * rstd * g4.z + b4.z, (v.w - mean) * rstd * g4.w + b4.w);
    *(uint2*)(out + (size_t)t * 128 + lane * 4) = u;
}

// ---------------- bf16 HMMA GEMM ----------------
// mode 5: QKV — bf16 out permuted to [mat][h][tok][32]
// mode 6: proj — A gathered from [h][tok][32]; scatter + residual fp32 out
#define GSMEM 65536
static __device__ __forceinline__ void stage_load(
    uint32_t sbase, const __nv_bfloat16* A, const __nv_bfloat16* B,
    int m0, int n0, int K, int kb, int tid, int gatherA)
{
    #pragma unroll
    for (int it = 0; it < 4; it++) {
        int idx = tid + (it << 8);
        int r = idx >> 3, q = idx & 7;
        uint32_t off = (uint32_t)((r << 7) | (q << 4));
        off ^= (off >> 3) & 0x70;   // SW128
        if (gatherA) {
            // A head-major [h][tok][32]; channel = kb*64 + q*8
            int hh = kb * 2 + (q >> 2);
            cpa16(sbase + off, A + ((size_t)hh * MTOK + (m0 + r)) * 32 + (q & 3) * 8);
        } else {
            cpa16(sbase + off, A + (size_t)(m0 + r) * K + kb * 64 + q * 8);
        }
        cpa16(sbase + 16384u + off, B + (size_t)(n0 + r) * K + kb * 64 + q * 8);
    }
    asm volatile("cp.async.commit_group;" ::: "memory");
}

__global__ __launch_bounds__(256) void gemm_mma(
    const unsigned short* __restrict__ Au, const unsigned short* __restrict__ Bu,
    const float* __restrict__ bias, const float* __restrict__ res,
    void* __restrict__ Dv, int M, int N, int K, int mode)
{
    extern __shared__ char dsm[];
    const __nv_bfloat16* A = (const __nv_bfloat16*)Au;
    const __nv_bfloat16* B = (const __nv_bfloat16*)Bu;
    uint32_t s0 = smem_u32(dsm);
    const int tid = threadIdx.x, lane = tid & 31, wid = tid >> 5;
    const int wm = wid >> 2, wn = wid & 3;
    const int m0 = blockIdx.y * 128, n0 = blockIdx.x * 128;
    const int gatherA = (mode == 6);

    float acc[4][4][4];
    #pragma unroll
    for (int a = 0; a < 4; a++)
        #pragma unroll
        for (int b = 0; b < 4; b++)
            #pragma unroll
            for (int c = 0; c < 4; c++) acc[a][b][c] = 0.f;

    const int lrow = (lane & 7) + ((lane >> 3) & 1) * 8;
    const int lhi  = lane >> 4;

    const int KB = K >> 6;
    stage_load(s0, A, B, m0, n0, K, 0, tid, gatherA);

    for (int kb = 0; kb < KB; kb++) {
        const uint32_t ab = s0 + (uint32_t)(kb & 1) * 32768u;
        const uint32_t bb = ab + 16384u;
        if (kb + 1 < KB) {
            stage_load(s0 + (uint32_t)((kb + 1) & 1) * 32768u, A, B, m0, n0, K, kb + 1, tid, gatherA);
            asm volatile("cp.async.wait_group 1;" ::: "memory");
        } else {
            asm volatile("cp.async.wait_group 0;" ::: "memory");
        }
        __syncthreads();
        #pragma unroll
        for (int ks = 0; ks < 4; ks++) {
            uint32_t af[4][4], bf[2][4];
            const int chunk = ks * 2 + lhi;
            #pragma unroll
            for (int tm = 0; tm < 4; tm++) {
                int row = wm * 64 + tm * 16 + lrow;
                ldsm4(af[tm], ab + (uint32_t)(row * 128 + ((chunk ^ (row & 7)) << 4)));
            }
            #pragma unroll
            for (int t2 = 0; t2 < 2; t2++) {
                int row = wn * 32 + t2 * 16 + lrow;
                ldsm4(bf[t2], bb + (uint32_t)(row * 128 + ((chunk ^ (row & 7)) << 4)));
            }
            #pragma unroll
            for (int tm = 0; tm < 4; tm++)
                #pragma unroll
                for (int tn = 0; tn < 4; tn++)
                    mma_bf16(acc[tm][tn],
                             af[tm][0], af[tm][1], af[tm][2], af[tm][3],
                             bf[tn >> 1][tn & 1], bf[tn >> 1][2 + (tn & 1)]);
        }
        __syncthreads();
    }

    float2 bs[4];
    #pragma unroll
    for (int tn = 0; tn < 4; tn++)
        bs[tn] = *(const float2*)(bias + n0 + wn * 32 + tn * 8 + (lane & 3) * 2);

    #pragma unroll
    for (int tm = 0; tm < 4; tm++) {
        #pragma unroll
        for (int h = 0; h < 2; h++) {
            const int m = m0 + wm * 64 + tm * 16 + (lane >> 2) + h * 8;
            size_t mo = (size_t)m;
            if (mode == 6) {
                int w = m >> 6, nt = m & 63;
                int b = w >> 8, wrem = w & 255;
                int wwi = wrem >> 4, wwj = wrem & 15;
                int yf = (wwi * 8 + (nt >> 3) + 4) & 127;
                int xf = (wwj * 8 + (nt & 7) + 4) & 127;
                mo = ((size_t)b << 14) + (size_t)yf * 128 + xf;
            }
            #pragma unroll
            for (int tn = 0; tn < 4; tn++) {
                const int nn = n0 + wn * 32 + tn * 8 + (lane & 3) * 2;
                float v0 = acc[tm][tn][h * 2 + 0] + bs[tn].x;
                float v1 = acc[tm][tn][h * 2 + 1] + bs[tn].y;
                if (mode == 5) {
                    // permute to [mat][head][tok][32]
                    int mat = nn >> 7, wh = (nn >> 5) & 3, c = nn & 31;
                    *(uint32_t*)((__nv_bfloat16*)Dv +
                        (((size_t)(mat * 4 + wh) * MTOK + m) * 32 + c)) = packbf(v0, v1);
                } else {
                    float2 r2 = *(const float2*)(res + mo * (size_t)N + nn);
                    v0 += r2.x; v1 += r2.y;
                    *(float2*)((float*)Dv + mo * (size_t)N + nn) = make_float2(v0, v1);
                }
            }
        }
    }
}

// ---------------- fused MLP: out = x1 + fc2(GELU(fc1(ln2))) ------------------
#define MSMEM 196608
static __device__ __forceinline__ void mlp_stage_w(
    uint32_t wbuf, const __nv_bfloat16* W1, const __nv_bfloat16* W2, int c, int tid)
{
    const int nc0 = c * 128;
    #pragma unroll
    for (int it = 0; it < 8; it++) {
        int idx = tid + (it << 8);
        int r = idx >> 4, q = idx & 15;
        int kblk = q >> 3, qi = q & 7;
        uint32_t off = (uint32_t)((r << 7) | (qi << 4));
        off ^= (off >> 3) & 0x70;
        cpa16(wbuf + (uint32_t)kblk * 16384u + off,            W1 + (size_t)(nc0 + r) * 128 + q * 8);
        cpa16(wbuf + 32768u + (uint32_t)kblk * 16384u + off,   W2 + (size_t)r * 512 + nc0 + q * 8);
    }
    asm volatile("cp.async.commit_group;" ::: "memory");
}

__global__ __launch_bounds__(256) void mlp_fused(
    const unsigned short* __restrict__ ln2u, const unsigned short* __restrict__ w1u,
    const float* __restrict__ b1, const unsigned short* __restrict__ w2u,
    const float* __restrict__ b2, const float* __restrict__ res,
    float* __restrict__ out)
{
    extern __shared__ char dsm[];
    const __nv_bfloat16* A  = (const __nv_bfloat16*)ln2u;
    const __nv_bfloat16* W1 = (const __nv_bfloat16*)w1u;
    const __nv_bfloat16* W2 = (const __nv_bfloat16*)w2u;
    const uint32_t s0 = smem_u32(dsm);
    const uint32_t A_B = s0;
    const uint32_t H_B = s0 + 32768u;
    const uint32_t W_B = s0 + 65536u;
    const int tid = threadIdx.x, lane = tid & 31, wid = tid >> 5;
    const int wm = wid >> 2, wn = wid & 3;
    const int m0 = blockIdx.x * 128;
    const int lrow = (lane & 7) + ((lane >> 3) & 1) * 8;
    const int lhi  = lane >> 4;

    #pragma unroll
    for (int it = 0; it < 8; it++) {
        int idx = tid + (it << 8);
        int r = idx >> 4, q = idx & 15;
        int kblk = q >> 3, qi = q & 7;
        uint32_t off = (uint32_t)((r << 7) | (qi << 4));
        off ^= (off >> 3) & 0x70;
        cpa16(A_B + (uint32_t)kblk * 16384u + off, A + (size_t)(m0 + r) * 128 + q * 8);
    }
    mlp_stage_w(W_B, W1, W2, 0, tid);

    float acc2[4][4][4];
    #pragma unroll
    for (int a = 0; a < 4; a++)
        #pragma unroll
        for (int b = 0; b < 4; b++)
            #pragma unroll
            for (int c = 0; c < 4; c++) acc2[a][b][c] = 0.f;

    for (int c = 0; c < 4; c++) {
        if (c + 1 < 4) mlp_stage_w(W_B + (uint32_t)((c + 1) & 1) * 65536u, W1, W2, c + 1, tid);
        if (c + 1 < 4) { asm volatile("cp.async.wait_group 1;" ::: "memory"); }
        else           { asm volatile("cp.async.wait_group 0;" ::: "memory"); }
        __syncthreads();

        const uint32_t wb = W_B + (uint32_t)(c & 1) * 65536u;

        float acc1[4][4][4];
        #pragma unroll
        for (int a = 0; a < 4; a++)
            #pragma unroll
            for (int b = 0; b < 4; b++)
                #pragma unroll
                for (int q = 0; q < 4; q++) acc1[a][b][q] = 0.f;
        #pragma unroll
        for (int kb = 0; kb < 2; kb++) {
            const uint32_t ab = A_B + (uint32_t)kb * 16384u;
            const uint32_t bb = wb + (uint32_t)kb * 16384u;
            #pragma unroll
            for (int ks = 0; ks < 4; ks++) {
                uint32_t af[4][4], bf[2][4];
                const int chunk = ks * 2 + lhi;
                #pragma unroll
                for (int tm = 0; tm < 4; tm++) {
                    int row = wm * 64 + tm * 16 + lrow;
                    ldsm4(af[tm], ab + (uint32_t)(row * 128 + ((chunk ^ (row & 7)) << 4)));
                }
                #pragma unroll
                for (int t2 = 0; t2 < 2; t2++) {
                    int row = wn * 32 + t2 * 16 + lrow;
                    ldsm4(bf[t2], bb + (uint32_t)(row * 128 + ((chunk ^ (row & 7)) << 4)));
                }
                #pragma unroll
                for (int tm = 0; tm < 4; tm++)
                    #pragma unroll
                    for (int tn = 0; tn < 4; tn++)
                        mma_bf16(acc1[tm][tn],
                                 af[tm][0], af[tm][1], af[tm][2], af[tm][3],
                                 bf[tn >> 1][tn & 1], bf[tn >> 1][2 + (tn & 1)]);
            }
        }

        {
            float2 bs1[4];
            #pragma unroll
            for (int tn = 0; tn < 4; tn++)
                bs1[tn] = *(const float2*)(b1 + c * 128 + wn * 32 + tn * 8 + (lane & 3) * 2);
            #pragma unroll
            for (int tm = 0; tm < 4; tm++) {
                #pragma unroll
                for (int h = 0; h < 2; h++) {
                    const int row = wm * 64 + tm * 16 + (lane >> 2) + h * 8;
                    #pragma unroll
                    for (int tn = 0; tn < 4; tn++) {
                        const int nn = wn * 32 + tn * 8 + (lane & 3) * 2;
                        float v0 = acc1[tm][tn][h * 2 + 0] + bs1[tn].x;
                        float v1 = acc1[tm][tn][h * 2 + 1] + bs1[tn].y;
                        v0 = 0.5f * v0 * (1.f + erff(v0 * 0.70710678118654752f));
                        v1 = 0.5f * v1 * (1.f + erff(v1 * 0.70710678118654752f));
                        uint32_t boff = (uint32_t)((row << 7) + (nn & 63) * 2);
                        boff ^= (boff >> 3) & 0x70;
                        uint32_t dst = H_B + ((nn >= 64) ? 16384u : 0u) + boff;
                        asm volatile("st.shared.b32 [%0], %1;" :: "r"(dst), "r"(packbf(v0, v1)) : "memory");
                    }
                }
            }
        }
        __syncthreads();

        #pragma unroll
        for (int kb = 0; kb < 2; kb++) {
            const uint32_t ab = H_B + (uint32_t)kb * 16384u;
            const uint32_t bb = wb + 32768u + (uint32_t)kb * 16384u;
            #pragma unroll
            for (int ks = 0; ks < 4; ks++) {
                uint32_t af[4][4], bf[2][4];
                const int chunk = ks * 2 + lhi;
                #pragma unroll
                for (int tm = 0; tm < 4; tm++) {
                    int row = wm * 64 + tm * 16 + lrow;
                    ldsm4(af[tm], ab + (uint32_t)(row * 128 + ((chunk ^ (row & 7)) << 4)));
                }
                #pragma unroll
                for (int t2 = 0; t2 < 2; t2++) {
                    int row = wn * 32 + t2 * 16 + lrow;
                    ldsm4(bf[t2], bb + (uint32_t)(row * 128 + ((chunk ^ (row & 7)) << 4)));
                }
                #pragma unroll
                for (int tm = 0; tm < 4; tm++)
                    #pragma unroll
                    for (int tn = 0; tn < 4; tn++)
                        mma_bf16(acc2[tm][tn],
                                 af[tm][0], af[tm][1], af[tm][2], af[tm][3],
                                 bf[tn >> 1][tn & 1], bf[tn >> 1][2 + (tn & 1)]);
            }
        }
        __syncthreads();
    }

    float2 bs[4];
    #pragma unroll
    for (int tn = 0; tn < 4; tn++)
        bs[tn] = *(const float2*)(b2 + wn * 32 + tn * 8 + (lane & 3) * 2);
    #pragma unroll
    for (int tm = 0; tm < 4; tm++) {
        #pragma unroll
        for (int h = 0; h < 2; h++) {
            const int m = m0 + wm * 64 + tm * 16 + (lane >> 2) + h * 8;
            #pragma unroll
            for (int tn = 0; tn < 4; tn++) {
                const int nn = wn * 32 + tn * 8 + (lane & 3) * 2;
                float2 r2 = *(const float2*)(res + (size_t)m * 128 + nn);
                float v0 = acc2[tm][tn][h * 2 + 0] + bs[tn].x + r2.x;
                float v1 = acc2[tm][tn][h * 2 + 1] + bs[tn].y + r2.y;
                *(float2*)(out + (size_t)m * 128 + nn) = make_float2(v0, v1);
            }
        }
    }
}

// ---------------- HMMA windowed attention (head-major qkv/ao) -----------------
__device__ __forceinline__ int reg3(int y) { return y < 120 ? 0 : (y < 124 ? 1 : 2); }

__global__ __launch_bounds__(128) void attn_mma(
    const unsigned short* __restrict__ qkvu, const float* __restrict__ rpb,
    unsigned short* __restrict__ aou)
{
    __shared__ __align__(16) unsigned short qs[64 * 40];
    __shared__ __align__(16) unsigned short ks[64 * 40];
    __shared__ __align__(16) unsigned short vs[64 * 40];
    __shared__ float rpbs[900];
    __shared__ int  regtok[64];
    const __nv_bfloat16* qkv = (const __nv_bfloat16*)qkvu;
    const int tid = threadIdx.x, lane = tid & 31, wm = tid >> 5;
    const int w = blockIdx.x >> 2, h = blockIdx.x & 3;

    {
        const size_t tokbase = (size_t)w * 64;
        #pragma unroll
        for (int it = 0; it < 6; it++) {
            int c = tid + it * 128;
            int mat = c >> 8, rem = c & 255;
            int row = rem >> 2, ch = rem & 3;
            // head-major: contiguous 4KB per (mat, h) slice
            const uint4 v = *(const uint4*)(qkv +
                ((size_t)(mat * 4 + h) * MTOK + tokbase + row) * 32 + ch * 8);
            unsigned short* dst = (mat == 0 ? qs : (mat == 1 ? ks : vs));
            *(uint4*)(dst + row * 40 + ch * 8) = v;
        }
        #pragma unroll
        for (int it = 0; it < 8; it++) {
            int idx = tid + it * 128;
            if (idx < 900) rpbs[idx] = rpb[idx];
        }
        if (tid < 64) {
            int wrem = w & 255, wi = wrem >> 4, wj = wrem & 15;
            regtok[tid] = 3 * reg3(wi * 8 + (tid >> 3)) + reg3(wj * 8 + (tid & 7));
        }
    }
    __syncthreads();

    const uint32_t qb = smem_u32(qs), kb_ = smem_u32(ks), vb_ = smem_u32(vs);
    const int lr8 = (lane & 7) + ((lane >> 3) & 1) * 8;
    const uint32_t lh16 = ((lane >> 4) & 1) * 16;

    uint32_t qa[2][4];
    {
        uint32_t addr = qb + (uint32_t)((wm * 16 + lr8) * 80) + lh16;
        ldsm4(qa[0], addr);
        ldsm4(qa[1], addr + 32);
    }
    uint32_t kf[4][2][4];
    #pragma unroll
    for (int nt = 0; nt < 4; nt++) {
        uint32_t addr = kb_ + (uint32_t)((nt * 16 + lr8) * 80) + lh16;
        ldsm4(kf[nt][0], addr);
        ldsm4(kf[nt][1], addr + 32);
    }

    float sc[8][4];
    #pragma unroll
    for (int i = 0; i < 8; i++)
        #pragma unroll
        for (int c = 0; c < 4; c++) sc[i][c] = 0.f;
    #pragma unroll
    for (int nt8 = 0; nt8 < 8; nt8++) {
        const int nt = nt8 >> 1, ii = nt8 & 1;
        mma_bf16(sc[nt8], qa[0][0], qa[0][1], qa[0][2], qa[0][3], kf[nt][0][ii], kf[nt][0][2 + ii]);
        mma_bf16(sc[nt8], qa[1][0], qa[1][1], qa[1][2], qa[1][3], kf[nt][1][ii], kf[nt][1][2 + ii]);
    }

    const float scale = 0.17677669529663689f;
    const int r0 = wm * 16 + (lane >> 2), r1 = r0 + 8;
    const int rg0 = regtok[r0], rg1 = regtok[r1];
    const int i1a = r0 >> 3, j1a = r0 & 7, i1b = r1 >> 3, j1b = r1 & 7;
    #pragma unroll
    for (int nt8 = 0; nt8 < 8; nt8++) {
        #pragma unroll
        for (int c = 0; c < 4; c++) {
            const int col = nt8 * 8 + (lane & 3) * 2 + (c & 1);
            const int i2 = col >> 3, j2 = col & 7;
            const int rgc = regtok[col];
            float v = sc[nt8][c] * scale;
            if (c < 2) {
                v += rpbs[((i1a - i2 + 7) * 15 + (j1a - j2 + 7)) * 4 + h];
                if (rgc != rg0) v -= 100.f;
            } else {
                v += rpbs[((i1b - i2 + 7) * 15 + (j1b - j2 + 7)) * 4 + h];
                if (rgc != rg1) v -= 100.f;
            }
            sc[nt8][c] = v;
        }
    }

    float mx0 = -1e30f, mx1 = -1e30f;
    #pragma unroll
    for (int nt8 = 0; nt8 < 8; nt8++) {
        mx0 = fmaxf(mx0, fmaxf(sc[nt8][0], sc[nt8][1]));
        mx1 = fmaxf(mx1, fmaxf(sc[nt8][2], sc[nt8][3]));
    }
    #pragma unroll
    for (int o = 1; o <= 2; o <<= 1) {
        mx0 = fmaxf(mx0, __shfl_xor_sync(0xffffffffu, mx0, o));
        mx1 = fmaxf(mx1, __shfl_xor_sync(0xffffffffu, mx1, o));
    }
    float sm0 = 0.f, sm1 = 0.f;
    #pragma unroll
    for (int nt8 = 0; nt8 < 8; nt8++) {
        sc[nt8][0] = __expf(sc[nt8][0] - mx0);
        sc[nt8][1] = __expf(sc[nt8][1] - mx0);
        sc[nt8][2] = __expf(sc[nt8][2] - mx1);
        sc[nt8][3] = __expf(sc[nt8][3] - mx1);
        sm0 += sc[nt8][0] + sc[nt8][1];
        sm1 += sc[nt8][2] + sc[nt8][3];
    }
    #pragma unroll
    for (int o = 1; o <= 2; o <<= 1) {
        sm0 += __shfl_xor_sync(0xffffffffu, sm0, o);
        sm1 += __shfl_xor_sync(0xffffffffu, sm1, o);
    }
    const float inv0 = 1.f / sm0, inv1 = 1.f / sm1;

    float oc[4][4];
    #pragma unroll
    for (int nt = 0; nt < 4; nt++)
        #pragma unroll
        for (int c = 0; c < 4; c++) oc[nt][c] = 0.f;
    #pragma unroll
    for (int kc = 0; kc < 4; kc++) {
        const uint32_t a0 = packbf(sc[2 * kc][0],     sc[2 * kc][1]);
        const uint32_t a1 = packbf(sc[2 * kc][2],     sc[2 * kc][3]);
        const uint32_t a2 = packbf(sc[2 * kc + 1][0], sc[2 * kc + 1][1]);
        const uint32_t a3 = packbf(sc[2 * kc + 1][2], sc[2 * kc + 1][3]);
        uint32_t vf0[4], vf1[4];
        const uint32_t vaddr = vb_ + (uint32_t)((kc * 16 + lr8) * 80) + lh16;
        ldsm4t(vf0, vaddr);
        ldsm4t(vf1, vaddr + 32);
        mma_bf16(oc[0], a0, a1, a2, a3, vf0[0], vf0[1]);
        mma_bf16(oc[1], a0, a1, a2, a3, vf0[2], vf0[3]);
        mma_bf16(oc[2], a0, a1, a2, a3, vf1[0], vf1[1]);
        mma_bf16(oc[3], a0, a1, a2, a3, vf1[2], vf1[3]);
    }

    // head-major ao: [h][tok][32] — contiguous 4KB per block
    __nv_bfloat16* ao = (__nv_bfloat16*)aou;
    const size_t t0 = (size_t)h * MTOK + (size_t)w * 64;
    #pragma unroll
    for (int nt = 0; nt < 4; nt++) {
        const int ch = nt * 8 + (lane & 3) * 2;
        *(uint32_t*)(ao + (t0 + r0) * 32 + ch) = packbf(oc[nt][0] * inv0, oc[nt][1] * inv0);
        *(uint32_t*)(ao + (t0 + r1) * 32 + ch) = packbf(oc[nt][2] * inv1, oc[nt][3] * inv1);
    }
}

// ---------------- launch ----------------
extern "C" void kernel_launch(void* const* d_in, const int* in_sizes, int n_in,
                              void* d_out, int out_size)
{
    const float* x      = (const float*)d_in[0];
    const float* rpb    = (const float*)d_in[1];
    const float* n1g    = (const float*)d_in[2];
    const float* n1b    = (const float*)d_in[3];
    const float* qkv_w  = (const float*)d_in[4];
    const float* qkv_b  = (const float*)d_in[5];
    const float* proj_w = (const float*)d_in[6];
    const float* proj_b = (const float*)d_in[7];
    const float* n2g    = (const float*)d_in[8];
    const float* n2b    = (const float*)d_in[9];
    const float* fc1_w  = (const float*)d_in[10];
    const float* fc1_b  = (const float*)d_in[11];
    const float* fc2_w  = (const float*)d_in[12];
    const float* fc2_b  = (const float*)d_in[13];
    float* out = (float*)d_out;

    unsigned short *ln1, *qkv, *ao, *ln2, *wq, *wp, *w1, *w2;
    float *x1;
    cudaGetSymbolAddress((void**)&ln1, g_ln1);
    cudaGetSymbolAddress((void**)&qkv, g_qkv);
    cudaGetSymbolAddress((void**)&ao,  g_ao);
    cudaGetSymbolAddress((void**)&x1,  g_x1);
    cudaGetSymbolAddress((void**)&ln2, g_ln2);
    cudaGetSymbolAddress((void**)&wq,  g_wq);
    cudaGetSymbolAddress((void**)&wp,  g_wp);
    cudaGetSymbolAddress((void**)&w1,  g_w1);
    cudaGetSymbolAddress((void**)&w2,  g_w2);

    cudaFuncSetAttribute(gemm_mma, cudaFuncAttributeMaxDynamicSharedMemorySize, GSMEM);
    cudaFuncSetAttribute(mlp_fused, cudaFuncAttributeMaxDynamicSharedMemorySize, MSMEM);

    const int M = MTOK;

    f2bf_all<<<192, 256>>>(qkv_w, wq, proj_w, wp, fc1_w, w1, fc2_w, w2);

    // 1) LN1 + cyclic shift + window partition (bf16)
    ln_kernel<<<M / 8, 256>>>(x, n1g, n1b, ln1, 1);
    // 2) QKV GEMM -> head-major [mat][h][tok][32]
    gemm_mma<<<dim3(3, M / 128), 256, GSMEM>>>(ln1, wq, qkv_b, nullptr, qkv, M, 384, 128, 5);
    // 3) HMMA windowed attention (head-major in/out)
    attn_mma<<<8192, 128>>>(qkv, rpb, ao);
    // 4) proj GEMM (A gathered head-major) + scatter + residual (fp32 out)
    gemm_mma<<<dim3(1, M / 128), 256, GSMEM>>>(ao, wp, proj_b, x, x1, M, 128, 128, 6);
    // 5) LN2 (bf16)
    ln_kernel<<<M / 8, 256>>>(x1, n2g, n2b, ln2, 0);
    // 6+7) fused MLP: out = x1 + fc2(GELU(fc1(ln2)))
    mlp_fused<<<M / 128, 256, MSMEM>>>(ln2, w1, fc1_b, w2, fc2_b, x1, out);
}

// round 8
// speedup vs baseline: 2.0590x; 1.0286x over previous
#include <cuda_runtime.h>
#include <cuda_bf16.h>
#include <math.h>
#include <stdint.h>

// B=8, H=W=128, C=128, HEADS=4, d=32, WS=8, SHIFT=4, HIDDEN=512
#define MTOK 131072

// ---------------- scratch (device globals; no allocs allowed) ----------------
static __device__ unsigned short g_ln1[(size_t)MTOK * 128];  // bf16
static __device__ float          g_x1 [(size_t)MTOK * 128];  // fp32 residual 1
static __device__ unsigned short g_ln2[(size_t)MTOK * 128];  // bf16
static __device__ unsigned short g_wq[384 * 128];
static __device__ unsigned short g_wp[128 * 128];
static __device__ unsigned short g_w1[512 * 128];
static __device__ unsigned short g_w2[128 * 512];

// ---------------- PTX helpers (sm_80+ features only) ----------------
static __device__ __forceinline__ uint32_t smem_u32(const void* p) {
    uint32_t a;
    asm("{ .reg .u64 t; cvta.to.shared.u64 t, %1; cvt.u32.u64 %0, t; }" : "=r"(a) : "l"(p));
    return a;
}
static __device__ __forceinline__ void cpa16(uint32_t s, const void* g) {
    asm volatile("cp.async.cg.shared.global [%0], [%1], 16;" :: "r"(s), "l"(g) : "memory");
}
static __device__ __forceinline__ void ldsm4(uint32_t* r, uint32_t addr) {
    asm volatile("ldmatrix.sync.aligned.m8n8.x4.shared.b16 {%0,%1,%2,%3}, [%4];"
                 : "=r"(r[0]), "=r"(r[1]), "=r"(r[2]), "=r"(r[3]) : "r"(addr));
}
static __device__ __forceinline__ void ldsm4t(uint32_t* r, uint32_t addr) {
    asm volatile("ldmatrix.sync.aligned.m8n8.x4.trans.shared.b16 {%0,%1,%2,%3}, [%4];"
                 : "=r"(r[0]), "=r"(r[1]), "=r"(r[2]), "=r"(r[3]) : "r"(addr));
}
static __device__ __forceinline__ void mma_bf16(float* c,
    uint32_t a0, uint32_t a1, uint32_t a2, uint32_t a3, uint32_t b0, uint32_t b1) {
    asm volatile(
        "mma.sync.aligned.m16n8k16.row.col.f32.bf16.bf16.f32 "
        "{%0,%1,%2,%3}, {%4,%5,%6,%7}, {%8,%9}, {%0,%1,%2,%3};"
        : "+f"(c[0]), "+f"(c[1]), "+f"(c[2]), "+f"(c[3])
        : "r"(a0), "r"(a1), "r"(a2), "r"(a3), "r"(b0), "r"(b1));
}
static __device__ __forceinline__ uint32_t packbf(float a, float b) {
    __nv_bfloat162 p = __floats2bfloat162_rn(a, b);
    return *reinterpret_cast<uint32_t*>(&p);
}

// ---------------- merged fp32 -> bf16 weight conversion ----------------
__global__ __launch_bounds__(256) void f2bf_all(
    const float* __restrict__ s0, unsigned short* __restrict__ d0,
    const float* __restrict__ s1, unsigned short* __restrict__ d1,
    const float* __restrict__ s2, unsigned short* __restrict__ d2,
    const float* __restrict__ s3, unsigned short* __restrict__ d3)
{
    int i = blockIdx.x * 256 + threadIdx.x;
    const float* s; unsigned short* d; int o;
    if (i < 12288)      { s = s0; d = d0; o = i; }
    else if (i < 16384) { s = s1; d = d1; o = i - 12288; }
    else if (i < 32768) { s = s2; d = d2; o = i - 16384; }
    else                { s = s3; d = d3; o = i - 32768; }
    float4 v = ((const float4*)s)[o];
    uint2 u;
    u.x = packbf(v.x, v.y);
    u.y = packbf(v.z, v.w);
    ((uint2*)d)[o] = u;
}

// ---------------- LayerNorm (warp/token), optional shift-gather, bf16 out ------
__global__ __launch_bounds__(256) void ln_kernel(
    const float* __restrict__ xin, const float* __restrict__ gam,
    const float* __restrict__ bet, unsigned short* __restrict__ out, int gather)
{
    int t = (blockIdx.x * blockDim.x + threadIdx.x) >> 5;
    int lane = threadIdx.x & 31;
    size_t src;
    if (gather) {
        int w = t >> 6, n = t & 63;
        int b = w >> 8, wrem = w & 255;
        int wi = wrem >> 4, wj = wrem & 15;
        int i = n >> 3, j = n & 7;
        int y  = (wi * 8 + i + 4) & 127;
        int xc = (wj * 8 + j + 4) & 127;
        src = ((size_t)b << 14) + (size_t)y * 128 + xc;
    } else {
        src = (size_t)t;
    }
    float4 v = *(const float4*)(xin + src * 128 + lane * 4);
    float s  = v.x + v.y + v.z + v.w;
    float sq = v.x * v.x + v.y * v.y + v.z * v.z + v.w * v.w;
    #pragma unroll
    for (int o = 16; o; o >>= 1) {
        s  += __shfl_xor_sync(0xffffffffu, s,  o);
        sq += __shfl_xor_sync(0xffffffffu, sq, o);
    }
    float mean = s * (1.f / 128.f);
    float rstd = rsqrtf(sq * (1.f / 128.f) - mean * mean + 1e-5f);
    float4 g4 = *(const float4*)(gam + lane * 4);
    float4 b4 = *(const float4*)(bet + lane * 4);
    uint2 u;
    u.x = packbf((v.x - mean) * rstd * g4.x + b4.x, (v.y - mean) * rstd * g4.y + b4.y);
    u.y = packbf((v.z - mean) * rstd * g4.z + b4.z, (v.w - mean) * rstd * g4.w + b4.w);
    *(uint2*)(out + (size_t)t * 128 + lane * 4) = u;
}

// ---------------- shared GEMM inner core: C128x128 += A(2 kblk) @ B(2 kblk)^T --
static __device__ __forceinline__ void gemm128(
    uint32_t abase, uint32_t bbase, float acc[4][4][4],
    int wm, int wn, int lrow, int lhi)
{
    #pragma unroll
    for (int kb = 0; kb < 2; kb++) {
        const uint32_t ab = abase + (uint32_t)kb * 16384u;
        const uint32_t bb = bbase + (uint32_t)kb * 16384u;
        #pragma unroll
        for (int ks = 0; ks < 4; ks++) {
            uint32_t af[4][4], bf[2][4];
            const int chunk = ks * 2 + lhi;
            #pragma unroll
            for (int tm = 0; tm < 4; tm++) {
                int row = wm * 64 + tm * 16 + lrow;
                ldsm4(af[tm], ab + (uint32_t)(row * 128 + ((chunk ^ (row & 7)) << 4)));
            }
            #pragma unroll
            for (int t2 = 0; t2 < 2; t2++) {
                int row = wn * 32 + t2 * 16 + lrow;
                ldsm4(bf[t2], bb + (uint32_t)(row * 128 + ((chunk ^ (row & 7)) << 4)));
            }
            #pragma unroll
            for (int tm = 0; tm < 4; tm++)
                #pragma unroll
                for (int tn = 0; tn < 4; tn++)
                    mma_bf16(acc[tm][tn],
                             af[tm][0], af[tm][1], af[tm][2], af[tm][3],
                             bf[tn >> 1][tn & 1], bf[tn >> 1][2 + (tn & 1)]);
        }
    }
}

// stage a 128x128 bf16 row-major matrix into 2 swizzled kblocks
static __device__ __forceinline__ void stage128(
    uint32_t dst, const __nv_bfloat16* src, int tid)
{
    #pragma unroll
    for (int it = 0; it < 8; it++) {
        int idx = tid + (it << 8);
        int r = idx >> 4, q = idx & 15;
        int kblk = q >> 3, qi = q & 7;
        uint32_t off = (uint32_t)((r << 7) | (qi << 4));
        off ^= (off >> 3) & 0x70;
        cpa16(dst + (uint32_t)kblk * 16384u + off, src + (size_t)r * 128 + q * 8);
    }
}

// ---------------- fused block: QKV GEMM + attention + proj + scatter-residual -
// CTA = 128 tokens = 2 windows. smem:
//  A_B   [0, 32768)        : ln1 A-tile, later reused as attn-output (proj A)
//  Q_B   [32768, 155648)   : 12 slices (mat*4+h) x 128 rows x 80B
//  W_B   [155648, 221184)  : 2 x 32KB weight double-buffer
//  RPB   [221184, 224784)  : 900 floats
//  RGT   [224784, 225296)  : 128 ints (region ids, 2 windows)
#define FSMEM 225296
__device__ __forceinline__ int reg3(int y) { return y < 120 ? 0 : (y < 124 ? 1 : 2); }

__global__ __launch_bounds__(256) void block_fused(
    const unsigned short* __restrict__ ln1u, const unsigned short* __restrict__ wqu,
    const float* __restrict__ qkv_b, const unsigned short* __restrict__ wpu,
    const float* __restrict__ proj_b, const float* __restrict__ rpb,
    const float* __restrict__ xres, float* __restrict__ x1)
{
    extern __shared__ char dsm[];
    const __nv_bfloat16* ln1 = (const __nv_bfloat16*)ln1u;
    const __nv_bfloat16* wq  = (const __nv_bfloat16*)wqu;
    const __nv_bfloat16* wp  = (const __nv_bfloat16*)wpu;
    const uint32_t s0 = smem_u32(dsm);
    const uint32_t A_B = s0;
    const uint32_t Q_B = s0 + 32768u;
    const uint32_t W_B = s0 + 155648u;
    float* rpbs = (float*)(dsm + 221184);
    int*   rgt  = (int*)(dsm + 224784);
    const int tid = threadIdx.x, lane = tid & 31, wid = tid >> 5;
    const int wm = wid >> 2, wn = wid & 3;
    const int m0 = blockIdx.x * 128;
    const int lrow = (lane & 7) + ((lane >> 3) & 1) * 8;
    const int lhi  = lane >> 4;

    // stage A (ln1 tile) + W chunk 0, and rpb/regtok via regular loads
    stage128(A_B, ln1 + (size_t)m0 * 128, tid);
    stage128(W_B, wq, tid);
    asm volatile("cp.async.commit_group;" ::: "memory");
    for (int i = tid; i < 900; i += 256) rpbs[i] = rpb[i];
    if (tid < 128) {
        int lw = tid >> 6, n = tid & 63;
        int w = (m0 >> 6) + lw, wrem = w & 255;
        int wi = wrem >> 4, wj = wrem & 15;
        rgt[tid] = 3 * reg3(wi * 8 + (n >> 3)) + reg3(wj * 8 + (n & 7));
    }

    // ---- phase 1: QKV GEMM, 3 chunks of N=128 (chunk c == matrix c, wn == head)
    for (int c = 0; c < 3; c++) {
        if (c < 2) {
            stage128(W_B + (uint32_t)((c + 1) & 1) * 32768u, wq + (size_t)(c + 1) * 128 * 128, tid);
            asm volatile("cp.async.commit_group;" ::: "memory");
            asm volatile("cp.async.wait_group 1;" ::: "memory");
        } else {
            asm volatile("cp.async.wait_group 0;" ::: "memory");
        }
        __syncthreads();

        float acc[4][4][4];
        #pragma unroll
        for (int a = 0; a < 4; a++)
            #pragma unroll
            for (int b = 0; b < 4; b++)
                #pragma unroll
                for (int q = 0; q < 4; q++) acc[a][b][q] = 0.f;
        gemm128(A_B, W_B + (uint32_t)(c & 1) * 32768u, acc, wm, wn, lrow, lhi);

        // epilogue -> Q_B slice (c*4 + wn), rows 0..127, cols tn*8+(lane&3)*2
        float2 bs[4];
        #pragma unroll
        for (int tn = 0; tn < 4; tn++)
            bs[tn] = *(const float2*)(qkv_b + c * 128 + wn * 32 + tn * 8 + (lane & 3) * 2);
        const uint32_t slice = Q_B + (uint32_t)(c * 4 + wn) * 10240u;
        #pragma unroll
        for (int tm = 0; tm < 4; tm++) {
            #pragma unroll
            for (int h8 = 0; h8 < 2; h8++) {
                const int row = wm * 64 + tm * 16 + (lane >> 2) + h8 * 8;
                #pragma unroll
                for (int tn = 0; tn < 4; tn++) {
                    const int c32 = tn * 8 + (lane & 3) * 2;
                    float v0 = acc[tm][tn][h8 * 2 + 0] + bs[tn].x;
                    float v1 = acc[tm][tn][h8 * 2 + 1] + bs[tn].y;
                    asm volatile("st.shared.b32 [%0], %1;"
                                 :: "r"(slice + (uint32_t)(row * 80 + c32 * 2)),
                                    "r"(packbf(v0, v1)) : "memory");
                }
            }
        }
        __syncthreads();
    }

    // prefetch proj weights into W buf1 (buf1 reads finished after chunk 1)
    stage128(W_B + 32768u, wp, tid);
    asm volatile("cp.async.commit_group;" ::: "memory");

    // ---- phase 2: attention. warps [0..3] -> window 0, [4..7] -> window 1.
    {
        const int lw = wid >> 2, wm4 = wid & 3;
        const int lr8 = lrow;
        const uint32_t lh16 = (uint32_t)lhi * 16u;
        const uint32_t rowbase = (uint32_t)(lw * 64) * 80u;
        const int r0 = wm4 * 16 + (lane >> 2), r1 = r0 + 8;
        const int rg0 = rgt[lw * 64 + r0], rg1 = rgt[lw * 64 + r1];
        const int i1a = r0 >> 3, j1a = r0 & 7, i1b = r1 >> 3, j1b = r1 & 7;
        const float scale = 0.17677669529663689f;

        #pragma unroll 1
        for (int h = 0; h < 4; h++) {
            const uint32_t qsl = Q_B + (uint32_t)(0 + h) * 10240u + rowbase;
            const uint32_t ksl = Q_B + (uint32_t)(4 + h) * 10240u + rowbase;
            const uint32_t vsl = Q_B + (uint32_t)(8 + h) * 10240u + rowbase;

            uint32_t qa[2][4];
            {
                uint32_t addr = qsl + (uint32_t)((wm4 * 16 + lr8) * 80) + lh16;
                ldsm4(qa[0], addr);
                ldsm4(qa[1], addr + 32);
            }
            uint32_t kf[4][2][4];
            #pragma unroll
            for (int nt = 0; nt < 4; nt++) {
                uint32_t addr = ksl + (uint32_t)((nt * 16 + lr8) * 80) + lh16;
                ldsm4(kf[nt][0], addr);
                ldsm4(kf[nt][1], addr + 32);
            }

            float sc[8][4];
            #pragma unroll
            for (int i = 0; i < 8; i++)
                #pragma unroll
                for (int q = 0; q < 4; q++) sc[i][q] = 0.f;
            #pragma unroll
            for (int nt8 = 0; nt8 < 8; nt8++) {
                const int nt = nt8 >> 1, ii = nt8 & 1;
                mma_bf16(sc[nt8], qa[0][0], qa[0][1], qa[0][2], qa[0][3],
                         kf[nt][0][ii], kf[nt][0][2 + ii]);
                mma_bf16(sc[nt8], qa[1][0], qa[1][1], qa[1][2], qa[1][3],
                         kf[nt][1][ii], kf[nt][1][2 + ii]);
            }

            #pragma unroll
            for (int nt8 = 0; nt8 < 8; nt8++) {
                #pragma unroll
                for (int q = 0; q < 4; q++) {
                    const int col = nt8 * 8 + (lane & 3) * 2 + (q & 1);
                    const int i2 = col >> 3, j2 = col & 7;
                    const int rgc = rgt[lw * 64 + col];
                    float v = sc[nt8][q] * scale;
                    if (q < 2) {
                        v += rpbs[((i1a - i2 + 7) * 15 + (j1a - j2 + 7)) * 4 + h];
                        if (rgc != rg0) v -= 100.f;
                    } else {
                        v += rpbs[((i1b - i2 + 7) * 15 + (j1b - j2 + 7)) * 4 + h];
                        if (rgc != rg1) v -= 100.f;
                    }
                    sc[nt8][q] = v;
                }
            }

            float mx0 = -1e30f, mx1 = -1e30f;
            #pragma unroll
            for (int nt8 = 0; nt8 < 8; nt8++) {
                mx0 = fmaxf(mx0, fmaxf(sc[nt8][0], sc[nt8][1]));
                mx1 = fmaxf(mx1, fmaxf(sc[nt8][2], sc[nt8][3]));
            }
            #pragma unroll
            for (int o = 1; o <= 2; o <<= 1) {
                mx0 = fmaxf(mx0, __shfl_xor_sync(0xffffffffu, mx0, o));
                mx1 = fmaxf(mx1, __shfl_xor_sync(0xffffffffu, mx1, o));
            }
            float sm0 = 0.f, sm1 = 0.f;
            #pragma unroll
            for (int nt8 = 0; nt8 < 8; nt8++) {
                sc[nt8][0] = __expf(sc[nt8][0] - mx0);
                sc[nt8][1] = __expf(sc[nt8][1] - mx0);
                sc[nt8][2] = __expf(sc[nt8][2] - mx1);
                sc[nt8][3] = __expf(sc[nt8][3] - mx1);
                sm0 += sc[nt8][0] + sc[nt8][1];
                sm1 += sc[nt8][2] + sc[nt8][3];
            }
            #pragma unroll
            for (int o = 1; o <= 2; o <<= 1) {
                sm0 += __shfl_xor_sync(0xffffffffu, sm0, o);
                sm1 += __shfl_xor_sync(0xffffffffu, sm1, o);
            }
            const float inv0 = 1.f / sm0, inv1 = 1.f / sm1;

            float oc[4][4];
            #pragma unroll
            for (int nt = 0; nt < 4; nt++)
                #pragma unroll
                for (int q = 0; q < 4; q++) oc[nt][q] = 0.f;
            #pragma unroll
            for (int kc = 0; kc < 4; kc++) {
                const uint32_t a0 = packbf(sc[2 * kc][0],     sc[2 * kc][1]);
                const uint32_t a1 = packbf(sc[2 * kc][2],     sc[2 * kc][3]);
                const uint32_t a2 = packbf(sc[2 * kc + 1][0], sc[2 * kc + 1][1]);
                const uint32_t a3 = packbf(sc[2 * kc + 1][2], sc[2 * kc + 1][3]);
                uint32_t vf0[4], vf1[4];
                const uint32_t vaddr = vsl + (uint32_t)((kc * 16 + lr8) * 80) + lh16;
                ldsm4t(vf0, vaddr);
                ldsm4t(vf1, vaddr + 32);
                mma_bf16(oc[0], a0, a1, a2, a3, vf0[0], vf0[1]);
                mma_bf16(oc[1], a0, a1, a2, a3, vf0[2], vf0[3]);
                mma_bf16(oc[2], a0, a1, a2, a3, vf1[0], vf1[1]);
                mma_bf16(oc[3], a0, a1, a2, a3, vf1[2], vf1[3]);
            }

            // write attn output into A_B (GEMM-A layout) — conflict-free
            #pragma unroll
            for (int nt = 0; nt < 4; nt++) {
                const int ch = h * 32 + nt * 8 + (lane & 3) * 2;
                const uint32_t kblk = (uint32_t)(ch >> 6) * 16384u;
                uint32_t b0 = (uint32_t)(((lw * 64 + r0) << 7) + ((ch & 63) << 1));
                uint32_t b1 = (uint32_t)(((lw * 64 + r1) << 7) + ((ch & 63) << 1));
                b0 ^= (b0 >> 3) & 0x70;
                b1 ^= (b1 >> 3) & 0x70;
                asm volatile("st.shared.b32 [%0], %1;" ::
                    "r"(A_B + kblk + b0), "r"(packbf(oc[nt][0] * inv0, oc[nt][1] * inv0)) : "memory");
                asm volatile("st.shared.b32 [%0], %1;" ::
                    "r"(A_B + kblk + b1), "r"(packbf(oc[nt][2] * inv1, oc[nt][3] * inv1)) : "memory");
            }
        }
    }
    asm volatile("cp.async.wait_group 0;" ::: "memory");
    __syncthreads();

    // ---- phase 3: proj GEMM + scatter + residual ----
    {
        float acc[4][4][4];
        #pragma unroll
        for (int a = 0; a < 4; a++)
            #pragma unroll
            for (int b = 0; b < 4; b++)
                #pragma unroll
                for (int q = 0; q < 4; q++) acc[a][b][q] = 0.f;
        gemm128(A_B, W_B + 32768u, acc, wm, wn, lrow, lhi);

        float2 bs[4];
        #pragma unroll
        for (int tn = 0; tn < 4; tn++)
            bs[tn] = *(const float2*)(proj_b + wn * 32 + tn * 8 + (lane & 3) * 2);
        #pragma unroll
        for (int tm = 0; tm < 4; tm++) {
            #pragma unroll
            for (int h8 = 0; h8 < 2; h8++) {
                const int m = m0 + wm * 64 + tm * 16 + (lane >> 2) + h8 * 8;
                int w = m >> 6, nt2 = m & 63;
                int b = w >> 8, wrem = w & 255;
                int wwi = wrem >> 4, wwj = wrem & 15;
                int yf = (wwi * 8 + (nt2 >> 3) + 4) & 127;
                int xf = (wwj * 8 + (nt2 & 7) + 4) & 127;
                size_t mo = ((size_t)b << 14) + (size_t)yf * 128 + xf;
                #pragma unroll
                for (int tn = 0; tn < 4; tn++) {
                    const int nn = wn * 32 + tn * 8 + (lane & 3) * 2;
                    float2 r2 = *(const float2*)(xres + mo * 128 + nn);
                    float v0 = acc[tm][tn][h8 * 2 + 0] + bs[tn].x + r2.x;
                    float v1 = acc[tm][tn][h8 * 2 + 1] + bs[tn].y + r2.y;
                    *(float2*)(x1 + mo * 128 + nn) = make_float2(v0, v1);
                }
            }
        }
    }
}

// ---------------- fused MLP: out = x1 + fc2(GELU(fc1(ln2))) ------------------
#define MSMEM 196608
static __device__ __forceinline__ void mlp_stage_w(
    uint32_t wbuf, const __nv_bfloat16* W1, const __nv_bfloat16* W2, int c, int tid)
{
    const int nc0 = c * 128;
    #pragma unroll
    for (int it = 0; it < 8; it++) {
        int idx = tid + (it << 8);
        int r = idx >> 4, q = idx & 15;
        int kblk = q >> 3, qi = q & 7;
        uint32_t off = (uint32_t)((r << 7) | (qi << 4));
        off ^= (off >> 3) & 0x70;
        cpa16(wbuf + (uint32_t)kblk * 16384u + off,            W1 + (size_t)(nc0 + r) * 128 + q * 8);
        cpa16(wbuf + 32768u + (uint32_t)kblk * 16384u + off,   W2 + (size_t)r * 512 + nc0 + q * 8);
    }
    asm volatile("cp.async.commit_group;" ::: "memory");
}

__global__ __launch_bounds__(256) void mlp_fused(
    const unsigned short* __restrict__ ln2u, const unsigned short* __restrict__ w1u,
    const float* __restrict__ b1, const unsigned short* __restrict__ w2u,
    const float* __restrict__ b2, const float* __restrict__ res,
    float* __restrict__ out)
{
    extern __shared__ char dsm[];
    const __nv_bfloat16* A  = (const __nv_bfloat16*)ln2u;
    const __nv_bfloat16* W1 = (const __nv_bfloat16*)w1u;
    const __nv_bfloat16* W2 = (const __nv_bfloat16*)w2u;
    const uint32_t s0 = smem_u32(dsm);
    const uint32_t A_B = s0;
    const uint32_t H_B = s0 + 32768u;
    const uint32_t W_B = s0 + 65536u;
    const int tid = threadIdx.x, lane = tid & 31, wid = tid >> 5;
    const int wm = wid >> 2, wn = wid & 3;
    const int m0 = blockIdx.x * 128;
    const int lrow = (lane & 7) + ((lane >> 3) & 1) * 8;
    const int lhi  = lane >> 4;

    stage128(A_B, A + (size_t)m0 * 128, tid);
    mlp_stage_w(W_B, W1, W2, 0, tid);

    float acc2[4][4][4];
    #pragma unroll
    for (int a = 0; a < 4; a++)
        #pragma unroll
        for (int b = 0; b < 4; b++)
            #pragma unroll
            for (int c = 0; c < 4; c++) acc2[a][b][c] = 0.f;

    for (int c = 0; c < 4; c++) {
        if (c + 1 < 4) {
            mlp_stage_w(W_B + (uint32_t)((c + 1) & 1) * 65536u, W1, W2, c + 1, tid);
            asm volatile("cp.async.wait_group 1;" ::: "memory");
        } else {
            asm volatile("cp.async.wait_group 0;" ::: "memory");
        }
        __syncthreads();

        const uint32_t wb = W_B + (uint32_t)(c & 1) * 65536u;

        float acc1[4][4][4];
        #pragma unroll
        for (int a = 0; a < 4; a++)
            #pragma unroll
            for (int b = 0; b < 4; b++)
                #pragma unroll
                for (int q = 0; q < 4; q++) acc1[a][b][q] = 0.f;
        gemm128(A_B, wb, acc1, wm, wn, lrow, lhi);

        {
            float2 bs1[4];
            #pragma unroll
            for (int tn = 0; tn < 4; tn++)
                bs1[tn] = *(const float2*)(b1 + c * 128 + wn * 32 + tn * 8 + (lane & 3) * 2);
            #pragma unroll
            for (int tm = 0; tm < 4; tm++) {
                #pragma unroll
                for (int h = 0; h < 2; h++) {
                    const int row = wm * 64 + tm * 16 + (lane >> 2) + h * 8;
                    #pragma unroll
                    for (int tn = 0; tn < 4; tn++) {
                        const int nn = wn * 32 + tn * 8 + (lane & 3) * 2;
                        float v0 = acc1[tm][tn][h * 2 + 0] + bs1[tn].x;
                        float v1 = acc1[tm][tn][h * 2 + 1] + bs1[tn].y;
                        v0 = 0.5f * v0 * (1.f + erff(v0 * 0.70710678118654752f));
                        v1 = 0.5f * v1 * (1.f + erff(v1 * 0.70710678118654752f));
                        uint32_t boff = (uint32_t)((row << 7) + (nn & 63) * 2);
                        boff ^= (boff >> 3) & 0x70;
                        uint32_t dst = H_B + ((nn >= 64) ? 16384u : 0u) + boff;
                        asm volatile("st.shared.b32 [%0], %1;" :: "r"(dst), "r"(packbf(v0, v1)) : "memory");
                    }
                }
            }
        }
        __syncthreads();

        gemm128(H_B, wb + 32768u, acc2, wm, wn, lrow, lhi);
        __syncthreads();
    }

    float2 bs[4];
    #pragma unroll
    for (int tn = 0; tn < 4; tn++)
        bs[tn] = *(const float2*)(b2 + wn * 32 + tn * 8 + (lane & 3) * 2);
    #pragma unroll
    for (int tm = 0; tm < 4; tm++) {
        #pragma unroll
        for (int h = 0; h < 2; h++) {
            const int m = m0 + wm * 64 + tm * 16 + (lane >> 2) + h * 8;
            #pragma unroll
            for (int tn = 0; tn < 4; tn++) {
                const int nn = wn * 32 + tn * 8 + (lane & 3) * 2;
                float2 r2 = *(const float2*)(res + (size_t)m * 128 + nn);
                float v0 = acc2[tm][tn][h * 2 + 0] + bs[tn].x + r2.x;
                float v1 = acc2[tm][tn][h * 2 + 1] + bs[tn].y + r2.y;
                *(float2*)(out + (size_t)m * 128 + nn) = make_float2(v0, v1);
            }
        }
    }
}

// ---------------- launch ----------------
extern "C" void kernel_launch(void* const* d_in, const int* in_sizes, int n_in,
                              void* d_out, int out_size)
{
    const float* x      = (const float*)d_in[0];
    const float* rpb    = (const float*)d_in[1];
    const float* n1g    = (const float*)d_in[2];
    const float* n1b    = (const float*)d_in[3];
    const float* qkv_w  = (const float*)d_in[4];
    const float* qkv_b  = (const float*)d_in[5];
    const float* proj_w = (const float*)d_in[6];
    const float* proj_b = (const float*)d_in[7];
    const float* n2g    = (const float*)d_in[8];
    const float* n2b    = (const float*)d_in[9];
    const float* fc1_w  = (const float*)d_in[10];
    const float* fc1_b  = (const float*)d_in[11];
    const float* fc2_w  = (const float*)d_in[12];
    const float* fc2_b  = (const float*)d_in[13];
    float* out = (float*)d_out;

    unsigned short *ln1, *ln2, *wq, *wp, *w1, *w2;
    float *x1;
    cudaGetSymbolAddress((void**)&ln1, g_ln1);
    cudaGetSymbolAddress((void**)&x1,  g_x1);
    cudaGetSymbolAddress((void**)&ln2, g_ln2);
    cudaGetSymbolAddress((void**)&wq,  g_wq);
    cudaGetSymbolAddress((void**)&wp,  g_wp);
    cudaGetSymbolAddress((void**)&w1,  g_w1);
    cudaGetSymbolAddress((void**)&w2,  g_w2);

    cudaFuncSetAttribute(block_fused, cudaFuncAttributeMaxDynamicSharedMemorySize, FSMEM);
    cudaFuncSetAttribute(mlp_fused,   cudaFuncAttributeMaxDynamicSharedMemorySize, MSMEM);

    const int M = MTOK;

    f2bf_all<<<192, 256>>>(qkv_w, wq, proj_w, wp, fc1_w, w1, fc2_w, w2);

    // 1) LN1 + cyclic shift + window partition (bf16)
    ln_kernel<<<M / 8, 256>>>(x, n1g, n1b, ln1, 1);
    // 2) fused QKV GEMM + windowed attention + proj + scatter + residual
    block_fused<<<M / 128, 256, FSMEM>>>(ln1, wq, qkv_b, wp, proj_b, rpb, x, x1);
    // 3) LN2 (bf16)
    ln_kernel<<<M / 8, 256>>>(x1, n2g, n2b, ln2, 0);
    // 4) fused MLP: out = x1 + fc2(GELU(fc1(ln2)))
    mlp_fused<<<M / 128, 256, MSMEM>>>(ln2, w1, fc1_b, w2, fc2_b, x1, out);
}

// round 9
// speedup vs baseline: 2.0847x; 1.0125x over previous
#include <cuda_runtime.h>
#include <cuda_bf16.h>
#include <math.h>
#include <stdint.h>

// B=8, H=W=128, C=128, HEADS=4, d=32, WS=8, SHIFT=4, HIDDEN=512
#define MTOK 131072

// ---------------- scratch (device globals; no allocs allowed) ----------------
static __device__ float          g_x1 [(size_t)MTOK * 128];  // fp32 residual 1
static __device__ unsigned short g_wq[384 * 128];
static __device__ unsigned short g_wp[128 * 128];
static __device__ unsigned short g_w1[512 * 128];
static __device__ unsigned short g_w2[128 * 512];

// ---------------- PTX helpers (sm_80+ features only) ----------------
static __device__ __forceinline__ uint32_t smem_u32(const void* p) {
    uint32_t a;
    asm("{ .reg .u64 t; cvta.to.shared.u64 t, %1; cvt.u32.u64 %0, t; }" : "=r"(a) : "l"(p));
    return a;
}
static __device__ __forceinline__ void cpa16(uint32_t s, const void* g) {
    asm volatile("cp.async.cg.shared.global [%0], [%1], 16;" :: "r"(s), "l"(g) : "memory");
}
static __device__ __forceinline__ void ldsm4(uint32_t* r, uint32_t addr) {
    asm volatile("ldmatrix.sync.aligned.m8n8.x4.shared.b16 {%0,%1,%2,%3}, [%4];"
                 : "=r"(r[0]), "=r"(r[1]), "=r"(r[2]), "=r"(r[3]) : "r"(addr));
}
static __device__ __forceinline__ void ldsm4t(uint32_t* r, uint32_t addr) {
    asm volatile("ldmatrix.sync.aligned.m8n8.x4.trans.shared.b16 {%0,%1,%2,%3}, [%4];"
                 : "=r"(r[0]), "=r"(r[1]), "=r"(r[2]), "=r"(r[3]) : "r"(addr));
}
static __device__ __forceinline__ void mma_bf16(float* c,
    uint32_t a0, uint32_t a1, uint32_t a2, uint32_t a3, uint32_t b0, uint32_t b1) {
    asm volatile(
        "mma.sync.aligned.m16n8k16.row.col.f32.bf16.bf16.f32 "
        "{%0,%1,%2,%3}, {%4,%5,%6,%7}, {%8,%9}, {%0,%1,%2,%3};"
        : "+f"(c[0]), "+f"(c[1]), "+f"(c[2]), "+f"(c[3])
        : "r"(a0), "r"(a1), "r"(a2), "r"(a3), "r"(b0), "r"(b1));
}
static __device__ __forceinline__ uint32_t packbf(float a, float b) {
    __nv_bfloat162 p = __floats2bfloat162_rn(a, b);
    return *reinterpret_cast<uint32_t*>(&p);
}

// ---------------- merged fp32 -> bf16 weight conversion ----------------
__global__ __launch_bounds__(256) void f2bf_all(
    const float* __restrict__ s0, unsigned short* __restrict__ d0,
    const float* __restrict__ s1, unsigned short* __restrict__ d1,
    const float* __restrict__ s2, unsigned short* __restrict__ d2,
    const float* __restrict__ s3, unsigned short* __restrict__ d3)
{
    int i = blockIdx.x * 256 + threadIdx.x;
    const float* s; unsigned short* d; int o;
    if (i < 12288)      { s = s0; d = d0; o = i; }
    else if (i < 16384) { s = s1; d = d1; o = i - 12288; }
    else if (i < 32768) { s = s2; d = d2; o = i - 16384; }
    else                { s = s3; d = d3; o = i - 32768; }
    float4 v = ((const float4*)s)[o];
    uint2 u;
    u.x = packbf(v.x, v.y);
    u.y = packbf(v.z, v.w);
    ((uint2*)d)[o] = u;
}

// ---------------- shared GEMM inner core: C128x128 += A(2 kblk) @ B(2 kblk)^T --
static __device__ __forceinline__ void gemm128(
    uint32_t abase, uint32_t bbase, float acc[4][4][4],
    int wm, int wn, int lrow, int lhi)
{
    #pragma unroll
    for (int kb = 0; kb < 2; kb++) {
        const uint32_t ab = abase + (uint32_t)kb * 16384u;
        const uint32_t bb = bbase + (uint32_t)kb * 16384u;
        #pragma unroll
        for (int ks = 0; ks < 4; ks++) {
            uint32_t af[4][4], bf[2][4];
            const int chunk = ks * 2 + lhi;
            #pragma unroll
            for (int tm = 0; tm < 4; tm++) {
                int row = wm * 64 + tm * 16 + lrow;
                ldsm4(af[tm], ab + (uint32_t)(row * 128 + ((chunk ^ (row & 7)) << 4)));
            }
            #pragma unroll
            for (int t2 = 0; t2 < 2; t2++) {
                int row = wn * 32 + t2 * 16 + lrow;
                ldsm4(bf[t2], bb + (uint32_t)(row * 128 + ((chunk ^ (row & 7)) << 4)));
            }
            #pragma unroll
            for (int tm = 0; tm < 4; tm++)
                #pragma unroll
                for (int tn = 0; tn < 4; tn++)
                    mma_bf16(acc[tm][tn],
                             af[tm][0], af[tm][1], af[tm][2], af[tm][3],
                             bf[tn >> 1][tn & 1], bf[tn >> 1][2 + (tn & 1)]);
        }
    }
}

// stage a 128x128 bf16 row-major matrix into 2 swizzled kblocks
static __device__ __forceinline__ void stage128(
    uint32_t dst, const __nv_bfloat16* src, int tid)
{
    #pragma unroll
    for (int it = 0; it < 8; it++) {
        int idx = tid + (it << 8);
        int r = idx >> 4, q = idx & 15;
        int kblk = q >> 3, qi = q & 7;
        uint32_t off = (uint32_t)((r << 7) | (qi << 4));
        off ^= (off >> 3) & 0x70;
        cpa16(dst + (uint32_t)kblk * 16384u + off, src + (size_t)r * 128 + q * 8);
    }
}

// in-kernel LayerNorm of one 128-row tile into swizzled A smem (warp per row)
// gather=1: shifted window-partition gather from x image layout
static __device__ __forceinline__ void ln_tile(
    uint32_t A_B, const float* __restrict__ xin,
    const float* __restrict__ gam, const float* __restrict__ bet,
    int m0, int wid, int lane, int gather)
{
    float4 g4 = *(const float4*)(gam + lane * 4);
    float4 b4 = *(const float4*)(bet + lane * 4);
    const uint32_t kblk = (lane >= 16) ? 16384u : 0u;
    uint32_t boff0 = (uint32_t)((lane * 4 & 63) * 2);
    #pragma unroll 4
    for (int it = 0; it < 16; it++) {
        const int row = it * 8 + wid;
        const int t = m0 + row;
        size_t src;
        if (gather) {
            int w = t >> 6, n = t & 63;
            int b = w >> 8, wrem = w & 255;
            int wi = wrem >> 4, wj = wrem & 15;
            int y  = (wi * 8 + (n >> 3) + 4) & 127;
            int xc = (wj * 8 + (n & 7) + 4) & 127;
            src = ((size_t)b << 14) + (size_t)y * 128 + xc;
        } else {
            src = (size_t)t;
        }
        float4 v = *(const float4*)(xin + src * 128 + lane * 4);
        float s  = v.x + v.y + v.z + v.w;
        float sq = v.x * v.x + v.y * v.y + v.z * v.z + v.w * v.w;
        #pragma unroll
        for (int o = 16; o; o >>= 1) {
            s  += __shfl_xor_sync(0xffffffffu, s,  o);
            sq += __shfl_xor_sync(0xffffffffu, sq, o);
        }
        float mean = s * (1.f / 128.f);
        float rstd = rsqrtf(sq * (1.f / 128.f) - mean * mean + 1e-5f);
        uint32_t u0 = packbf((v.x - mean) * rstd * g4.x + b4.x,
                             (v.y - mean) * rstd * g4.y + b4.y);
        uint32_t u1 = packbf((v.z - mean) * rstd * g4.z + b4.z,
                             (v.w - mean) * rstd * g4.w + b4.w);
        uint32_t boff = (uint32_t)(row << 7) + boff0;
        boff ^= (boff >> 3) & 0x70;
        asm volatile("st.shared.v2.b32 [%0], {%1, %2};"
                     :: "r"(A_B + kblk + boff), "r"(u0), "r"(u1) : "memory");
    }
}

// ---------------- fused block: LN1 + QKV GEMM + attention + proj + residual ---
// CTA = 128 tokens = 2 windows. smem:
//  A_B   [0, 32768)        : LN1 A-tile, later reused as attn-output (proj A)
//  Q_B   [32768, 155648)   : 12 slices (mat*4+h) x 128 rows x 80B
//  W_B   [155648, 221184)  : 2 x 32KB weight double-buffer
//  RPB   [221184, 224784)  : 900 floats
//  RGT   [224784, 225296)  : 128 ints
#define FSMEM 225296
__device__ __forceinline__ int reg3(int y) { return y < 120 ? 0 : (y < 124 ? 1 : 2); }

__global__ __launch_bounds__(256) void block_fused(
    const float* __restrict__ x, const float* __restrict__ n1g,
    const float* __restrict__ n1b, const unsigned short* __restrict__ wqu,
    const float* __restrict__ qkv_b, const unsigned short* __restrict__ wpu,
    const float* __restrict__ proj_b, const float* __restrict__ rpb,
    float* __restrict__ x1)
{
    extern __shared__ char dsm[];
    const __nv_bfloat16* wq  = (const __nv_bfloat16*)wqu;
    const __nv_bfloat16* wp  = (const __nv_bfloat16*)wpu;
    const uint32_t s0 = smem_u32(dsm);
    const uint32_t A_B = s0;
    const uint32_t Q_B = s0 + 32768u;
    const uint32_t W_B = s0 + 155648u;
    float* rpbs = (float*)(dsm + 221184);
    int*   rgt  = (int*)(dsm + 224784);
    const int tid = threadIdx.x, lane = tid & 31, wid = tid >> 5;
    const int wm = wid >> 2, wn = wid & 3;
    const int m0 = blockIdx.x * 128;
    const int lrow = (lane & 7) + ((lane >> 3) & 1) * 8;
    const int lhi  = lane >> 4;

    // async-prefetch W chunk 0 first, then do LN1 (overlaps)
    stage128(W_B, wq, tid);
    asm volatile("cp.async.commit_group;" ::: "memory");

    ln_tile(A_B, x, n1g, n1b, m0, wid, lane, 1);

    for (int i = tid; i < 900; i += 256) rpbs[i] = rpb[i];
    if (tid < 128) {
        int lw = tid >> 6, n = tid & 63;
        int w = (m0 >> 6) + lw, wrem = w & 255;
        int wi = wrem >> 4, wj = wrem & 15;
        rgt[tid] = 3 * reg3(wi * 8 + (n >> 3)) + reg3(wj * 8 + (n & 7));
    }

    // ---- phase 1: QKV GEMM, 3 chunks of N=128 (chunk c == matrix c, wn == head)
    for (int c = 0; c < 3; c++) {
        if (c < 2) {
            stage128(W_B + (uint32_t)((c + 1) & 1) * 32768u, wq + (size_t)(c + 1) * 128 * 128, tid);
            asm volatile("cp.async.commit_group;" ::: "memory");
            asm volatile("cp.async.wait_group 1;" ::: "memory");
        } else {
            asm volatile("cp.async.wait_group 0;" ::: "memory");
        }
        __syncthreads();

        float acc[4][4][4];
        #pragma unroll
        for (int a = 0; a < 4; a++)
            #pragma unroll
            for (int b = 0; b < 4; b++)
                #pragma unroll
                for (int q = 0; q < 4; q++) acc[a][b][q] = 0.f;
        gemm128(A_B, W_B + (uint32_t)(c & 1) * 32768u, acc, wm, wn, lrow, lhi);

        float2 bs[4];
        #pragma unroll
        for (int tn = 0; tn < 4; tn++)
            bs[tn] = *(const float2*)(qkv_b + c * 128 + wn * 32 + tn * 8 + (lane & 3) * 2);
        const uint32_t slice = Q_B + (uint32_t)(c * 4 + wn) * 10240u;
        #pragma unroll
        for (int tm = 0; tm < 4; tm++) {
            #pragma unroll
            for (int h8 = 0; h8 < 2; h8++) {
                const int row = wm * 64 + tm * 16 + (lane >> 2) + h8 * 8;
                #pragma unroll
                for (int tn = 0; tn < 4; tn++) {
                    const int c32 = tn * 8 + (lane & 3) * 2;
                    float v0 = acc[tm][tn][h8 * 2 + 0] + bs[tn].x;
                    float v1 = acc[tm][tn][h8 * 2 + 1] + bs[tn].y;
                    asm volatile("st.shared.b32 [%0], %1;"
                                 :: "r"(slice + (uint32_t)(row * 80 + c32 * 2)),
                                    "r"(packbf(v0, v1)) : "memory");
                }
            }
        }
        __syncthreads();
    }

    // prefetch proj weights into W buf1
    stage128(W_B + 32768u, wp, tid);
    asm volatile("cp.async.commit_group;" ::: "memory");

    // ---- phase 2: attention. warps [0..3] -> window 0, [4..7] -> window 1.
    {
        const int lw = wid >> 2, wm4 = wid & 3;
        const int lr8 = lrow;
        const uint32_t lh16 = (uint32_t)lhi * 16u;
        const uint32_t rowbase = (uint32_t)(lw * 64) * 80u;
        const int r0 = wm4 * 16 + (lane >> 2), r1 = r0 + 8;
        const int rg0 = rgt[lw * 64 + r0], rg1 = rgt[lw * 64 + r1];
        const int i1a = r0 >> 3, j1a = r0 & 7, i1b = r1 >> 3, j1b = r1 & 7;
        const float scale = 0.17677669529663689f;

        #pragma unroll 1
        for (int h = 0; h < 4; h++) {
            const uint32_t qsl = Q_B + (uint32_t)(0 + h) * 10240u + rowbase;
            const uint32_t ksl = Q_B + (uint32_t)(4 + h) * 10240u + rowbase;
            const uint32_t vsl = Q_B + (uint32_t)(8 + h) * 10240u + rowbase;

            uint32_t qa[2][4];
            {
                uint32_t addr = qsl + (uint32_t)((wm4 * 16 + lr8) * 80) + lh16;
                ldsm4(qa[0], addr);
                ldsm4(qa[1], addr + 32);
            }
            uint32_t kf[4][2][4];
            #pragma unroll
            for (int nt = 0; nt < 4; nt++) {
                uint32_t addr = ksl + (uint32_t)((nt * 16 + lr8) * 80) + lh16;
                ldsm4(kf[nt][0], addr);
                ldsm4(kf[nt][1], addr + 32);
            }

            float sc[8][4];
            #pragma unroll
            for (int i = 0; i < 8; i++)
                #pragma unroll
                for (int q = 0; q < 4; q++) sc[i][q] = 0.f;
            #pragma unroll
            for (int nt8 = 0; nt8 < 8; nt8++) {
                const int nt = nt8 >> 1, ii = nt8 & 1;
                mma_bf16(sc[nt8], qa[0][0], qa[0][1], qa[0][2], qa[0][3],
                         kf[nt][0][ii], kf[nt][0][2 + ii]);
                mma_bf16(sc[nt8], qa[1][0], qa[1][1], qa[1][2], qa[1][3],
                         kf[nt][1][ii], kf[nt][1][2 + ii]);
            }

            #pragma unroll
            for (int nt8 = 0; nt8 < 8; nt8++) {
                #pragma unroll
                for (int q = 0; q < 4; q++) {
                    const int col = nt8 * 8 + (lane & 3) * 2 + (q & 1);
                    const int i2 = col >> 3, j2 = col & 7;
                    const int rgc = rgt[lw * 64 + col];
                    float v = sc[nt8][q] * scale;
                    if (q < 2) {
                        v += rpbs[((i1a - i2 + 7) * 15 + (j1a - j2 + 7)) * 4 + h];
                        if (rgc != rg0) v -= 100.f;
                    } else {
                        v += rpbs[((i1b - i2 + 7) * 15 + (j1b - j2 + 7)) * 4 + h];
                        if (rgc != rg1) v -= 100.f;
                    }
                    sc[nt8][q] = v;
                }
            }

            float mx0 = -1e30f, mx1 = -1e30f;
            #pragma unroll
            for (int nt8 = 0; nt8 < 8; nt8++) {
                mx0 = fmaxf(mx0, fmaxf(sc[nt8][0], sc[nt8][1]));
                mx1 = fmaxf(mx1, fmaxf(sc[nt8][2], sc[nt8][3]));
            }
            #pragma unroll
            for (int o = 1; o <= 2; o <<= 1) {
                mx0 = fmaxf(mx0, __shfl_xor_sync(0xffffffffu, mx0, o));
                mx1 = fmaxf(mx1, __shfl_xor_sync(0xffffffffu, mx1, o));
            }
            float sm0 = 0.f, sm1 = 0.f;
            #pragma unroll
            for (int nt8 = 0; nt8 < 8; nt8++) {
                sc[nt8][0] = __expf(sc[nt8][0] - mx0);
                sc[nt8][1] = __expf(sc[nt8][1] - mx0);
                sc[nt8][2] = __expf(sc[nt8][2] - mx1);
                sc[nt8][3] = __expf(sc[nt8][3] - mx1);
                sm0 += sc[nt8][0] + sc[nt8][1];
                sm1 += sc[nt8][2] + sc[nt8][3];
            }
            #pragma unroll
            for (int o = 1; o <= 2; o <<= 1) {
                sm0 += __shfl_xor_sync(0xffffffffu, sm0, o);
                sm1 += __shfl_xor_sync(0xffffffffu, sm1, o);
            }
            const float inv0 = 1.f / sm0, inv1 = 1.f / sm1;

            float oc[4][4];
            #pragma unroll
            for (int nt = 0; nt < 4; nt++)
                #pragma unroll
                for (int q = 0; q < 4; q++) oc[nt][q] = 0.f;
            #pragma unroll
            for (int kc = 0; kc < 4; kc++) {
                const uint32_t a0 = packbf(sc[2 * kc][0],     sc[2 * kc][1]);
                const uint32_t a1 = packbf(sc[2 * kc][2],     sc[2 * kc][3]);
                const uint32_t a2 = packbf(sc[2 * kc + 1][0], sc[2 * kc + 1][1]);
                const uint32_t a3 = packbf(sc[2 * kc + 1][2], sc[2 * kc + 1][3]);
                uint32_t vf0[4], vf1[4];
                const uint32_t vaddr = vsl + (uint32_t)((kc * 16 + lr8) * 80) + lh16;
                ldsm4t(vf0, vaddr);
                ldsm4t(vf1, vaddr + 32);
                mma_bf16(oc[0], a0, a1, a2, a3, vf0[0], vf0[1]);
                mma_bf16(oc[1], a0, a1, a2, a3, vf0[2], vf0[3]);
                mma_bf16(oc[2], a0, a1, a2, a3, vf1[0], vf1[1]);
                mma_bf16(oc[3], a0, a1, a2, a3, vf1[2], vf1[3]);
            }

            #pragma unroll
            for (int nt = 0; nt < 4; nt++) {
                const int ch = h * 32 + nt * 8 + (lane & 3) * 2;
                const uint32_t kblk = (uint32_t)(ch >> 6) * 16384u;
                uint32_t b0 = (uint32_t)(((lw * 64 + r0) << 7) + ((ch & 63) << 1));
                uint32_t b1 = (uint32_t)(((lw * 64 + r1) << 7) + ((ch & 63) << 1));
                b0 ^= (b0 >> 3) & 0x70;
                b1 ^= (b1 >> 3) & 0x70;
                asm volatile("st.shared.b32 [%0], %1;" ::
                    "r"(A_B + kblk + b0), "r"(packbf(oc[nt][0] * inv0, oc[nt][1] * inv0)) : "memory");
                asm volatile("st.shared.b32 [%0], %1;" ::
                    "r"(A_B + kblk + b1), "r"(packbf(oc[nt][2] * inv1, oc[nt][3] * inv1)) : "memory");
            }
        }
    }
    asm volatile("cp.async.wait_group 0;" ::: "memory");
    __syncthreads();

    // ---- phase 3: proj GEMM + scatter + residual ----
    {
        float acc[4][4][4];
        #pragma unroll
        for (int a = 0; a < 4; a++)
            #pragma unroll
            for (int b = 0; b < 4; b++)
                #pragma unroll
                for (int q = 0; q < 4; q++) acc[a][b][q] = 0.f;
        gemm128(A_B, W_B + 32768u, acc, wm, wn, lrow, lhi);

        float2 bs[4];
        #pragma unroll
        for (int tn = 0; tn < 4; tn++)
            bs[tn] = *(const float2*)(proj_b + wn * 32 + tn * 8 + (lane & 3) * 2);
        #pragma unroll
        for (int tm = 0; tm < 4; tm++) {
            #pragma unroll
            for (int h8 = 0; h8 < 2; h8++) {
                const int m = m0 + wm * 64 + tm * 16 + (lane >> 2) + h8 * 8;
                int w = m >> 6, nt2 = m & 63;
                int b = w >> 8, wrem = w & 255;
                int wwi = wrem >> 4, wwj = wrem & 15;
                int yf = (wwi * 8 + (nt2 >> 3) + 4) & 127;
                int xf = (wwj * 8 + (nt2 & 7) + 4) & 127;
                size_t mo = ((size_t)b << 14) + (size_t)yf * 128 + xf;
                #pragma unroll
                for (int tn = 0; tn < 4; tn++) {
                    const int nn = wn * 32 + tn * 8 + (lane & 3) * 2;
                    float2 r2 = *(const float2*)(x + mo * 128 + nn);
                    float v0 = acc[tm][tn][h8 * 2 + 0] + bs[tn].x + r2.x;
                    float v1 = acc[tm][tn][h8 * 2 + 1] + bs[tn].y + r2.y;
                    *(float2*)(x1 + mo * 128 + nn) = make_float2(v0, v1);
                }
            }
        }
    }
}

// ---------------- fused MLP: out = x1 + fc2(GELU(fc1(LN2(x1)))) ---------------
#define MSMEM 196608
static __device__ __forceinline__ void mlp_stage_w(
    uint32_t wbuf, const __nv_bfloat16* W1, const __nv_bfloat16* W2, int c, int tid)
{
    const int nc0 = c * 128;
    #pragma unroll
    for (int it = 0; it < 8; it++) {
        int idx = tid + (it << 8);
        int r = idx >> 4, q = idx & 15;
        int kblk = q >> 3, qi = q & 7;
        uint32_t off = (uint32_t)((r << 7) | (qi << 4));
        off ^= (off >> 3) & 0x70;
        cpa16(wbuf + (uint32_t)kblk * 16384u + off,            W1 + (size_t)(nc0 + r) * 128 + q * 8);
        cpa16(wbuf + 32768u + (uint32_t)kblk * 16384u + off,   W2 + (size_t)r * 512 + nc0 + q * 8);
    }
    asm volatile("cp.async.commit_group;" ::: "memory");
}

__global__ __launch_bounds__(256) void mlp_fused(
    const float* __restrict__ x1, const float* __restrict__ n2g,
    const float* __restrict__ n2b, const unsigned short* __restrict__ w1u,
    const float* __restrict__ b1, const unsigned short* __restrict__ w2u,
    const float* __restrict__ b2, float* __restrict__ out)
{
    extern __shared__ char dsm[];
    const __nv_bfloat16* W1 = (const __nv_bfloat16*)w1u;
    const __nv_bfloat16* W2 = (const __nv_bfloat16*)w2u;
    const uint32_t s0 = smem_u32(dsm);
    const uint32_t A_B = s0;
    const uint32_t H_B = s0 + 32768u;
    const uint32_t W_B = s0 + 65536u;
    const int tid = threadIdx.x, lane = tid & 31, wid = tid >> 5;
    const int wm = wid >> 2, wn = wid & 3;
    const int m0 = blockIdx.x * 128;
    const int lrow = (lane & 7) + ((lane >> 3) & 1) * 8;
    const int lhi  = lane >> 4;

    mlp_stage_w(W_B, W1, W2, 0, tid);
    ln_tile(A_B, x1, n2g, n2b, m0, wid, lane, 0);

    float acc2[4][4][4];
    #pragma unroll
    for (int a = 0; a < 4; a++)
        #pragma unroll
        for (int b = 0; b < 4; b++)
            #pragma unroll
            for (int c = 0; c < 4; c++) acc2[a][b][c] = 0.f;

    for (int c = 0; c < 4; c++) {
        if (c + 1 < 4) {
            mlp_stage_w(W_B + (uint32_t)((c + 1) & 1) * 65536u, W1, W2, c + 1, tid);
            asm volatile("cp.async.wait_group 1;" ::: "memory");
        } else {
            asm volatile("cp.async.wait_group 0;" ::: "memory");
        }
        __syncthreads();

        const uint32_t wb = W_B + (uint32_t)(c & 1) * 65536u;

        float acc1[4][4][4];
        #pragma unroll
        for (int a = 0; a < 4; a++)
            #pragma unroll
            for (int b = 0; b < 4; b++)
                #pragma unroll
                for (int q = 0; q < 4; q++) acc1[a][b][q] = 0.f;
        gemm128(A_B, wb, acc1, wm, wn, lrow, lhi);

        {
            float2 bs1[4];
            #pragma unroll
            for (int tn = 0; tn < 4; tn++)
                bs1[tn] = *(const float2*)(b1 + c * 128 + wn * 32 + tn * 8 + (lane & 3) * 2);
            #pragma unroll
            for (int tm = 0; tm < 4; tm++) {
                #pragma unroll
                for (int h = 0; h < 2; h++) {
                    const int row = wm * 64 + tm * 16 + (lane >> 2) + h * 8;
                    #pragma unroll
                    for (int tn = 0; tn < 4; tn++) {
                        const int nn = wn * 32 + tn * 8 + (lane & 3) * 2;
                        float v0 = acc1[tm][tn][h * 2 + 0] + bs1[tn].x;
                        float v1 = acc1[tm][tn][h * 2 + 1] + bs1[tn].y;
                        v0 = 0.5f * v0 * (1.f + erff(v0 * 0.70710678118654752f));
                        v1 = 0.5f * v1 * (1.f + erff(v1 * 0.70710678118654752f));
                        uint32_t boff = (uint32_t)((row << 7) + (nn & 63) * 2);
                        boff ^= (boff >> 3) & 0x70;
                        uint32_t dst = H_B + ((nn >= 64) ? 16384u : 0u) + boff;
                        asm volatile("st.shared.b32 [%0], %1;" :: "r"(dst), "r"(packbf(v0, v1)) : "memory");
                    }
                }
            }
        }
        __syncthreads();

        gemm128(H_B, wb + 32768u, acc2, wm, wn, lrow, lhi);
        __syncthreads();
    }

    float2 bs[4];
    #pragma unroll
    for (int tn = 0; tn < 4; tn++)
        bs[tn] = *(const float2*)(b2 + wn * 32 + tn * 8 + (lane & 3) * 2);
    #pragma unroll
    for (int tm = 0; tm < 4; tm++) {
        #pragma unroll
        for (int h = 0; h < 2; h++) {
            const int m = m0 + wm * 64 + tm * 16 + (lane >> 2) + h * 8;
            #pragma unroll
            for (int tn = 0; tn < 4; tn++) {
                const int nn = wn * 32 + tn * 8 + (lane & 3) * 2;
                float2 r2 = *(const float2*)(x1 + (size_t)m * 128 + nn);
                float v0 = acc2[tm][tn][h * 2 + 0] + bs[tn].x + r2.x;
                float v1 = acc2[tm][tn][h * 2 + 1] + bs[tn].y + r2.y;
                *(float2*)(out + (size_t)m * 128 + nn) = make_float2(v0, v1);
            }
        }
    }
}

// ---------------- launch ----------------
extern "C" void kernel_launch(void* const* d_in, const int* in_sizes, int n_in,
                              void* d_out, int out_size)
{
    const float* x      = (const float*)d_in[0];
    const float* rpb    = (const float*)d_in[1];
    const float* n1g    = (const float*)d_in[2];
    const float* n1b    = (const float*)d_in[3];
    const float* qkv_w  = (const float*)d_in[4];
    const float* qkv_b  = (const float*)d_in[5];
    const float* proj_w = (const float*)d_in[6];
    const float* proj_b = (const float*)d_in[7];
    const float* n2g    = (const float*)d_in[8];
    const float* n2b    = (const float*)d_in[9];
    const float* fc1_w  = (const float*)d_in[10];
    const float* fc1_b  = (const float*)d_in[11];
    const float* fc2_w  = (const float*)d_in[12];
    const float* fc2_b  = (const float*)d_in[13];
    float* out = (float*)d_out;

    unsigned short *wq, *wp, *w1, *w2;
    float *x1;
    cudaGetSymbolAddress((void**)&x1,  g_x1);
    cudaGetSymbolAddress((void**)&wq,  g_wq);
    cudaGetSymbolAddress((void**)&wp,  g_wp);
    cudaGetSymbolAddress((void**)&w1,  g_w1);
    cudaGetSymbolAddress((void**)&w2,  g_w2);

    cudaFuncSetAttribute(block_fused, cudaFuncAttributeMaxDynamicSharedMemorySize, FSMEM);
    cudaFuncSetAttribute(mlp_fused,   cudaFuncAttributeMaxDynamicSharedMemorySize, MSMEM);

    const int M = MTOK;

    f2bf_all<<<192, 256>>>(qkv_w, wq, proj_w, wp, fc1_w, w1, fc2_w, w2);

    // 1) LN1 + shift-gather + QKV GEMM + attention + proj + scatter + residual
    block_fused<<<M / 128, 256, FSMEM>>>(x, n1g, n1b, wq, qkv_b, wp, proj_b, rpb, x1);
    // 2) LN2 + fc1 + GELU + fc2 + residual -> final output
    mlp_fused<<<M / 128, 256, MSMEM>>>(x1, n2g, n2b, w1, fc1_b, w2, fc2_b, out);
}

// round 10
// speedup vs baseline: 2.2030x; 1.0567x over previous
#include <cuda_runtime.h>
#include <cuda_bf16.h>
#include <math.h>
#include <stdint.h>

// B=8, H=W=128, C=128, HEADS=4, d=32, WS=8, SHIFT=4, HIDDEN=512
#define MTOK 131072

// ---------------- scratch (device globals; no allocs allowed) ----------------
static __device__ float          g_x1 [(size_t)MTOK * 128];  // fp32 residual 1
static __device__ unsigned short g_wq[384 * 128];
static __device__ unsigned short g_wp[128 * 128];
static __device__ unsigned short g_w1[512 * 128];
static __device__ unsigned short g_w2[128 * 512];

// ---------------- PTX helpers (sm_80+ features only) ----------------
static __device__ __forceinline__ uint32_t smem_u32(const void* p) {
    uint32_t a;
    asm("{ .reg .u64 t; cvta.to.shared.u64 t, %1; cvt.u32.u64 %0, t; }" : "=r"(a) : "l"(p));
    return a;
}
static __device__ __forceinline__ void cpa16(uint32_t s, const void* g) {
    asm volatile("cp.async.cg.shared.global [%0], [%1], 16;" :: "r"(s), "l"(g) : "memory");
}
static __device__ __forceinline__ void ldsm4(uint32_t* r, uint32_t addr) {
    asm volatile("ldmatrix.sync.aligned.m8n8.x4.shared.b16 {%0,%1,%2,%3}, [%4];"
                 : "=r"(r[0]), "=r"(r[1]), "=r"(r[2]), "=r"(r[3]) : "r"(addr));
}
static __device__ __forceinline__ void ldsm4t(uint32_t* r, uint32_t addr) {
    asm volatile("ldmatrix.sync.aligned.m8n8.x4.trans.shared.b16 {%0,%1,%2,%3}, [%4];"
                 : "=r"(r[0]), "=r"(r[1]), "=r"(r[2]), "=r"(r[3]) : "r"(addr));
}
static __device__ __forceinline__ void mma_bf16(float* c,
    uint32_t a0, uint32_t a1, uint32_t a2, uint32_t a3, uint32_t b0, uint32_t b1) {
    asm volatile(
        "mma.sync.aligned.m16n8k16.row.col.f32.bf16.bf16.f32 "
        "{%0,%1,%2,%3}, {%4,%5,%6,%7}, {%8,%9}, {%0,%1,%2,%3};"
        : "+f"(c[0]), "+f"(c[1]), "+f"(c[2]), "+f"(c[3])
        : "r"(a0), "r"(a1), "r"(a2), "r"(a3), "r"(b0), "r"(b1));
}
static __device__ __forceinline__ uint32_t packbf(float a, float b) {
    __nv_bfloat162 p = __floats2bfloat162_rn(a, b);
    return *reinterpret_cast<uint32_t*>(&p);
}

// ---------------- merged fp32 -> bf16 weight conversion ----------------
__global__ __launch_bounds__(256) void f2bf_all(
    const float* __restrict__ s0, unsigned short* __restrict__ d0,
    const float* __restrict__ s1, unsigned short* __restrict__ d1,
    const float* __restrict__ s2, unsigned short* __restrict__ d2,
    const float* __restrict__ s3, unsigned short* __restrict__ d3)
{
    int i = blockIdx.x * 256 + threadIdx.x;
    const float* s; unsigned short* d; int o;
    if (i < 12288)      { s = s0; d = d0; o = i; }
    else if (i < 16384) { s = s1; d = d1; o = i - 12288; }
    else if (i < 32768) { s = s2; d = d2; o = i - 16384; }
    else                { s = s3; d = d3; o = i - 32768; }
    float4 v = ((const float4*)s)[o];
    uint2 u;
    u.x = packbf(v.x, v.y);
    u.y = packbf(v.z, v.w);
    ((uint2*)d)[o] = u;
}

// ------------- 16-warp GEMM core: C128x128 += A(2 kblk) @ B(2 kblk)^T ---------
// warp (wm 0-3, wn 0-3): rows wm*32+tm*16, cols wn*32+tn*8
static __device__ __forceinline__ void gemm128(
    uint32_t abase, uint32_t bbase, float acc[2][4][4],
    int wm, int wn, int lrow, int lhi)
{
    #pragma unroll
    for (int kb = 0; kb < 2; kb++) {
        const uint32_t ab = abase + (uint32_t)kb * 16384u;
        const uint32_t bb = bbase + (uint32_t)kb * 16384u;
        #pragma unroll
        for (int ks = 0; ks < 4; ks++) {
            uint32_t af[2][4], bf[2][4];
            const int chunk = ks * 2 + lhi;
            #pragma unroll
            for (int tm = 0; tm < 2; tm++) {
                int row = wm * 32 + tm * 16 + lrow;
                ldsm4(af[tm], ab + (uint32_t)(row * 128 + ((chunk ^ (row & 7)) << 4)));
            }
            #pragma unroll
            for (int t2 = 0; t2 < 2; t2++) {
                int row = wn * 32 + t2 * 16 + lrow;
                ldsm4(bf[t2], bb + (uint32_t)(row * 128 + ((chunk ^ (row & 7)) << 4)));
            }
            #pragma unroll
            for (int tm = 0; tm < 2; tm++)
                #pragma unroll
                for (int tn = 0; tn < 4; tn++)
                    mma_bf16(acc[tm][tn],
                             af[tm][0], af[tm][1], af[tm][2], af[tm][3],
                             bf[tn >> 1][tn & 1], bf[tn >> 1][2 + (tn & 1)]);
        }
    }
}

// stage a 128x128 bf16 row-major matrix into 2 swizzled kblocks (512 threads)
static __device__ __forceinline__ void stage128(
    uint32_t dst, const __nv_bfloat16* src, int tid)
{
    #pragma unroll
    for (int it = 0; it < 4; it++) {
        int idx = tid + (it << 9);
        int r = idx >> 4, q = idx & 15;
        int kblk = q >> 3, qi = q & 7;
        uint32_t off = (uint32_t)((r << 7) | (qi << 4));
        off ^= (off >> 3) & 0x70;
        cpa16(dst + (uint32_t)kblk * 16384u + off, src + (size_t)r * 128 + q * 8);
    }
}

// in-kernel LayerNorm of one 128-row tile into swizzled A smem (16 warps)
static __device__ __forceinline__ void ln_tile(
    uint32_t A_B, const float* __restrict__ xin,
    const float* __restrict__ gam, const float* __restrict__ bet,
    int m0, int wid, int lane, int gather)
{
    float4 g4 = *(const float4*)(gam + lane * 4);
    float4 b4 = *(const float4*)(bet + lane * 4);
    const uint32_t kblk = (lane >= 16) ? 16384u : 0u;
    uint32_t boff0 = (uint32_t)((lane * 4 & 63) * 2);
    #pragma unroll 4
    for (int it = 0; it < 8; it++) {
        const int row = it * 16 + wid;
        const int t = m0 + row;
        size_t src;
        if (gather) {
            int w = t >> 6, n = t & 63;
            int b = w >> 8, wrem = w & 255;
            int wi = wrem >> 4, wj = wrem & 15;
            int y  = (wi * 8 + (n >> 3) + 4) & 127;
            int xc = (wj * 8 + (n & 7) + 4) & 127;
            src = ((size_t)b << 14) + (size_t)y * 128 + xc;
        } else {
            src = (size_t)t;
        }
        float4 v = *(const float4*)(xin + src * 128 + lane * 4);
        float s  = v.x + v.y + v.z + v.w;
        float sq = v.x * v.x + v.y * v.y + v.z * v.z + v.w * v.w;
        #pragma unroll
        for (int o = 16; o; o >>= 1) {
            s  += __shfl_xor_sync(0xffffffffu, s,  o);
            sq += __shfl_xor_sync(0xffffffffu, sq, o);
        }
        float mean = s * (1.f / 128.f);
        float rstd = rsqrtf(sq * (1.f / 128.f) - mean * mean + 1e-5f);
        uint32_t u0 = packbf((v.x - mean) * rstd * g4.x + b4.x,
                             (v.y - mean) * rstd * g4.y + b4.y);
        uint32_t u1 = packbf((v.z - mean) * rstd * g4.z + b4.z,
                             (v.w - mean) * rstd * g4.w + b4.w);
        uint32_t boff = (uint32_t)(row << 7) + boff0;
        boff ^= (boff >> 3) & 0x70;
        asm volatile("st.shared.v2.b32 [%0], {%1, %2};"
                     :: "r"(A_B + kblk + boff), "r"(u0), "r"(u1) : "memory");
    }
}

// ---------------- fused block: LN1 + QKV GEMM + attention + proj + residual ---
// CTA = 128 tokens = 2 windows, 512 threads (16 warps).
#define FSMEM 225296
__device__ __forceinline__ int reg3(int y) { return y < 120 ? 0 : (y < 124 ? 1 : 2); }

__global__ __launch_bounds__(512) void block_fused(
    const float* __restrict__ x, const float* __restrict__ n1g,
    const float* __restrict__ n1b, const unsigned short* __restrict__ wqu,
    const float* __restrict__ qkv_b, const unsigned short* __restrict__ wpu,
    const float* __restrict__ proj_b, const float* __restrict__ rpb,
    float* __restrict__ x1)
{
    extern __shared__ char dsm[];
    const __nv_bfloat16* wq  = (const __nv_bfloat16*)wqu;
    const __nv_bfloat16* wp  = (const __nv_bfloat16*)wpu;
    const uint32_t s0 = smem_u32(dsm);
    const uint32_t A_B = s0;
    const uint32_t Q_B = s0 + 32768u;
    const uint32_t W_B = s0 + 155648u;
    float* rpbs = (float*)(dsm + 221184);
    int*   rgt  = (int*)(dsm + 224784);
    const int tid = threadIdx.x, lane = tid & 31, wid = tid >> 5;
    const int wm = wid >> 2, wn = wid & 3;
    const int m0 = blockIdx.x * 128;
    const int lrow = (lane & 7) + ((lane >> 3) & 1) * 8;
    const int lhi  = lane >> 4;

    stage128(W_B, wq, tid);
    asm volatile("cp.async.commit_group;" ::: "memory");

    ln_tile(A_B, x, n1g, n1b, m0, wid, lane, 1);

    for (int i = tid; i < 900; i += 512) rpbs[i] = rpb[i];
    if (tid < 128) {
        int lw = tid >> 6, n = tid & 63;
        int w = (m0 >> 6) + lw, wrem = w & 255;
        int wi = wrem >> 4, wj = wrem & 15;
        rgt[tid] = 3 * reg3(wi * 8 + (n >> 3)) + reg3(wj * 8 + (n & 7));
    }

    // ---- phase 1: QKV GEMM, 3 chunks of N=128 (chunk c == matrix c, wn == head)
    for (int c = 0; c < 3; c++) {
        if (c < 2) {
            stage128(W_B + (uint32_t)((c + 1) & 1) * 32768u, wq + (size_t)(c + 1) * 128 * 128, tid);
            asm volatile("cp.async.commit_group;" ::: "memory");
            asm volatile("cp.async.wait_group 1;" ::: "memory");
        } else {
            asm volatile("cp.async.wait_group 0;" ::: "memory");
        }
        __syncthreads();

        float acc[2][4][4];
        #pragma unroll
        for (int a = 0; a < 2; a++)
            #pragma unroll
            for (int b = 0; b < 4; b++)
                #pragma unroll
                for (int q = 0; q < 4; q++) acc[a][b][q] = 0.f;
        gemm128(A_B, W_B + (uint32_t)(c & 1) * 32768u, acc, wm, wn, lrow, lhi);

        float2 bs[4];
        #pragma unroll
        for (int tn = 0; tn < 4; tn++)
            bs[tn] = *(const float2*)(qkv_b + c * 128 + wn * 32 + tn * 8 + (lane & 3) * 2);
        const uint32_t slice = Q_B + (uint32_t)(c * 4 + wn) * 10240u;
        #pragma unroll
        for (int tm = 0; tm < 2; tm++) {
            #pragma unroll
            for (int h8 = 0; h8 < 2; h8++) {
                const int row = wm * 32 + tm * 16 + (lane >> 2) + h8 * 8;
                #pragma unroll
                for (int tn = 0; tn < 4; tn++) {
                    const int c32 = tn * 8 + (lane & 3) * 2;
                    float v0 = acc[tm][tn][h8 * 2 + 0] + bs[tn].x;
                    float v1 = acc[tm][tn][h8 * 2 + 1] + bs[tn].y;
                    asm volatile("st.shared.b32 [%0], %1;"
                                 :: "r"(slice + (uint32_t)(row * 80 + c32 * 2)),
                                    "r"(packbf(v0, v1)) : "memory");
                }
            }
        }
        __syncthreads();
    }

    // prefetch proj weights into W buf1
    stage128(W_B + 32768u, wp, tid);
    asm volatile("cp.async.commit_group;" ::: "memory");

    // ---- phase 2: attention. 16 warps: (window, head-pair, row-quarter)
    {
        const int lw  = wid >> 3;          // window 0/1
        const int hp  = (wid >> 2) & 1;    // head pair
        const int wm4 = wid & 3;           // row quarter
        const int lr8 = lrow;
        const uint32_t lh16 = (uint32_t)lhi * 16u;
        const uint32_t rowbase = (uint32_t)(lw * 64) * 80u;
        const int r0 = wm4 * 16 + (lane >> 2), r1 = r0 + 8;
        const int rg0 = rgt[lw * 64 + r0], rg1 = rgt[lw * 64 + r1];
        const int i1a = r0 >> 3, j1a = r0 & 7, i1b = r1 >> 3, j1b = r1 & 7;
        const float scale = 0.17677669529663689f;

        #pragma unroll 1
        for (int hh = 0; hh < 2; hh++) {
            const int h = hp * 2 + hh;
            const uint32_t qsl = Q_B + (uint32_t)(0 + h) * 10240u + rowbase;
            const uint32_t ksl = Q_B + (uint32_t)(4 + h) * 10240u + rowbase;
            const uint32_t vsl = Q_B + (uint32_t)(8 + h) * 10240u + rowbase;

            uint32_t qa[2][4];
            {
                uint32_t addr = qsl + (uint32_t)((wm4 * 16 + lr8) * 80) + lh16;
                ldsm4(qa[0], addr);
                ldsm4(qa[1], addr + 32);
            }
            uint32_t kf[4][2][4];
            #pragma unroll
            for (int nt = 0; nt < 4; nt++) {
                uint32_t addr = ksl + (uint32_t)((nt * 16 + lr8) * 80) + lh16;
                ldsm4(kf[nt][0], addr);
                ldsm4(kf[nt][1], addr + 32);
            }

            float sc[8][4];
            #pragma unroll
            for (int i = 0; i < 8; i++)
                #pragma unroll
                for (int q = 0; q < 4; q++) sc[i][q] = 0.f;
            #pragma unroll
            for (int nt8 = 0; nt8 < 8; nt8++) {
                const int nt = nt8 >> 1, ii = nt8 & 1;
                mma_bf16(sc[nt8], qa[0][0], qa[0][1], qa[0][2], qa[0][3],
                         kf[nt][0][ii], kf[nt][0][2 + ii]);
                mma_bf16(sc[nt8], qa[1][0], qa[1][1], qa[1][2], qa[1][3],
                         kf[nt][1][ii], kf[nt][1][2 + ii]);
            }

            #pragma unroll
            for (int nt8 = 0; nt8 < 8; nt8++) {
                #pragma unroll
                for (int q = 0; q < 4; q++) {
                    const int col = nt8 * 8 + (lane & 3) * 2 + (q & 1);
                    const int i2 = col >> 3, j2 = col & 7;
                    const int rgc = rgt[lw * 64 + col];
                    float v = sc[nt8][q] * scale;
                    if (q < 2) {
                        v += rpbs[((i1a - i2 + 7) * 15 + (j1a - j2 + 7)) * 4 + h];
                        if (rgc != rg0) v -= 100.f;
                    } else {
                        v += rpbs[((i1b - i2 + 7) * 15 + (j1b - j2 + 7)) * 4 + h];
                        if (rgc != rg1) v -= 100.f;
                    }
                    sc[nt8][q] = v;
                }
            }

            float mx0 = -1e30f, mx1 = -1e30f;
            #pragma unroll
            for (int nt8 = 0; nt8 < 8; nt8++) {
                mx0 = fmaxf(mx0, fmaxf(sc[nt8][0], sc[nt8][1]));
                mx1 = fmaxf(mx1, fmaxf(sc[nt8][2], sc[nt8][3]));
            }
            #pragma unroll
            for (int o = 1; o <= 2; o <<= 1) {
                mx0 = fmaxf(mx0, __shfl_xor_sync(0xffffffffu, mx0, o));
                mx1 = fmaxf(mx1, __shfl_xor_sync(0xffffffffu, mx1, o));
            }
            float sm0 = 0.f, sm1 = 0.f;
            #pragma unroll
            for (int nt8 = 0; nt8 < 8; nt8++) {
                sc[nt8][0] = __expf(sc[nt8][0] - mx0);
                sc[nt8][1] = __expf(sc[nt8][1] - mx0);
                sc[nt8][2] = __expf(sc[nt8][2] - mx1);
                sc[nt8][3] = __expf(sc[nt8][3] - mx1);
                sm0 += sc[nt8][0] + sc[nt8][1];
                sm1 += sc[nt8][2] + sc[nt8][3];
            }
            #pragma unroll
            for (int o = 1; o <= 2; o <<= 1) {
                sm0 += __shfl_xor_sync(0xffffffffu, sm0, o);
                sm1 += __shfl_xor_sync(0xffffffffu, sm1, o);
            }
            const float inv0 = 1.f / sm0, inv1 = 1.f / sm1;

            float oc[4][4];
            #pragma unroll
            for (int nt = 0; nt < 4; nt++)
                #pragma unroll
                for (int q = 0; q < 4; q++) oc[nt][q] = 0.f;
            #pragma unroll
            for (int kc = 0; kc < 4; kc++) {
                const uint32_t a0 = packbf(sc[2 * kc][0],     sc[2 * kc][1]);
                const uint32_t a1 = packbf(sc[2 * kc][2],     sc[2 * kc][3]);
                const uint32_t a2 = packbf(sc[2 * kc + 1][0], sc[2 * kc + 1][1]);
                const uint32_t a3 = packbf(sc[2 * kc + 1][2], sc[2 * kc + 1][3]);
                uint32_t vf0[4], vf1[4];
                const uint32_t vaddr = vsl + (uint32_t)((kc * 16 + lr8) * 80) + lh16;
                ldsm4t(vf0, vaddr);
                ldsm4t(vf1, vaddr + 32);
                mma_bf16(oc[0], a0, a1, a2, a3, vf0[0], vf0[1]);
                mma_bf16(oc[1], a0, a1, a2, a3, vf0[2], vf0[3]);
                mma_bf16(oc[2], a0, a1, a2, a3, vf1[0], vf1[1]);
                mma_bf16(oc[3], a0, a1, a2, a3, vf1[2], vf1[3]);
            }

            #pragma unroll
            for (int nt = 0; nt < 4; nt++) {
                const int ch = h * 32 + nt * 8 + (lane & 3) * 2;
                const uint32_t kblk = (uint32_t)(ch >> 6) * 16384u;
                uint32_t b0 = (uint32_t)(((lw * 64 + r0) << 7) + ((ch & 63) << 1));
                uint32_t b1 = (uint32_t)(((lw * 64 + r1) << 7) + ((ch & 63) << 1));
                b0 ^= (b0 >> 3) & 0x70;
                b1 ^= (b1 >> 3) & 0x70;
                asm volatile("st.shared.b32 [%0], %1;" ::
                    "r"(A_B + kblk + b0), "r"(packbf(oc[nt][0] * inv0, oc[nt][1] * inv0)) : "memory");
                asm volatile("st.shared.b32 [%0], %1;" ::
                    "r"(A_B + kblk + b1), "r"(packbf(oc[nt][2] * inv1, oc[nt][3] * inv1)) : "memory");
            }
        }
    }
    asm volatile("cp.async.wait_group 0;" ::: "memory");
    __syncthreads();

    // ---- phase 3: proj GEMM + scatter + residual ----
    {
        float acc[2][4][4];
        #pragma unroll
        for (int a = 0; a < 2; a++)
            #pragma unroll
            for (int b = 0; b < 4; b++)
                #pragma unroll
                for (int q = 0; q < 4; q++) acc[a][b][q] = 0.f;
        gemm128(A_B, W_B + 32768u, acc, wm, wn, lrow, lhi);

        float2 bs[4];
        #pragma unroll
        for (int tn = 0; tn < 4; tn++)
            bs[tn] = *(const float2*)(proj_b + wn * 32 + tn * 8 + (lane & 3) * 2);
        #pragma unroll
        for (int tm = 0; tm < 2; tm++) {
            #pragma unroll
            for (int h8 = 0; h8 < 2; h8++) {
                const int m = m0 + wm * 32 + tm * 16 + (lane >> 2) + h8 * 8;
                int w = m >> 6, nt2 = m & 63;
                int b = w >> 8, wrem = w & 255;
                int wwi = wrem >> 4, wwj = wrem & 15;
                int yf = (wwi * 8 + (nt2 >> 3) + 4) & 127;
                int xf = (wwj * 8 + (nt2 & 7) + 4) & 127;
                size_t mo = ((size_t)b << 14) + (size_t)yf * 128 + xf;
                #pragma unroll
                for (int tn = 0; tn < 4; tn++) {
                    const int nn = wn * 32 + tn * 8 + (lane & 3) * 2;
                    float2 r2 = *(const float2*)(x + mo * 128 + nn);
                    float v0 = acc[tm][tn][h8 * 2 + 0] + bs[tn].x + r2.x;
                    float v1 = acc[tm][tn][h8 * 2 + 1] + bs[tn].y + r2.y;
                    *(float2*)(x1 + mo * 128 + nn) = make_float2(v0, v1);
                }
            }
        }
    }
}

// ---------------- fused MLP: out = x1 + fc2(GELU(fc1(LN2(x1)))) ---------------
#define MSMEM 196608
static __device__ __forceinline__ void mlp_stage_w(
    uint32_t wbuf, const __nv_bfloat16* W1, const __nv_bfloat16* W2, int c, int tid)
{
    const int nc0 = c * 128;
    #pragma unroll
    for (int it = 0; it < 4; it++) {
        int idx = tid + (it << 9);
        int r = idx >> 4, q = idx & 15;
        int kblk = q >> 3, qi = q & 7;
        uint32_t off = (uint32_t)((r << 7) | (qi << 4));
        off ^= (off >> 3) & 0x70;
        cpa16(wbuf + (uint32_t)kblk * 16384u + off,            W1 + (size_t)(nc0 + r) * 128 + q * 8);
        cpa16(wbuf + 32768u + (uint32_t)kblk * 16384u + off,   W2 + (size_t)r * 512 + nc0 + q * 8);
    }
    asm volatile("cp.async.commit_group;" ::: "memory");
}

__global__ __launch_bounds__(512) void mlp_fused(
    const float* __restrict__ x1, const float* __restrict__ n2g,
    const float* __restrict__ n2b, const unsigned short* __restrict__ w1u,
    const float* __restrict__ b1, const unsigned short* __restrict__ w2u,
    const float* __restrict__ b2, float* __restrict__ out)
{
    extern __shared__ char dsm[];
    const __nv_bfloat16* W1 = (const __nv_bfloat16*)w1u;
    const __nv_bfloat16* W2 = (const __nv_bfloat16*)w2u;
    const uint32_t s0 = smem_u32(dsm);
    const uint32_t A_B = s0;
    const uint32_t H_B = s0 + 32768u;
    const uint32_t W_B = s0 + 65536u;
    const int tid = threadIdx.x, lane = tid & 31, wid = tid >> 5;
    const int wm = wid >> 2, wn = wid & 3;
    const int m0 = blockIdx.x * 128;
    const int lrow = (lane & 7) + ((lane >> 3) & 1) * 8;
    const int lhi  = lane >> 4;

    mlp_stage_w(W_B, W1, W2, 0, tid);
    ln_tile(A_B, x1, n2g, n2b, m0, wid, lane, 0);

    float acc2[2][4][4];
    #pragma unroll
    for (int a = 0; a < 2; a++)
        #pragma unroll
        for (int b = 0; b < 4; b++)
            #pragma unroll
            for (int c = 0; c < 4; c++) acc2[a][b][c] = 0.f;

    for (int c = 0; c < 4; c++) {
        if (c + 1 < 4) {
            mlp_stage_w(W_B + (uint32_t)((c + 1) & 1) * 65536u, W1, W2, c + 1, tid);
            asm volatile("cp.async.wait_group 1;" ::: "memory");
        } else {
            asm volatile("cp.async.wait_group 0;" ::: "memory");
        }
        __syncthreads();

        const uint32_t wb = W_B + (uint32_t)(c & 1) * 65536u;

        float acc1[2][4][4];
        #pragma unroll
        for (int a = 0; a < 2; a++)
            #pragma unroll
            for (int b = 0; b < 4; b++)
                #pragma unroll
                for (int q = 0; q < 4; q++) acc1[a][b][q] = 0.f;
        gemm128(A_B, wb, acc1, wm, wn, lrow, lhi);

        {
            float2 bs1[4];
            #pragma unroll
            for (int tn = 0; tn < 4; tn++)
                bs1[tn] = *(const float2*)(b1 + c * 128 + wn * 32 + tn * 8 + (lane & 3) * 2);
            #pragma unroll
            for (int tm = 0; tm < 2; tm++) {
                #pragma unroll
                for (int h = 0; h < 2; h++) {
                    const int row = wm * 32 + tm * 16 + (lane >> 2) + h * 8;
                    #pragma unroll
                    for (int tn = 0; tn < 4; tn++) {
                        const int nn = wn * 32 + tn * 8 + (lane & 3) * 2;
                        float v0 = acc1[tm][tn][h * 2 + 0] + bs1[tn].x;
                        float v1 = acc1[tm][tn][h * 2 + 1] + bs1[tn].y;
                        v0 = 0.5f * v0 * (1.f + erff(v0 * 0.70710678118654752f));
                        v1 = 0.5f * v1 * (1.f + erff(v1 * 0.70710678118654752f));
                        uint32_t boff = (uint32_t)((row << 7) + (nn & 63) * 2);
                        boff ^= (boff >> 3) & 0x70;
                        uint32_t dst = H_B + ((nn >= 64) ? 16384u : 0u) + boff;
                        asm volatile("st.shared.b32 [%0], %1;" :: "r"(dst), "r"(packbf(v0, v1)) : "memory");
                    }
                }
            }
        }
        __syncthreads();

        gemm128(H_B, wb + 32768u, acc2, wm, wn, lrow, lhi);
        __syncthreads();
    }

    float2 bs[4];
    #pragma unroll
    for (int tn = 0; tn < 4; tn++)
        bs[tn] = *(const float2*)(b2 + wn * 32 + tn * 8 + (lane & 3) * 2);
    #pragma unroll
    for (int tm = 0; tm < 2; tm++) {
        #pragma unroll
        for (int h = 0; h < 2; h++) {
            const int m = m0 + wm * 32 + tm * 16 + (lane >> 2) + h * 8;
            #pragma unroll
            for (int tn = 0; tn < 4; tn++) {
                const int nn = wn * 32 + tn * 8 + (lane & 3) * 2;
                float2 r2 = *(const float2*)(x1 + (size_t)m * 128 + nn);
                float v0 = acc2[tm][tn][h * 2 + 0] + bs[tn].x + r2.x;
                float v1 = acc2[tm][tn][h * 2 + 1] + bs[tn].y + r2.y;
                *(float2*)(out + (size_t)m * 128 + nn) = make_float2(v0, v1);
            }
        }
    }
}

// ---------------- launch ----------------
extern "C" void kernel_launch(void* const* d_in, const int* in_sizes, int n_in,
                              void* d_out, int out_size)
{
    const float* x      = (const float*)d_in[0];
    const float* rpb    = (const float*)d_in[1];
    const float* n1g    = (const float*)d_in[2];
    const float* n1b    = (const float*)d_in[3];
    const float* qkv_w  = (const float*)d_in[4];
    const float* qkv_b  = (const float*)d_in[5];
    const float* proj_w = (const float*)d_in[6];
    const float* proj_b = (const float*)d_in[7];
    const float* n2g    = (const float*)d_in[8];
    const float* n2b    = (const float*)d_in[9];
    const float* fc1_w  = (const float*)d_in[10];
    const float* fc1_b  = (const float*)d_in[11];
    const float* fc2_w  = (const float*)d_in[12];
    const float* fc2_b  = (const float*)d_in[13];
    float* out = (float*)d_out;

    unsigned short *wq, *wp, *w1, *w2;
    float *x1;
    cudaGetSymbolAddress((void**)&x1,  g_x1);
    cudaGetSymbolAddress((void**)&wq,  g_wq);
    cudaGetSymbolAddress((void**)&wp,  g_wp);
    cudaGetSymbolAddress((void**)&w1,  g_w1);
    cudaGetSymbolAddress((void**)&w2,  g_w2);

    cudaFuncSetAttribute(block_fused, cudaFuncAttributeMaxDynamicSharedMemorySize, FSMEM);
    cudaFuncSetAttribute(mlp_fused,   cudaFuncAttributeMaxDynamicSharedMemorySize, MSMEM);

    const int M = MTOK;

    f2bf_all<<<192, 256>>>(qkv_w, wq, proj_w, wp, fc1_w, w1, fc2_w, w2);

    // 1) LN1 + shift-gather + QKV GEMM + attention + proj + scatter + residual
    block_fused<<<M / 128, 512, FSMEM>>>(x, n1g, n1b, wq, qkv_b, wp, proj_b, rpb, x1);
    // 2) LN2 + fc1 + GELU + fc2 + residual -> final output
    mlp_fused<<<M / 128, 512, MSMEM>>>(x1, n2g, n2b, w1, fc1_b, w2, fc2_b, out);
}

// round 11
// speedup vs baseline: 2.4050x; 1.0917x over previous
#include <cuda_runtime.h>
#include <cuda_bf16.h>
#include <math.h>
#include <stdint.h>

// B=8, H=W=128, C=128, HEADS=4, d=32, WS=8, SHIFT=4, HIDDEN=512
#define MTOK 131072

// ---------------- scratch (device globals; no allocs allowed) ----------------
static __device__ unsigned short g_wq[384 * 128];
static __device__ unsigned short g_wp[128 * 128];
static __device__ unsigned short g_w1[512 * 128];
static __device__ unsigned short g_w2[128 * 512];

// ---------------- PTX helpers (sm_80+ features only) ----------------
static __device__ __forceinline__ uint32_t smem_u32(const void* p) {
    uint32_t a;
    asm("{ .reg .u64 t; cvta.to.shared.u64 t, %1; cvt.u32.u64 %0, t; }" : "=r"(a) : "l"(p));
    return a;
}
static __device__ __forceinline__ void cpa16(uint32_t s, const void* g) {
    asm volatile("cp.async.cg.shared.global [%0], [%1], 16;" :: "r"(s), "l"(g) : "memory");
}
static __device__ __forceinline__ void ldsm4(uint32_t* r, uint32_t addr) {
    asm volatile("ldmatrix.sync.aligned.m8n8.x4.shared.b16 {%0,%1,%2,%3}, [%4];"
                 : "=r"(r[0]), "=r"(r[1]), "=r"(r[2]), "=r"(r[3]) : "r"(addr));
}
static __device__ __forceinline__ void ldsm4t(uint32_t* r, uint32_t addr) {
    asm volatile("ldmatrix.sync.aligned.m8n8.x4.trans.shared.b16 {%0,%1,%2,%3}, [%4];"
                 : "=r"(r[0]), "=r"(r[1]), "=r"(r[2]), "=r"(r[3]) : "r"(addr));
}
static __device__ __forceinline__ void mma_bf16(float* c,
    uint32_t a0, uint32_t a1, uint32_t a2, uint32_t a3, uint32_t b0, uint32_t b1) {
    asm volatile(
        "mma.sync.aligned.m16n8k16.row.col.f32.bf16.bf16.f32 "
        "{%0,%1,%2,%3}, {%4,%5,%6,%7}, {%8,%9}, {%0,%1,%2,%3};"
        : "+f"(c[0]), "+f"(c[1]), "+f"(c[2]), "+f"(c[3])
        : "r"(a0), "r"(a1), "r"(a2), "r"(a3), "r"(b0), "r"(b1));
}
static __device__ __forceinline__ uint32_t packbf(float a, float b) {
    __nv_bfloat162 p = __floats2bfloat162_rn(a, b);
    return *reinterpret_cast<uint32_t*>(&p);
}

// ---------------- merged fp32 -> bf16 weight conversion ----------------
__global__ __launch_bounds__(256) void f2bf_all(
    const float* __restrict__ s0, unsigned short* __restrict__ d0,
    const float* __restrict__ s1, unsigned short* __restrict__ d1,
    const float* __restrict__ s2, unsigned short* __restrict__ d2,
    const float* __restrict__ s3, unsigned short* __restrict__ d3)
{
    int i = blockIdx.x * 256 + threadIdx.x;
    const float* s; unsigned short* d; int o;
    if (i < 12288)      { s = s0; d = d0; o = i; }
    else if (i < 16384) { s = s1; d = d1; o = i - 12288; }
    else if (i < 32768) { s = s2; d = d2; o = i - 16384; }
    else                { s = s3; d = d3; o = i - 32768; }
    float4 v = ((const float4*)s)[o];
    uint2 u;
    u.x = packbf(v.x, v.y);
    u.y = packbf(v.z, v.w);
    ((uint2*)d)[o] = u;
}

// ------------- 16-warp GEMM core: C128x128 += A(2 kblk) @ B(2 kblk)^T ---------
static __device__ __forceinline__ void gemm128(
    uint32_t abase, uint32_t bbase, float acc[2][4][4],
    int wm, int wn, int lrow, int lhi)
{
    #pragma unroll
    for (int kb = 0; kb < 2; kb++) {
        const uint32_t ab = abase + (uint32_t)kb * 16384u;
        const uint32_t bb = bbase + (uint32_t)kb * 16384u;
        #pragma unroll
        for (int ks = 0; ks < 4; ks++) {
            uint32_t af[2][4], bf[2][4];
            const int chunk = ks * 2 + lhi;
            #pragma unroll
            for (int tm = 0; tm < 2; tm++) {
                int row = wm * 32 + tm * 16 + lrow;
                ldsm4(af[tm], ab + (uint32_t)(row * 128 + ((chunk ^ (row & 7)) << 4)));
            }
            #pragma unroll
            for (int t2 = 0; t2 < 2; t2++) {
                int row = wn * 32 + t2 * 16 + lrow;
                ldsm4(bf[t2], bb + (uint32_t)(row * 128 + ((chunk ^ (row & 7)) << 4)));
            }
            #pragma unroll
            for (int tm = 0; tm < 2; tm++)
                #pragma unroll
                for (int tn = 0; tn < 4; tn++)
                    mma_bf16(acc[tm][tn],
                             af[tm][0], af[tm][1], af[tm][2], af[tm][3],
                             bf[tn >> 1][tn & 1], bf[tn >> 1][2 + (tn & 1)]);
        }
    }
}

// stage a 128x128 bf16 row-major matrix into 2 swizzled kblocks (512 threads)
static __device__ __forceinline__ void stage128(
    uint32_t dst, const __nv_bfloat16* src, int tid)
{
    #pragma unroll
    for (int it = 0; it < 4; it++) {
        int idx = tid + (it << 9);
        int r = idx >> 4, q = idx & 15;
        int kblk = q >> 3, qi = q & 7;
        uint32_t off = (uint32_t)((r << 7) | (qi << 4));
        off ^= (off >> 3) & 0x70;
        cpa16(dst + (uint32_t)kblk * 16384u + off, src + (size_t)r * 128 + q * 8);
    }
}

// stage MLP weight chunk c: W1 rows [c*128, ...) and W2 cols [c*128, ...)
static __device__ __forceinline__ void mlp_stage_w(
    uint32_t wbuf, const __nv_bfloat16* W1, const __nv_bfloat16* W2, int c, int tid)
{
    const int nc0 = c * 128;
    #pragma unroll
    for (int it = 0; it < 4; it++) {
        int idx = tid + (it << 9);
        int r = idx >> 4, q = idx & 15;
        int kblk = q >> 3, qi = q & 7;
        uint32_t off = (uint32_t)((r << 7) | (qi << 4));
        off ^= (off >> 3) & 0x70;
        cpa16(wbuf + (uint32_t)kblk * 16384u + off,            W1 + (size_t)(nc0 + r) * 128 + q * 8);
        cpa16(wbuf + 32768u + (uint32_t)kblk * 16384u + off,   W2 + (size_t)r * 512 + nc0 + q * 8);
    }
    asm volatile("cp.async.commit_group;" ::: "memory");
}

// in-kernel LayerNorm of one 128-row tile into swizzled A smem (16 warps)
static __device__ __forceinline__ void ln_tile(
    uint32_t A_B, const float* __restrict__ xin,
    const float* __restrict__ gam, const float* __restrict__ bet,
    int m0, int wid, int lane)
{
    float4 g4 = *(const float4*)(gam + lane * 4);
    float4 b4 = *(const float4*)(bet + lane * 4);
    const uint32_t kblk = (lane >= 16) ? 16384u : 0u;
    uint32_t boff0 = (uint32_t)((lane * 4 & 63) * 2);
    #pragma unroll 4
    for (int it = 0; it < 8; it++) {
        const int row = it * 16 + wid;
        const int t = m0 + row;
        int w = t >> 6, n = t & 63;
        int b = w >> 8, wrem = w & 255;
        int wi = wrem >> 4, wj = wrem & 15;
        int y  = (wi * 8 + (n >> 3) + 4) & 127;
        int xc = (wj * 8 + (n & 7) + 4) & 127;
        size_t src = ((size_t)b << 14) + (size_t)y * 128 + xc;
        float4 v = *(const float4*)(xin + src * 128 + lane * 4);
        float s  = v.x + v.y + v.z + v.w;
        float sq = v.x * v.x + v.y * v.y + v.z * v.z + v.w * v.w;
        #pragma unroll
        for (int o = 16; o; o >>= 1) {
            s  += __shfl_xor_sync(0xffffffffu, s,  o);
            sq += __shfl_xor_sync(0xffffffffu, sq, o);
        }
        float mean = s * (1.f / 128.f);
        float rstd = rsqrtf(sq * (1.f / 128.f) - mean * mean + 1e-5f);
        uint32_t u0 = packbf((v.x - mean) * rstd * g4.x + b4.x,
                             (v.y - mean) * rstd * g4.y + b4.y);
        uint32_t u1 = packbf((v.z - mean) * rstd * g4.z + b4.z,
                             (v.w - mean) * rstd * g4.w + b4.w);
        uint32_t boff = (uint32_t)(row << 7) + boff0;
        boff ^= (boff >> 3) & 0x70;
        asm volatile("st.shared.v2.b32 [%0], {%1, %2};"
                     :: "r"(A_B + kblk + boff), "r"(u0), "r"(u1) : "memory");
    }
}

// ---------------- mega kernel: full Swin block per 128-token CTA --------------
// smem map (225296 bytes):
//  A_B  [0, 32768)       LN1 tile -> attn out (proj A) -> LN2 tile (MLP A)
//  Q_B  [32768, 155648)  12 qkv slices (128 rows x 80B) ; MLP: HID @32768,
//                        WBUF0 @65536, WBUF1 @131072 (each 64K)
//  W_B  [155648, 221184) qkv weight double buffer; proj weights @ +32768
//  AUX  [221184, 225296) rpb (900 f) + rgt (128 i) ; MLP: red[128*8] floats
#define FSMEM 225296
__device__ __forceinline__ int reg3(int y) { return y < 120 ? 0 : (y < 124 ? 1 : 2); }

__global__ __launch_bounds__(512) void swin_fused(
    const float* __restrict__ x, const float* __restrict__ n1g,
    const float* __restrict__ n1b, const unsigned short* __restrict__ wqu,
    const float* __restrict__ qkv_b, const unsigned short* __restrict__ wpu,
    const float* __restrict__ proj_b, const float* __restrict__ rpb,
    const float* __restrict__ n2g, const float* __restrict__ n2b,
    const unsigned short* __restrict__ w1u, const float* __restrict__ b1,
    const unsigned short* __restrict__ w2u, const float* __restrict__ b2,
    float* __restrict__ out)
{
    extern __shared__ char dsm[];
    const __nv_bfloat16* wq = (const __nv_bfloat16*)wqu;
    const __nv_bfloat16* wp = (const __nv_bfloat16*)wpu;
    const __nv_bfloat16* W1 = (const __nv_bfloat16*)w1u;
    const __nv_bfloat16* W2 = (const __nv_bfloat16*)w2u;
    const uint32_t s0 = smem_u32(dsm);
    const uint32_t A_B = s0;
    const uint32_t Q_B = s0 + 32768u;
    const uint32_t W_B = s0 + 155648u;
    const uint32_t HID = s0 + 32768u;
    float* rpbs = (float*)(dsm + 221184);
    int*   rgt  = (int*)(dsm + 224784);
    float* red  = (float*)(dsm + 221184);   // reused after attention
    const int tid = threadIdx.x, lane = tid & 31, wid = tid >> 5;
    const int wm = wid >> 2, wn = wid & 3;
    const int m0 = blockIdx.x * 128;
    const int lrow = (lane & 7) + ((lane >> 3) & 1) * 8;
    const int lhi  = lane >> 4;

    stage128(W_B, wq, tid);
    asm volatile("cp.async.commit_group;" ::: "memory");

    ln_tile(A_B, x, n1g, n1b, m0, wid, lane);

    for (int i = tid; i < 900; i += 512) rpbs[i] = rpb[i];
    if (tid < 128) {
        int lw = tid >> 6, n = tid & 63;
        int w = (m0 >> 6) + lw, wrem = w & 255;
        int wi = wrem >> 4, wj = wrem & 15;
        rgt[tid] = 3 * reg3(wi * 8 + (n >> 3)) + reg3(wj * 8 + (n & 7));
    }

    // ---- phase 1: QKV GEMM, 3 chunks of N=128 ----
    for (int c = 0; c < 3; c++) {
        if (c < 2) {
            stage128(W_B + (uint32_t)((c + 1) & 1) * 32768u, wq + (size_t)(c + 1) * 128 * 128, tid);
            asm volatile("cp.async.commit_group;" ::: "memory");
            asm volatile("cp.async.wait_group 1;" ::: "memory");
        } else {
            asm volatile("cp.async.wait_group 0;" ::: "memory");
        }
        __syncthreads();

        float acc[2][4][4];
        #pragma unroll
        for (int a = 0; a < 2; a++)
            #pragma unroll
            for (int b = 0; b < 4; b++)
                #pragma unroll
                for (int q = 0; q < 4; q++) acc[a][b][q] = 0.f;
        gemm128(A_B, W_B + (uint32_t)(c & 1) * 32768u, acc, wm, wn, lrow, lhi);

        float2 bs[4];
        #pragma unroll
        for (int tn = 0; tn < 4; tn++)
            bs[tn] = *(const float2*)(qkv_b + c * 128 + wn * 32 + tn * 8 + (lane & 3) * 2);
        const uint32_t slice = Q_B + (uint32_t)(c * 4 + wn) * 10240u;
        #pragma unroll
        for (int tm = 0; tm < 2; tm++) {
            #pragma unroll
            for (int h8 = 0; h8 < 2; h8++) {
                const int row = wm * 32 + tm * 16 + (lane >> 2) + h8 * 8;
                #pragma unroll
                for (int tn = 0; tn < 4; tn++) {
                    const int c32 = tn * 8 + (lane & 3) * 2;
                    float v0 = acc[tm][tn][h8 * 2 + 0] + bs[tn].x;
                    float v1 = acc[tm][tn][h8 * 2 + 1] + bs[tn].y;
                    asm volatile("st.shared.b32 [%0], %1;"
                                 :: "r"(slice + (uint32_t)(row * 80 + c32 * 2)),
                                    "r"(packbf(v0, v1)) : "memory");
                }
            }
        }
        __syncthreads();
    }

    // prefetch proj weights (group P)
    stage128(W_B + 32768u, wp, tid);
    asm volatile("cp.async.commit_group;" ::: "memory");

    // ---- phase 2: attention (16 warps: window, head-pair, row-quarter) ----
    {
        const int lw  = wid >> 3;
        const int hp  = (wid >> 2) & 1;
        const int wm4 = wid & 3;
        const uint32_t lh16 = (uint32_t)lhi * 16u;
        const uint32_t rowbase = (uint32_t)(lw * 64) * 80u;
        const int r0 = wm4 * 16 + (lane >> 2), r1 = r0 + 8;
        const int rg0 = rgt[lw * 64 + r0], rg1 = rgt[lw * 64 + r1];
        const int i1a = r0 >> 3, j1a = r0 & 7, i1b = r1 >> 3, j1b = r1 & 7;
        const float scale = 0.17677669529663689f;

        #pragma unroll 1
        for (int hh = 0; hh < 2; hh++) {
            const int h = hp * 2 + hh;
            const uint32_t qsl = Q_B + (uint32_t)(0 + h) * 10240u + rowbase;
            const uint32_t ksl = Q_B + (uint32_t)(4 + h) * 10240u + rowbase;
            const uint32_t vsl = Q_B + (uint32_t)(8 + h) * 10240u + rowbase;

            uint32_t qa[2][4];
            {
                uint32_t addr = qsl + (uint32_t)((wm4 * 16 + lrow) * 80) + lh16;
                ldsm4(qa[0], addr);
                ldsm4(qa[1], addr + 32);
            }
            uint32_t kf[4][2][4];
            #pragma unroll
            for (int nt = 0; nt < 4; nt++) {
                uint32_t addr = ksl + (uint32_t)((nt * 16 + lrow) * 80) + lh16;
                ldsm4(kf[nt][0], addr);
                ldsm4(kf[nt][1], addr + 32);
            }

            float sc[8][4];
            #pragma unroll
            for (int i = 0; i < 8; i++)
                #pragma unroll
                for (int q = 0; q < 4; q++) sc[i][q] = 0.f;
            #pragma unroll
            for (int nt8 = 0; nt8 < 8; nt8++) {
                const int nt = nt8 >> 1, ii = nt8 & 1;
                mma_bf16(sc[nt8], qa[0][0], qa[0][1], qa[0][2], qa[0][3],
                         kf[nt][0][ii], kf[nt][0][2 + ii]);
                mma_bf16(sc[nt8], qa[1][0], qa[1][1], qa[1][2], qa[1][3],
                         kf[nt][1][ii], kf[nt][1][2 + ii]);
            }

            #pragma unroll
            for (int nt8 = 0; nt8 < 8; nt8++) {
                #pragma unroll
                for (int q = 0; q < 4; q++) {
                    const int col = nt8 * 8 + (lane & 3) * 2 + (q & 1);
                    const int i2 = col >> 3, j2 = col & 7;
                    const int rgc = rgt[lw * 64 + col];
                    float v = sc[nt8][q] * scale;
                    if (q < 2) {
                        v += rpbs[((i1a - i2 + 7) * 15 + (j1a - j2 + 7)) * 4 + h];
                        if (rgc != rg0) v -= 100.f;
                    } else {
                        v += rpbs[((i1b - i2 + 7) * 15 + (j1b - j2 + 7)) * 4 + h];
                        if (rgc != rg1) v -= 100.f;
                    }
                    sc[nt8][q] = v;
                }
            }

            float mx0 = -1e30f, mx1 = -1e30f;
            #pragma unroll
            for (int nt8 = 0; nt8 < 8; nt8++) {
                mx0 = fmaxf(mx0, fmaxf(sc[nt8][0], sc[nt8][1]));
                mx1 = fmaxf(mx1, fmaxf(sc[nt8][2], sc[nt8][3]));
            }
            #pragma unroll
            for (int o = 1; o <= 2; o <<= 1) {
                mx0 = fmaxf(mx0, __shfl_xor_sync(0xffffffffu, mx0, o));
                mx1 = fmaxf(mx1, __shfl_xor_sync(0xffffffffu, mx1, o));
            }
            float sm0 = 0.f, sm1 = 0.f;
            #pragma unroll
            for (int nt8 = 0; nt8 < 8; nt8++) {
                sc[nt8][0] = __expf(sc[nt8][0] - mx0);
                sc[nt8][1] = __expf(sc[nt8][1] - mx0);
                sc[nt8][2] = __expf(sc[nt8][2] - mx1);
                sc[nt8][3] = __expf(sc[nt8][3] - mx1);
                sm0 += sc[nt8][0] + sc[nt8][1];
                sm1 += sc[nt8][2] + sc[nt8][3];
            }
            #pragma unroll
            for (int o = 1; o <= 2; o <<= 1) {
                sm0 += __shfl_xor_sync(0xffffffffu, sm0, o);
                sm1 += __shfl_xor_sync(0xffffffffu, sm1, o);
            }
            const float inv0 = 1.f / sm0, inv1 = 1.f / sm1;

            float oc[4][4];
            #pragma unroll
            for (int nt = 0; nt < 4; nt++)
                #pragma unroll
                for (int q = 0; q < 4; q++) oc[nt][q] = 0.f;
            #pragma unroll
            for (int kc = 0; kc < 4; kc++) {
                const uint32_t a0 = packbf(sc[2 * kc][0],     sc[2 * kc][1]);
                const uint32_t a1 = packbf(sc[2 * kc][2],     sc[2 * kc][3]);
                const uint32_t a2 = packbf(sc[2 * kc + 1][0], sc[2 * kc + 1][1]);
                const uint32_t a3 = packbf(sc[2 * kc + 1][2], sc[2 * kc + 1][3]);
                uint32_t vf0[4], vf1[4];
                const uint32_t vaddr = vsl + (uint32_t)((kc * 16 + lrow) * 80) + lh16;
                ldsm4t(vf0, vaddr);
                ldsm4t(vf1, vaddr + 32);
                mma_bf16(oc[0], a0, a1, a2, a3, vf0[0], vf0[1]);
                mma_bf16(oc[1], a0, a1, a2, a3, vf0[2], vf0[3]);
                mma_bf16(oc[2], a0, a1, a2, a3, vf1[0], vf1[1]);
                mma_bf16(oc[3], a0, a1, a2, a3, vf1[2], vf1[3]);
            }

            #pragma unroll
            for (int nt = 0; nt < 4; nt++) {
                const int ch = h * 32 + nt * 8 + (lane & 3) * 2;
                const uint32_t kblk = (uint32_t)(ch >> 6) * 16384u;
                uint32_t b0 = (uint32_t)(((lw * 64 + r0) << 7) + ((ch & 63) << 1));
                uint32_t b1 = (uint32_t)(((lw * 64 + r1) << 7) + ((ch & 63) << 1));
                b0 ^= (b0 >> 3) & 0x70;
                b1 ^= (b1 >> 3) & 0x70;
                asm volatile("st.shared.b32 [%0], %1;" ::
                    "r"(A_B + kblk + b0), "r"(packbf(oc[nt][0] * inv0, oc[nt][1] * inv0)) : "memory");
                asm volatile("st.shared.b32 [%0], %1;" ::
                    "r"(A_B + kblk + b1), "r"(packbf(oc[nt][2] * inv1, oc[nt][3] * inv1)) : "memory");
            }
        }
    }
    __syncthreads();   // attn outputs in A_B; Q_B now dead

    // prefetch MLP weight chunk 0 into pool (Q_B region; group M0)
    mlp_stage_w(Q_B + 32768u, W1, W2, 0, tid);
    asm volatile("cp.async.wait_group 1;" ::: "memory");  // proj weights (P) ready
    __syncthreads();

    // ---- phase 3: proj GEMM; x1 kept in registers ----
    float xv[2][4][4];
    {
        #pragma unroll
        for (int a = 0; a < 2; a++)
            #pragma unroll
            for (int b = 0; b < 4; b++)
                #pragma unroll
                for (int q = 0; q < 4; q++) xv[a][b][q] = 0.f;
        gemm128(A_B, W_B + 32768u, xv, wm, wn, lrow, lhi);

        float2 bs[4];
        #pragma unroll
        for (int tn = 0; tn < 4; tn++)
            bs[tn] = *(const float2*)(proj_b + wn * 32 + tn * 8 + (lane & 3) * 2);
        #pragma unroll
        for (int tm = 0; tm < 2; tm++) {
            #pragma unroll
            for (int h8 = 0; h8 < 2; h8++) {
                const int m = m0 + wm * 32 + tm * 16 + (lane >> 2) + h8 * 8;
                int w = m >> 6, nt2 = m & 63;
                int b = w >> 8, wrem = w & 255;
                int wwi = wrem >> 4, wwj = wrem & 15;
                int yf = (wwi * 8 + (nt2 >> 3) + 4) & 127;
                int xf = (wwj * 8 + (nt2 & 7) + 4) & 127;
                size_t mo = ((size_t)b << 14) + (size_t)yf * 128 + xf;
                float s = 0.f, sq = 0.f;
                #pragma unroll
                for (int tn = 0; tn < 4; tn++) {
                    const int nn = wn * 32 + tn * 8 + (lane & 3) * 2;
                    float2 r2 = *(const float2*)(x + mo * 128 + nn);
                    float v0 = xv[tm][tn][h8 * 2 + 0] + bs[tn].x + r2.x;
                    float v1 = xv[tm][tn][h8 * 2 + 1] + bs[tn].y + r2.y;
                    xv[tm][tn][h8 * 2 + 0] = v0;
                    xv[tm][tn][h8 * 2 + 1] = v1;
                    s += v0 + v1;
                    sq += v0 * v0 + v1 * v1;
                }
                #pragma unroll
                for (int o = 1; o <= 2; o <<= 1) {
                    s  += __shfl_xor_sync(0xffffffffu, s,  o);
                    sq += __shfl_xor_sync(0xffffffffu, sq, o);
                }
                if ((lane & 3) == 0) {
                    const int rloc = wm * 32 + tm * 16 + (lane >> 2) + h8 * 8;
                    red[rloc * 8 + wn * 2 + 0] = s;
                    red[rloc * 8 + wn * 2 + 1] = sq;
                }
            }
        }
    }
    __syncthreads();

    // ---- phase 4: LN2 from registers -> A_B (bf16 swizzled) ----
    #pragma unroll
    for (int tm = 0; tm < 2; tm++) {
        #pragma unroll
        for (int h8 = 0; h8 < 2; h8++) {
            const int rloc = wm * 32 + tm * 16 + (lane >> 2) + h8 * 8;
            float4 p0 = *(const float4*)(red + rloc * 8);
            float4 p1 = *(const float4*)(red + rloc * 8 + 4);
            float s  = p0.x + p0.z + p1.x + p1.z;
            float sq = p0.y + p0.w + p1.y + p1.w;
            float mean = s * (1.f / 128.f);
            float rstd = rsqrtf(sq * (1.f / 128.f) - mean * mean + 1e-5f);
            #pragma unroll
            for (int tn = 0; tn < 4; tn++) {
                const int nn = wn * 32 + tn * 8 + (lane & 3) * 2;
                float2 gg = *(const float2*)(n2g + nn);
                float2 bb = *(const float2*)(n2b + nn);
                float v0 = (xv[tm][tn][h8 * 2 + 0] - mean) * rstd * gg.x + bb.x;
                float v1 = (xv[tm][tn][h8 * 2 + 1] - mean) * rstd * gg.y + bb.y;
                const uint32_t kblk = (uint32_t)(nn >> 6) * 16384u;
                uint32_t boff = (uint32_t)((rloc << 7) + ((nn & 63) << 1));
                boff ^= (boff >> 3) & 0x70;
                asm volatile("st.shared.b32 [%0], %1;"
                             :: "r"(A_B + kblk + boff), "r"(packbf(v0, v1)) : "memory");
            }
        }
    }
    __syncthreads();

    // ---- phase 5: MLP loop (hid @ HID, weights double-buffered in pool) ----
    float acc2[2][4][4];
    #pragma unroll
    for (int a = 0; a < 2; a++)
        #pragma unroll
        for (int b = 0; b < 4; b++)
            #pragma unroll
            for (int q = 0; q < 4; q++) acc2[a][b][q] = 0.f;

    for (int c = 0; c < 4; c++) {
        if (c + 1 < 4) {
            mlp_stage_w(Q_B + 32768u + (uint32_t)((c + 1) & 1) * 65536u, W1, W2, c + 1, tid);
            asm volatile("cp.async.wait_group 1;" ::: "memory");
        } else {
            asm volatile("cp.async.wait_group 0;" ::: "memory");
        }
        __syncthreads();

        const uint32_t wb = Q_B + 32768u + (uint32_t)(c & 1) * 65536u;

        float acc1[2][4][4];
        #pragma unroll
        for (int a = 0; a < 2; a++)
            #pragma unroll
            for (int b = 0; b < 4; b++)
                #pragma unroll
                for (int q = 0; q < 4; q++) acc1[a][b][q] = 0.f;
        gemm128(A_B, wb, acc1, wm, wn, lrow, lhi);

        {
            float2 bs1[4];
            #pragma unroll
            for (int tn = 0; tn < 4; tn++)
                bs1[tn] = *(const float2*)(b1 + c * 128 + wn * 32 + tn * 8 + (lane & 3) * 2);
            #pragma unroll
            for (int tm = 0; tm < 2; tm++) {
                #pragma unroll
                for (int h = 0; h < 2; h++) {
                    const int row = wm * 32 + tm * 16 + (lane >> 2) + h * 8;
                    #pragma unroll
                    for (int tn = 0; tn < 4; tn++) {
                        const int nn = wn * 32 + tn * 8 + (lane & 3) * 2;
                        float v0 = acc1[tm][tn][h * 2 + 0] + bs1[tn].x;
                        float v1 = acc1[tm][tn][h * 2 + 1] + bs1[tn].y;
                        v0 = 0.5f * v0 * (1.f + erff(v0 * 0.70710678118654752f));
                        v1 = 0.5f * v1 * (1.f + erff(v1 * 0.70710678118654752f));
                        uint32_t boff = (uint32_t)((row << 7) + (nn & 63) * 2);
                        boff ^= (boff >> 3) & 0x70;
                        uint32_t dst = HID + ((nn >= 64) ? 16384u : 0u) + boff;
                        asm volatile("st.shared.b32 [%0], %1;" :: "r"(dst), "r"(packbf(v0, v1)) : "memory");
                    }
                }
            }
        }
        __syncthreads();

        gemm128(HID, wb + 32768u, acc2, wm, wn, lrow, lhi);
        __syncthreads();
    }

    // ---- epilogue: out = acc2 + b2 + x1(regs), scattered ----
    float2 bs[4];
    #pragma unroll
    for (int tn = 0; tn < 4; tn++)
        bs[tn] = *(const float2*)(b2 + wn * 32 + tn * 8 + (lane & 3) * 2);
    #pragma unroll
    for (int tm = 0; tm < 2; tm++) {
        #pragma unroll
        for (int h8 = 0; h8 < 2; h8++) {
            const int m = m0 + wm * 32 + tm * 16 + (lane >> 2) + h8 * 8;
            int w = m >> 6, nt2 = m & 63;
            int b = w >> 8, wrem = w & 255;
            int wwi = wrem >> 4, wwj = wrem & 15;
            int yf = (wwi * 8 + (nt2 >> 3) + 4) & 127;
            int xf = (wwj * 8 + (nt2 & 7) + 4) & 127;
            size_t mo = ((size_t)b << 14) + (size_t)yf * 128 + xf;
            #pragma unroll
            for (int tn = 0; tn < 4; tn++) {
                const int nn = wn * 32 + tn * 8 + (lane & 3) * 2;
                float v0 = acc2[tm][tn][h8 * 2 + 0] + bs[tn].x + xv[tm][tn][h8 * 2 + 0];
                float v1 = acc2[tm][tn][h8 * 2 + 1] + bs[tn].y + xv[tm][tn][h8 * 2 + 1];
                *(float2*)(out + mo * 128 + nn) = make_float2(v0, v1);
            }
        }
    }
}

// ---------------- launch ----------------
extern "C" void kernel_launch(void* const* d_in, const int* in_sizes, int n_in,
                              void* d_out, int out_size)
{
    const float* x      = (const float*)d_in[0];
    const float* rpb    = (const float*)d_in[1];
    const float* n1g    = (const float*)d_in[2];
    const float* n1b    = (const float*)d_in[3];
    const float* qkv_w  = (const float*)d_in[4];
    const float* qkv_b  = (const float*)d_in[5];
    const float* proj_w = (const float*)d_in[6];
    const float* proj_b = (const float*)d_in[7];
    const float* n2g    = (const float*)d_in[8];
    const float* n2b    = (const float*)d_in[9];
    const float* fc1_w  = (const float*)d_in[10];
    const float* fc1_b  = (const float*)d_in[11];
    const float* fc2_w  = (const float*)d_in[12];
    const float* fc2_b  = (const float*)d_in[13];
    float* out = (float*)d_out;

    unsigned short *wq, *wp, *w1, *w2;
    cudaGetSymbolAddress((void**)&wq,  g_wq);
    cudaGetSymbolAddress((void**)&wp,  g_wp);
    cudaGetSymbolAddress((void**)&w1,  g_w1);
    cudaGetSymbolAddress((void**)&w2,  g_w2);

    cudaFuncSetAttribute(swin_fused, cudaFuncAttributeMaxDynamicSharedMemorySize, FSMEM);

    f2bf_all<<<192, 256>>>(qkv_w, wq, proj_w, wp, fc1_w, w1, fc2_w, w2);

    // full Swin block in one kernel per 128-token tile
    swin_fused<<<MTOK / 128, 512, FSMEM>>>(x, n1g, n1b, wq, qkv_b, wp, proj_b, rpb,
                                           n2g, n2b, w1, fc1_b, w2, fc2_b, out);
}

// round 12
// speedup vs baseline: 2.4250x; 1.0083x over previous
#include <cuda_runtime.h>
#include <cuda_bf16.h>
#include <math.h>
#include <stdint.h>

// B=8, H=W=128, C=128, HEADS=4, d=32, WS=8, SHIFT=4, HIDDEN=512
#define MTOK 131072

// ---------------- scratch (device globals; no allocs allowed) ----------------
static __device__ unsigned short g_wq[384 * 128];
static __device__ unsigned short g_wp[128 * 128];
static __device__ unsigned short g_w1[512 * 128];
static __device__ unsigned short g_w2[128 * 512];

// ---------------- PTX helpers (sm_80+ features only) ----------------
static __device__ __forceinline__ uint32_t smem_u32(const void* p) {
    uint32_t a;
    asm("{ .reg .u64 t; cvta.to.shared.u64 t, %1; cvt.u32.u64 %0, t; }" : "=r"(a) : "l"(p));
    return a;
}
static __device__ __forceinline__ void cpa16(uint32_t s, const void* g) {
    asm volatile("cp.async.cg.shared.global [%0], [%1], 16;" :: "r"(s), "l"(g) : "memory");
}
static __device__ __forceinline__ void ldsm4(uint32_t* r, uint32_t addr) {
    asm volatile("ldmatrix.sync.aligned.m8n8.x4.shared.b16 {%0,%1,%2,%3}, [%4];"
                 : "=r"(r[0]), "=r"(r[1]), "=r"(r[2]), "=r"(r[3]) : "r"(addr));
}
static __device__ __forceinline__ void ldsm4t(uint32_t* r, uint32_t addr) {
    asm volatile("ldmatrix.sync.aligned.m8n8.x4.trans.shared.b16 {%0,%1,%2,%3}, [%4];"
                 : "=r"(r[0]), "=r"(r[1]), "=r"(r[2]), "=r"(r[3]) : "r"(addr));
}
static __device__ __forceinline__ void mma_bf16(float* c,
    uint32_t a0, uint32_t a1, uint32_t a2, uint32_t a3, uint32_t b0, uint32_t b1) {
    asm volatile(
        "mma.sync.aligned.m16n8k16.row.col.f32.bf16.bf16.f32 "
        "{%0,%1,%2,%3}, {%4,%5,%6,%7}, {%8,%9}, {%0,%1,%2,%3};"
        : "+f"(c[0]), "+f"(c[1]), "+f"(c[2]), "+f"(c[3])
        : "r"(a0), "r"(a1), "r"(a2), "r"(a3), "r"(b0), "r"(b1));
}
static __device__ __forceinline__ uint32_t packbf(float a, float b) {
    __nv_bfloat162 p = __floats2bfloat162_rn(a, b);
    return *reinterpret_cast<uint32_t*>(&p);
}

// ---------------- merged fp32 -> bf16 weight conversion ----------------
__global__ __launch_bounds__(256) void f2bf_all(
    const float* __restrict__ s0, unsigned short* __restrict__ d0,
    const float* __restrict__ s1, unsigned short* __restrict__ d1,
    const float* __restrict__ s2, unsigned short* __restrict__ d2,
    const float* __restrict__ s3, unsigned short* __restrict__ d3)
{
    int i = blockIdx.x * 256 + threadIdx.x;
    const float* s; unsigned short* d; int o;
    if (i < 12288)      { s = s0; d = d0; o = i; }
    else if (i < 16384) { s = s1; d = d1; o = i - 12288; }
    else if (i < 32768) { s = s2; d = d2; o = i - 16384; }
    else                { s = s3; d = d3; o = i - 32768; }
    float4 v = ((const float4*)s)[o];
    uint2 u;
    u.x = packbf(v.x, v.y);
    u.y = packbf(v.z, v.w);
    ((uint2*)d)[o] = u;
}

// ------------- 16-warp GEMM core: C128x128 += A(2 kblk) @ B(2 kblk)^T ---------
static __device__ __forceinline__ void gemm128(
    uint32_t abase, uint32_t bbase, float acc[2][4][4],
    int wm, int wn, int lrow, int lhi)
{
    #pragma unroll
    for (int kb = 0; kb < 2; kb++) {
        const uint32_t ab = abase + (uint32_t)kb * 16384u;
        const uint32_t bb = bbase + (uint32_t)kb * 16384u;
        #pragma unroll
        for (int ks = 0; ks < 4; ks++) {
            uint32_t af[2][4], bf[2][4];
            const int chunk = ks * 2 + lhi;
            #pragma unroll
            for (int tm = 0; tm < 2; tm++) {
                int row = wm * 32 + tm * 16 + lrow;
                ldsm4(af[tm], ab + (uint32_t)(row * 128 + ((chunk ^ (row & 7)) << 4)));
            }
            #pragma unroll
            for (int t2 = 0; t2 < 2; t2++) {
                int row = wn * 32 + t2 * 16 + lrow;
                ldsm4(bf[t2], bb + (uint32_t)(row * 128 + ((chunk ^ (row & 7)) << 4)));
            }
            #pragma unroll
            for (int tm = 0; tm < 2; tm++)
                #pragma unroll
                for (int tn = 0; tn < 4; tn++)
                    mma_bf16(acc[tm][tn],
                             af[tm][0], af[tm][1], af[tm][2], af[tm][3],
                             bf[tn >> 1][tn & 1], bf[tn >> 1][2 + (tn & 1)]);
        }
    }
}

// stage a 128x128 bf16 row-major matrix into 2 swizzled kblocks (512 threads)
static __device__ __forceinline__ void stage128(
    uint32_t dst, const __nv_bfloat16* src, int tid)
{
    #pragma unroll
    for (int it = 0; it < 4; it++) {
        int idx = tid + (it << 9);
        int r = idx >> 4, q = idx & 15;
        int kblk = q >> 3, qi = q & 7;
        uint32_t off = (uint32_t)((r << 7) | (qi << 4));
        off ^= (off >> 3) & 0x70;
        cpa16(dst + (uint32_t)kblk * 16384u + off, src + (size_t)r * 128 + q * 8);
    }
}

// stage MLP weight chunk c: W1 rows [c*128, ...) and W2 cols [c*128, ...)
static __device__ __forceinline__ void mlp_stage_w(
    uint32_t wbuf, const __nv_bfloat16* W1, const __nv_bfloat16* W2, int c, int tid)
{
    const int nc0 = c * 128;
    #pragma unroll
    for (int it = 0; it < 4; it++) {
        int idx = tid + (it << 9);
        int r = idx >> 4, q = idx & 15;
        int kblk = q >> 3, qi = q & 7;
        uint32_t off = (uint32_t)((r << 7) | (qi << 4));
        off ^= (off >> 3) & 0x70;
        cpa16(wbuf + (uint32_t)kblk * 16384u + off,            W1 + (size_t)(nc0 + r) * 128 + q * 8);
        cpa16(wbuf + 32768u + (uint32_t)kblk * 16384u + off,   W2 + (size_t)r * 512 + nc0 + q * 8);
    }
    asm volatile("cp.async.commit_group;" ::: "memory");
}

// in-kernel LayerNorm of one 128-row tile into swizzled A smem (16 warps)
static __device__ __forceinline__ void ln_tile(
    uint32_t A_B, const float* __restrict__ xin,
    const float* __restrict__ gam, const float* __restrict__ bet,
    int m0, int wid, int lane)
{
    float4 g4 = *(const float4*)(gam + lane * 4);
    float4 b4 = *(const float4*)(bet + lane * 4);
    const uint32_t kblk = (lane >= 16) ? 16384u : 0u;
    uint32_t boff0 = (uint32_t)((lane * 4 & 63) * 2);
    #pragma unroll 4
    for (int it = 0; it < 8; it++) {
        const int row = it * 16 + wid;
        const int t = m0 + row;
        int w = t >> 6, n = t & 63;
        int b = w >> 8, wrem = w & 255;
        int wi = wrem >> 4, wj = wrem & 15;
        int y  = (wi * 8 + (n >> 3) + 4) & 127;
        int xc = (wj * 8 + (n & 7) + 4) & 127;
        size_t src = ((size_t)b << 14) + (size_t)y * 128 + xc;
        float4 v = *(const float4*)(xin + src * 128 + lane * 4);
        float s  = v.x + v.y + v.z + v.w;
        float sq = v.x * v.x + v.y * v.y + v.z * v.z + v.w * v.w;
        #pragma unroll
        for (int o = 16; o; o >>= 1) {
            s  += __shfl_xor_sync(0xffffffffu, s,  o);
            sq += __shfl_xor_sync(0xffffffffu, sq, o);
        }
        float mean = s * (1.f / 128.f);
        float rstd = rsqrtf(sq * (1.f / 128.f) - mean * mean + 1e-5f);
        uint32_t u0 = packbf((v.x - mean) * rstd * g4.x + b4.x,
                             (v.y - mean) * rstd * g4.y + b4.y);
        uint32_t u1 = packbf((v.z - mean) * rstd * g4.z + b4.z,
                             (v.w - mean) * rstd * g4.w + b4.w);
        uint32_t boff = (uint32_t)(row << 7) + boff0;
        boff ^= (boff >> 3) & 0x70;
        asm volatile("st.shared.v2.b32 [%0], {%1, %2};"
                     :: "r"(A_B + kblk + boff), "r"(u0), "r"(u1) : "memory");
    }
}

// ---------------- mega kernel: full Swin block per 128-token CTA --------------
#define FSMEM 225296
__device__ __forceinline__ int reg3(int y) { return y < 120 ? 0 : (y < 124 ? 1 : 2); }

__global__ __launch_bounds__(512) void swin_fused(
    const float* __restrict__ x, const float* __restrict__ n1g,
    const float* __restrict__ n1b, const unsigned short* __restrict__ wqu,
    const float* __restrict__ qkv_b, const unsigned short* __restrict__ wpu,
    const float* __restrict__ proj_b, const float* __restrict__ rpb,
    const float* __restrict__ n2g, const float* __restrict__ n2b,
    const unsigned short* __restrict__ w1u, const float* __restrict__ b1,
    const unsigned short* __restrict__ w2u, const float* __restrict__ b2,
    float* __restrict__ out)
{
    extern __shared__ char dsm[];
    const __nv_bfloat16* wq = (const __nv_bfloat16*)wqu;
    const __nv_bfloat16* wp = (const __nv_bfloat16*)wpu;
    const __nv_bfloat16* W1 = (const __nv_bfloat16*)w1u;
    const __nv_bfloat16* W2 = (const __nv_bfloat16*)w2u;
    const uint32_t s0 = smem_u32(dsm);
    const uint32_t A_B = s0;
    const uint32_t Q_B = s0 + 32768u;
    const uint32_t W_B = s0 + 155648u;
    const uint32_t HID = s0 + 32768u;
    float* rpbs = (float*)(dsm + 221184);
    int*   rgt  = (int*)(dsm + 224784);
    float* red  = (float*)(dsm + 221184);   // reused after attention
    const int tid = threadIdx.x, lane = tid & 31, wid = tid >> 5;
    const int wm = wid >> 2, wn = wid & 3;
    const int m0 = blockIdx.x * 128;
    const int lrow = (lane & 7) + ((lane >> 3) & 1) * 8;
    const int lhi  = lane >> 4;

    stage128(W_B, wq, tid);
    asm volatile("cp.async.commit_group;" ::: "memory");

    ln_tile(A_B, x, n1g, n1b, m0, wid, lane);

    for (int i = tid; i < 900; i += 512) rpbs[i] = rpb[i];
    if (tid < 128) {
        int lw = tid >> 6, n = tid & 63;
        int w = (m0 >> 6) + lw, wrem = w & 255;
        int wi = wrem >> 4, wj = wrem & 15;
        rgt[tid] = 3 * reg3(wi * 8 + (n >> 3)) + reg3(wj * 8 + (n & 7));
    }

    // ---- phase 1: QKV GEMM, 3 chunks of N=128 ----
    for (int c = 0; c < 3; c++) {
        if (c < 2) {
            stage128(W_B + (uint32_t)((c + 1) & 1) * 32768u, wq + (size_t)(c + 1) * 128 * 128, tid);
            asm volatile("cp.async.commit_group;" ::: "memory");
            asm volatile("cp.async.wait_group 1;" ::: "memory");
        } else {
            asm volatile("cp.async.wait_group 0;" ::: "memory");
        }
        __syncthreads();

        float acc[2][4][4];
        #pragma unroll
        for (int a = 0; a < 2; a++)
            #pragma unroll
            for (int b = 0; b < 4; b++)
                #pragma unroll
                for (int q = 0; q < 4; q++) acc[a][b][q] = 0.f;
        gemm128(A_B, W_B + (uint32_t)(c & 1) * 32768u, acc, wm, wn, lrow, lhi);

        float2 bs[4];
        #pragma unroll
        for (int tn = 0; tn < 4; tn++)
            bs[tn] = *(const float2*)(qkv_b + c * 128 + wn * 32 + tn * 8 + (lane & 3) * 2);
        const uint32_t slice = Q_B + (uint32_t)(c * 4 + wn) * 10240u;
        #pragma unroll
        for (int tm = 0; tm < 2; tm++) {
            #pragma unroll
            for (int h8 = 0; h8 < 2; h8++) {
                const int row = wm * 32 + tm * 16 + (lane >> 2) + h8 * 8;
                #pragma unroll
                for (int tn = 0; tn < 4; tn++) {
                    const int c32 = tn * 8 + (lane & 3) * 2;
                    float v0 = acc[tm][tn][h8 * 2 + 0] + bs[tn].x;
                    float v1 = acc[tm][tn][h8 * 2 + 1] + bs[tn].y;
                    asm volatile("st.shared.b32 [%0], %1;"
                                 :: "r"(slice + (uint32_t)(row * 80 + c32 * 2)),
                                    "r"(packbf(v0, v1)) : "memory");
                }
            }
        }
        __syncthreads();
    }

    // prefetch proj weights (group P)
    stage128(W_B + 32768u, wp, tid);
    asm volatile("cp.async.commit_group;" ::: "memory");

    // ---- phase 2: attention (16 warps: window, head-pair, row-quarter) ----
    {
        const int lw  = wid >> 3;
        const int hp  = (wid >> 2) & 1;
        const int wm4 = wid & 3;
        const uint32_t lh16 = (uint32_t)lhi * 16u;
        const uint32_t rowbase = (uint32_t)(lw * 64) * 80u;
        const int r0 = wm4 * 16 + (lane >> 2), r1 = r0 + 8;
        const int rg0 = rgt[lw * 64 + r0], rg1 = rgt[lw * 64 + r1];
        const int i1a = r0 >> 3, j1a = r0 & 7, i1b = r1 >> 3, j1b = r1 & 7;
        const int c0 = (lane & 3) * 2;
        const float scale = 0.17677669529663689f;

        // window edge test (warp-uniform): mask only matters for wi==15 or wj==15
        const int wthis = (m0 >> 6) + lw;
        const int wtr = wthis & 255;
        const bool edge = ((wtr >> 4) == 15) || ((wtr & 15) == 15);

        // strength-reduced bias bases: idx = (i1*15+j1+112) - (nt8*15 + c0 + dq)
        const float* pb0 = rpbs + (size_t)((i1a * 15 + j1a + 112 - c0) * 4);
        const float* pb1 = rpbs + (size_t)((i1b * 15 + j1b + 112 - c0) * 4);

        #pragma unroll 1
        for (int hh = 0; hh < 2; hh++) {
            const int h = hp * 2 + hh;
            const uint32_t qsl = Q_B + (uint32_t)(0 + h) * 10240u + rowbase;
            const uint32_t ksl = Q_B + (uint32_t)(4 + h) * 10240u + rowbase;
            const uint32_t vsl = Q_B + (uint32_t)(8 + h) * 10240u + rowbase;
            const float* pbh0 = pb0 + h;
            const float* pbh1 = pb1 + h;

            uint32_t qa[2][4];
            {
                uint32_t addr = qsl + (uint32_t)((wm4 * 16 + lrow) * 80) + lh16;
                ldsm4(qa[0], addr);
                ldsm4(qa[1], addr + 32);
            }
            uint32_t kf[4][2][4];
            #pragma unroll
            for (int nt = 0; nt < 4; nt++) {
                uint32_t addr = ksl + (uint32_t)((nt * 16 + lrow) * 80) + lh16;
                ldsm4(kf[nt][0], addr);
                ldsm4(kf[nt][1], addr + 32);
            }

            float sc[8][4];
            #pragma unroll
            for (int i = 0; i < 8; i++)
                #pragma unroll
                for (int q = 0; q < 4; q++) sc[i][q] = 0.f;
            #pragma unroll
            for (int nt8 = 0; nt8 < 8; nt8++) {
                const int nt = nt8 >> 1, ii = nt8 & 1;
                mma_bf16(sc[nt8], qa[0][0], qa[0][1], qa[0][2], qa[0][3],
                         kf[nt][0][ii], kf[nt][0][2 + ii]);
                mma_bf16(sc[nt8], qa[1][0], qa[1][1], qa[1][2], qa[1][3],
                         kf[nt][1][ii], kf[nt][1][2 + ii]);
            }

            // scale + rel-pos bias (+ shift mask only on edge windows)
            if (!edge) {
                #pragma unroll
                for (int nt8 = 0; nt8 < 8; nt8++) {
                    sc[nt8][0] = fmaf(sc[nt8][0], scale, pbh0[-nt8 * 60]);
                    sc[nt8][1] = fmaf(sc[nt8][1], scale, pbh0[-nt8 * 60 - 4]);
                    sc[nt8][2] = fmaf(sc[nt8][2], scale, pbh1[-nt8 * 60]);
                    sc[nt8][3] = fmaf(sc[nt8][3], scale, pbh1[-nt8 * 60 - 4]);
                }
            } else {
                const int* rg = rgt + lw * 64;
                #pragma unroll
                for (int nt8 = 0; nt8 < 8; nt8++) {
                    const int colb = nt8 * 8 + c0;
                    int rga = rg[colb], rgb = rg[colb + 1];
                    float v0 = fmaf(sc[nt8][0], scale, pbh0[-nt8 * 60]);
                    float v1 = fmaf(sc[nt8][1], scale, pbh0[-nt8 * 60 - 4]);
                    float v2 = fmaf(sc[nt8][2], scale, pbh1[-nt8 * 60]);
                    float v3 = fmaf(sc[nt8][3], scale, pbh1[-nt8 * 60 - 4]);
                    if (rga != rg0) v0 -= 100.f;
                    if (rgb != rg0) v1 -= 100.f;
                    if (rga != rg1) v2 -= 100.f;
                    if (rgb != rg1) v3 -= 100.f;
                    sc[nt8][0] = v0; sc[nt8][1] = v1; sc[nt8][2] = v2; sc[nt8][3] = v3;
                }
            }

            float mx0 = -1e30f, mx1 = -1e30f;
            #pragma unroll
            for (int nt8 = 0; nt8 < 8; nt8++) {
                mx0 = fmaxf(mx0, fmaxf(sc[nt8][0], sc[nt8][1]));
                mx1 = fmaxf(mx1, fmaxf(sc[nt8][2], sc[nt8][3]));
            }
            #pragma unroll
            for (int o = 1; o <= 2; o <<= 1) {
                mx0 = fmaxf(mx0, __shfl_xor_sync(0xffffffffu, mx0, o));
                mx1 = fmaxf(mx1, __shfl_xor_sync(0xffffffffu, mx1, o));
            }
            float sm0 = 0.f, sm1 = 0.f;
            #pragma unroll
            for (int nt8 = 0; nt8 < 8; nt8++) {
                sc[nt8][0] = __expf(sc[nt8][0] - mx0);
                sc[nt8][1] = __expf(sc[nt8][1] - mx0);
                sc[nt8][2] = __expf(sc[nt8][2] - mx1);
                sc[nt8][3] = __expf(sc[nt8][3] - mx1);
                sm0 += sc[nt8][0] + sc[nt8][1];
                sm1 += sc[nt8][2] + sc[nt8][3];
            }
            #pragma unroll
            for (int o = 1; o <= 2; o <<= 1) {
                sm0 += __shfl_xor_sync(0xffffffffu, sm0, o);
                sm1 += __shfl_xor_sync(0xffffffffu, sm1, o);
            }
            const float inv0 = 1.f / sm0, inv1 = 1.f / sm1;

            float oc[4][4];
            #pragma unroll
            for (int nt = 0; nt < 4; nt++)
                #pragma unroll
                for (int q = 0; q < 4; q++) oc[nt][q] = 0.f;
            #pragma unroll
            for (int kc = 0; kc < 4; kc++) {
                const uint32_t a0 = packbf(sc[2 * kc][0],     sc[2 * kc][1]);
                const uint32_t a1 = packbf(sc[2 * kc][2],     sc[2 * kc][3]);
                const uint32_t a2 = packbf(sc[2 * kc + 1][0], sc[2 * kc + 1][1]);
                const uint32_t a3 = packbf(sc[2 * kc + 1][2], sc[2 * kc + 1][3]);
                uint32_t vf0[4], vf1[4];
                const uint32_t vaddr = vsl + (uint32_t)((kc * 16 + lrow) * 80) + lh16;
                ldsm4t(vf0, vaddr);
                ldsm4t(vf1, vaddr + 32);
                mma_bf16(oc[0], a0, a1, a2, a3, vf0[0], vf0[1]);
                mma_bf16(oc[1], a0, a1, a2, a3, vf0[2], vf0[3]);
                mma_bf16(oc[2], a0, a1, a2, a3, vf1[0], vf1[1]);
                mma_bf16(oc[3], a0, a1, a2, a3, vf1[2], vf1[3]);
            }

            #pragma unroll
            for (int nt = 0; nt < 4; nt++) {
                const int ch = h * 32 + nt * 8 + c0;
                const uint32_t kblk = (uint32_t)(ch >> 6) * 16384u;
                uint32_t b0 = (uint32_t)(((lw * 64 + r0) << 7) + ((ch & 63) << 1));
                uint32_t b1 = (uint32_t)(((lw * 64 + r1) << 7) + ((ch & 63) << 1));
                b0 ^= (b0 >> 3) & 0x70;
                b1 ^= (b1 >> 3) & 0x70;
                asm volatile("st.shared.b32 [%0], %1;" ::
                    "r"(A_B + kblk + b0), "r"(packbf(oc[nt][0] * inv0, oc[nt][1] * inv0)) : "memory");
                asm volatile("st.shared.b32 [%0], %1;" ::
                    "r"(A_B + kblk + b1), "r"(packbf(oc[nt][2] * inv1, oc[nt][3] * inv1)) : "memory");
            }
        }
    }
    __syncthreads();   // attn outputs in A_B; Q_B now dead

    // prefetch MLP weight chunk 0 into pool (Q_B region; group M0)
    mlp_stage_w(Q_B + 32768u, W1, W2, 0, tid);
    asm volatile("cp.async.wait_group 1;" ::: "memory");  // proj weights (P) ready
    __syncthreads();

    // ---- phase 3: proj GEMM; x1 kept in registers ----
    float xv[2][4][4];
    {
        #pragma unroll
        for (int a = 0; a < 2; a++)
            #pragma unroll
            for (int b = 0; b < 4; b++)
                #pragma unroll
                for (int q = 0; q < 4; q++) xv[a][b][q] = 0.f;
        gemm128(A_B, W_B + 32768u, xv, wm, wn, lrow, lhi);

        float2 bs[4];
        #pragma unroll
        for (int tn = 0; tn < 4; tn++)
            bs[tn] = *(const float2*)(proj_b + wn * 32 + tn * 8 + (lane & 3) * 2);
        #pragma unroll
        for (int tm = 0; tm < 2; tm++) {
            #pragma unroll
            for (int h8 = 0; h8 < 2; h8++) {
                const int m = m0 + wm * 32 + tm * 16 + (lane >> 2) + h8 * 8;
                int w = m >> 6, nt2 = m & 63;
                int b = w >> 8, wrem = w & 255;
                int wwi = wrem >> 4, wwj = wrem & 15;
                int yf = (wwi * 8 + (nt2 >> 3) + 4) & 127;
                int xf = (wwj * 8 + (nt2 & 7) + 4) & 127;
                size_t mo = ((size_t)b << 14) + (size_t)yf * 128 + xf;
                float s = 0.f, sq = 0.f;
                #pragma unroll
                for (int tn = 0; tn < 4; tn++) {
                    const int nn = wn * 32 + tn * 8 + (lane & 3) * 2;
                    float2 r2 = *(const float2*)(x + mo * 128 + nn);
                    float v0 = xv[tm][tn][h8 * 2 + 0] + bs[tn].x + r2.x;
                    float v1 = xv[tm][tn][h8 * 2 + 1] + bs[tn].y + r2.y;
                    xv[tm][tn][h8 * 2 + 0] = v0;
                    xv[tm][tn][h8 * 2 + 1] = v1;
                    s += v0 + v1;
                    sq += v0 * v0 + v1 * v1;
                }
                #pragma unroll
                for (int o = 1; o <= 2; o <<= 1) {
                    s  += __shfl_xor_sync(0xffffffffu, s,  o);
                    sq += __shfl_xor_sync(0xffffffffu, sq, o);
                }
                if ((lane & 3) == 0) {
                    const int rloc = wm * 32 + tm * 16 + (lane >> 2) + h8 * 8;
                    red[rloc * 8 + wn * 2 + 0] = s;
                    red[rloc * 8 + wn * 2 + 1] = sq;
                }
            }
        }
    }
    __syncthreads();

    // ---- phase 4: LN2 from registers -> A_B (bf16 swizzled) ----
    #pragma unroll
    for (int tm = 0; tm < 2; tm++) {
        #pragma unroll
        for (int h8 = 0; h8 < 2; h8++) {
            const int rloc = wm * 32 + tm * 16 + (lane >> 2) + h8 * 8;
            float4 p0 = *(const float4*)(red + rloc * 8);
            float4 p1 = *(const float4*)(red + rloc * 8 + 4);
            float s  = p0.x + p0.z + p1.x + p1.z;
            float sq = p0.y + p0.w + p1.y + p1.w;
            float mean = s * (1.f / 128.f);
            float rstd = rsqrtf(sq * (1.f / 128.f) - mean * mean + 1e-5f);
            #pragma unroll
            for (int tn = 0; tn < 4; tn++) {
                const int nn = wn * 32 + tn * 8 + (lane & 3) * 2;
                float2 gg = *(const float2*)(n2g + nn);
                float2 bb = *(const float2*)(n2b + nn);
                float v0 = (xv[tm][tn][h8 * 2 + 0] - mean) * rstd * gg.x + bb.x;
                float v1 = (xv[tm][tn][h8 * 2 + 1] - mean) * rstd * gg.y + bb.y;
                const uint32_t kblk = (uint32_t)(nn >> 6) * 16384u;
                uint32_t boff = (uint32_t)((rloc << 7) + ((nn & 63) << 1));
                boff ^= (boff >> 3) & 0x70;
                asm volatile("st.shared.b32 [%0], %1;"
                             :: "r"(A_B + kblk + boff), "r"(packbf(v0, v1)) : "memory");
            }
        }
    }
    __syncthreads();

    // ---- phase 5: MLP loop (hid @ HID, weights double-buffered in pool) ----
    float acc2[2][4][4];
    #pragma unroll
    for (int a = 0; a < 2; a++)
        #pragma unroll
        for (int b = 0; b < 4; b++)
            #pragma unroll
            for (int q = 0; q < 4; q++) acc2[a][b][q] = 0.f;

    for (int c = 0; c < 4; c++) {
        if (c + 1 < 4) {
            mlp_stage_w(Q_B + 32768u + (uint32_t)((c + 1) & 1) * 65536u, W1, W2, c + 1, tid);
            asm volatile("cp.async.wait_group 1;" ::: "memory");
        } else {
            asm volatile("cp.async.wait_group 0;" ::: "memory");
        }
        __syncthreads();

        const uint32_t wb = Q_B + 32768u + (uint32_t)(c & 1) * 65536u;

        float acc1[2][4][4];
        #pragma unroll
        for (int a = 0; a < 2; a++)
            #pragma unroll
            for (int b = 0; b < 4; b++)
                #pragma unroll
                for (int q = 0; q < 4; q++) acc1[a][b][q] = 0.f;
        gemm128(A_B, wb, acc1, wm, wn, lrow, lhi);

        {
            float2 bs1[4];
            #pragma unroll
            for (int tn = 0; tn < 4; tn++)
                bs1[tn] = *(const float2*)(b1 + c * 128 + wn * 32 + tn * 8 + (lane & 3) * 2);
            #pragma unroll
            for (int tm = 0; tm < 2; tm++) {
                #pragma unroll
                for (int h = 0; h < 2; h++) {
                    const int row = wm * 32 + tm * 16 + (lane >> 2) + h * 8;
                    #pragma unroll
                    for (int tn = 0; tn < 4; tn++) {
                        const int nn = wn * 32 + tn * 8 + (lane & 3) * 2;
                        float v0 = acc1[tm][tn][h * 2 + 0] + bs1[tn].x;
                        float v1 = acc1[tm][tn][h * 2 + 1] + bs1[tn].y;
                        v0 = 0.5f * v0 * (1.f + erff(v0 * 0.70710678118654752f));
                        v1 = 0.5f * v1 * (1.f + erff(v1 * 0.70710678118654752f));
                        uint32_t boff = (uint32_t)((row << 7) + (nn & 63) * 2);
                        boff ^= (boff >> 3) & 0x70;
                        uint32_t dst = HID + ((nn >= 64) ? 16384u : 0u) + boff;
                        asm volatile("st.shared.b32 [%0], %1;" :: "r"(dst), "r"(packbf(v0, v1)) : "memory");
                    }
                }
            }
        }
        __syncthreads();

        gemm128(HID, wb + 32768u, acc2, wm, wn, lrow, lhi);
        __syncthreads();
    }

    // ---- epilogue: out = acc2 + b2 + x1(regs), scattered ----
    float2 bs[4];
    #pragma unroll
    for (int tn = 0; tn < 4; tn++)
        bs[tn] = *(const float2*)(b2 + wn * 32 + tn * 8 + (lane & 3) * 2);
    #pragma unroll
    for (int tm = 0; tm < 2; tm++) {
        #pragma unroll
        for (int h8 = 0; h8 < 2; h8++) {
            const int m = m0 + wm * 32 + tm * 16 + (lane >> 2) + h8 * 8;
            int w = m >> 6, nt2 = m & 63;
            int b = w >> 8, wrem = w & 255;
            int wwi = wrem >> 4, wwj = wrem & 15;
            int yf = (wwi * 8 + (nt2 >> 3) + 4) & 127;
            int xf = (wwj * 8 + (nt2 & 7) + 4) & 127;
            size_t mo = ((size_t)b << 14) + (size_t)yf * 128 + xf;
            #pragma unroll
            for (int tn = 0; tn < 4; tn++) {
                const int nn = wn * 32 + tn * 8 + (lane & 3) * 2;
                float v0 = acc2[tm][tn][h8 * 2 + 0] + bs[tn].x + xv[tm][tn][h8 * 2 + 0];
                float v1 = acc2[tm][tn][h8 * 2 + 1] + bs[tn].y + xv[tm][tn][h8 * 2 + 1];
                *(float2*)(out + mo * 128 + nn) = make_float2(v0, v1);
            }
        }
    }
}

// ---------------- launch ----------------
extern "C" void kernel_launch(void* const* d_in, const int* in_sizes, int n_in,
                              void* d_out, int out_size)
{
    const float* x      = (const float*)d_in[0];
    const float* rpb    = (const float*)d_in[1];
    const float* n1g    = (const float*)d_in[2];
    const float* n1b    = (const float*)d_in[3];
    const float* qkv_w  = (const float*)d_in[4];
    const float* qkv_b  = (const float*)d_in[5];
    const float* proj_w = (const float*)d_in[6];
    const float* proj_b = (const float*)d_in[7];
    const float* n2g    = (const float*)d_in[8];
    const float* n2b    = (const float*)d_in[9];
    const float* fc1_w  = (const float*)d_in[10];
    const float* fc1_b  = (const float*)d_in[11];
    const float* fc2_w  = (const float*)d_in[12];
    const float* fc2_b  = (const float*)d_in[13];
    float* out = (float*)d_out;

    unsigned short *wq, *wp, *w1, *w2;
    cudaGetSymbolAddress((void**)&wq,  g_wq);
    cudaGetSymbolAddress((void**)&wp,  g_wp);
    cudaGetSymbolAddress((void**)&w1,  g_w1);
    cudaGetSymbolAddress((void**)&w2,  g_w2);

    cudaFuncSetAttribute(swin_fused, cudaFuncAttributeMaxDynamicSharedMemorySize, FSMEM);

    f2bf_all<<<192, 256>>>(qkv_w, wq, proj_w, wp, fc1_w, w1, fc2_w, w2);

    swin_fused<<<MTOK / 128, 512, FSMEM>>>(x, n1g, n1b, wq, qkv_b, wp, proj_b, rpb,
                                           n2g, n2b, w1, fc1_b, w2, fc2_b, out);
}